// round 11
// baseline (speedup 1.0000x reference)
#include <cuda_runtime.h>
#include <cuda_fp16.h>
#include <mma.h>
#include <math.h>
#include <stdint.h>

using namespace nvcuda;

#define NNODES 50000
#define NPAD   50048
#define NEDGES 800000
#define TOTE   (NEDGES + NNODES)
#define GNUM   64
#define NEG_SLOPE 0.2f
#define CSRB   ((NNODES + 255) / 256)   // 196 blocks, all resident

// ---------------- static device scratch ----------------
static __device__ int      g_is64;
static __device__ unsigned g_barcnt;
static __device__ unsigned g_bargen;
static __device__ int    g_src[NEDGES];
static __device__ int    g_dst[NEDGES];
static __device__ int    g_batch[NNODES];
static __device__ int    g_deg[NNODES];
static __device__ int    g_row[NNODES + 1];
static __device__ int    g_cur[NNODES];
static __device__ int    g_col[TOTE];
static __device__ int    g_bsum[CSRB];
static __device__ int    g_gptr[GNUM + 1];
static __device__ __half g_x16[(size_t)NPAD * 128];
static __device__ __half g_w1h[128 * 256];
static __device__ __half g_w2h[64 * 256];
static __device__ __half g_gw1h[64 * 64];
static __device__ __half g_o16[(size_t)NPAD * 64];
static __device__ uint4  g_hh[(size_t)NPAD * 32];
static __device__ float  g_asrc[NPAD * 4];
static __device__ float  g_adst[NPAD * 4];
static __device__ float  g_out1[(size_t)NNODES * 64];
static __device__ float  g_out2[(size_t)NNODES * 64];
static __device__ float  g_gate[NNODES];

// ---------------- cp.async helpers ----------------
__device__ __forceinline__ void cp_async16(uint32_t smem_addr, const void* gptr) {
    asm volatile("cp.async.cg.shared.global [%0], [%1], 16;"
                 :: "r"(smem_addr), "l"(gptr));
}
#define CP_COMMIT() asm volatile("cp.async.commit_group;" ::: "memory")
#define CP_WAIT(n)  asm volatile("cp.async.wait_group %0;" :: "n"(n) : "memory")

// ---------------- prep: zero deg, detect dtype, fp16 weights, fp16 x ----------------
__global__ void prep_kernel(const long long* __restrict__ ei,
                            const float* __restrict__ x,
                            const float* __restrict__ W1,
                            const float* __restrict__ W2,
                            const float* __restrict__ gw1,
                            int N, int total8) {
    int i = blockIdx.x * blockDim.x + threadIdx.x;
    if (i < N) g_deg[i] = 0;
    if (i < 128 * 256) g_w1h[i] = __float2half(W1[i]);
    if (i < 64 * 256)  g_w2h[i] = __float2half(W2[i]);
    if (i < 64 * 64)   g_gw1h[i] = __float2half(gw1[i]);
    if (i < total8) {
        float4 a = ((const float4*)x)[2 * i];
        float4 b = ((const float4*)x)[2 * i + 1];
        __half h8[8] = {__float2half(a.x), __float2half(a.y), __float2half(a.z), __float2half(a.w),
                        __float2half(b.x), __float2half(b.y), __float2half(b.z), __float2half(b.w)};
        ((uint4*)g_x16)[i] = *(uint4*)h8;
    }
    if (blockIdx.x == 0 && threadIdx.x < 32) {
        long long v = ei[threadIdx.x];
        int ok = (v >= 0 && v < (long long)N);
        unsigned all = __all_sync(0xFFFFFFFFu, ok);
        if (threadIdx.x == 0) g_is64 = all ? 1 : 0;
    }
}

// ---------------- convert indices + batch + fused degree ----------------
__global__ void convert_kernel(const void* __restrict__ ei, const void* __restrict__ bt,
                               int E, int N) {
    int i = blockIdx.x * blockDim.x + threadIdx.x;
    int total = 2 * E + N;
    if (i >= total) return;
    int is64 = g_is64;
    if (i < 2 * E) {
        int v = is64 ? (int)((const long long*)ei)[i] : ((const int*)ei)[i];
        if (i < E) g_src[i] = v;
        else { g_dst[i - E] = v; atomicAdd(&g_deg[v], 1); }
    } else {
        int j = i - 2 * E;
        int v = is64 ? (int)((const long long*)bt)[j] : ((const int*)bt)[j];
        g_batch[j] = v;
    }
}

// ---------------- fused CSR: scan + offsets + scatter (grid barriers) ----------------
__device__ __forceinline__ void grid_barrier(int nblocks) {
    __threadfence();
    __syncthreads();
    if (threadIdx.x == 0) {
        unsigned gen = atomicAdd(&g_bargen, 0u);
        unsigned prev = atomicAdd(&g_barcnt, 1u);
        if (prev == (unsigned)(nblocks - 1)) {
            atomicExch(&g_barcnt, 0u);
            __threadfence();
            atomicAdd(&g_bargen, 1u);
        } else {
            while (atomicAdd(&g_bargen, 0u) == gen) { }
        }
    }
    __syncthreads();
}

__global__ void __launch_bounds__(256) csr_kernel(int N, int E) {
    __shared__ int ws[8];
    __shared__ int red[32];
    int tid = threadIdx.x, lane = tid & 31, wid = tid >> 5;
    int bid = blockIdx.x;
    int i = bid * 256 + tid;

    int x = (i < N) ? g_deg[i] + 1 : 0;
    int v = x;
    #pragma unroll
    for (int o = 1; o < 32; o <<= 1) {
        int u = __shfl_up_sync(0xFFFFFFFFu, v, o);
        if (lane >= o) v += u;
    }
    if (lane == 31) ws[wid] = v;
    __syncthreads();
    if (wid == 0) {
        int w = (lane < 8) ? ws[lane] : 0;
        #pragma unroll
        for (int o = 1; o < 8; o <<= 1) {
            int u = __shfl_up_sync(0xFFFFFFFFu, w, o);
            if (lane >= o) w += u;
        }
        if (lane < 8) ws[lane] = w;
    }
    __syncthreads();
    int incl = v + (wid ? ws[wid - 1] : 0);
    if (tid == 255) g_bsum[bid] = incl;

    grid_barrier(CSRB);

    int part = (tid < bid) ? g_bsum[tid] : 0;
    #pragma unroll
    for (int o = 16; o; o >>= 1) part += __shfl_xor_sync(0xFFFFFFFFu, part, o);
    if (lane == 0) red[wid] = part;
    __syncthreads();
    int off;
    {
        int t = (lane < 8) ? red[lane] : 0;
        #pragma unroll
        for (int o = 4; o; o >>= 1) t += __shfl_xor_sync(0xFFFFFFFFu, t, o);
        off = __shfl_sync(0xFFFFFFFFu, t, 0);
    }
    int r = incl - x + off;
    if (i < N) { g_row[i] = r; g_cur[i] = r; }
    if (i == 0) g_row[N] = E + N;

    grid_barrier(CSRB);

    for (int e = bid * 256 + tid; e < E + N; e += CSRB * 256) {
        int s, d;
        if (e < E) { s = g_src[e]; d = g_dst[e]; }
        else       { s = d = e - E; }
        int pos = atomicAdd(&g_cur[d], 1);
        g_col[pos] = s;
    }
}

// ---------------- cp.async double-buffered tensor-core GEMM ----------------
// Block: 512 thr (16 warps), 64 rows x 256 cols, 2 blocks/SM.
// B staged in 32-k-row chunks, double buffered via cp.async.
#define SM_AS_BYTES 17408                 // 64 * 136 halves (K=128 worst case)
#define SM_BS_BYTES 16896                 // 32 * 264 halves per buffer
__global__ void __launch_bounds__(512, 2) gemm_attn_kernel(const __half* __restrict__ A,
                                                           const __half* __restrict__ B,
                                                           uint4* __restrict__ C,
                                                           const float* __restrict__ att_src,
                                                           const float* __restrict__ att_dst,
                                                           float* __restrict__ asrc,
                                                           float* __restrict__ adst,
                                                           int K) {
    __shared__ __align__(16) char smbuf[SM_AS_BYTES + 2 * SM_BS_BYTES];
    __half* As = (__half*)smbuf;                       // [64][K+8]
    float*  Cs = (float*)smbuf;                        // [64][132] (epilogue reuse)
    int tid = threadIdx.x;
    int warp = tid >> 5;
    int by = blockIdx.x;
    int lda = K + 8;
    int row0 = by * 64;

    uint32_t sm_base = (uint32_t)__cvta_generic_to_shared(smbuf);
    uint32_t as_base = sm_base;
    uint32_t bs_base[2] = {sm_base + SM_AS_BYTES, sm_base + SM_AS_BYTES + SM_BS_BYTES};
    __half* BsGen[2] = {(__half*)(smbuf + SM_AS_BYTES), (__half*)(smbuf + SM_AS_BYTES + SM_BS_BYTES)};

    // issue A tile (64 x K) + first B chunk via cp.async, one commit group
    int kv = K >> 3;
    int nA = 64 * kv;
    for (int i = tid; i < nA; i += 512) {
        int r = i / kv, c = i - r * kv;
        cp_async16(as_base + (r * lda + c * 8) * 2, A + (size_t)(row0 + r) * K + c * 8);
    }
    for (int i = tid; i < 1024; i += 512) {
        int r = i >> 5, c = i & 31;
        cp_async16(bs_base[0] + (r * 264 + c * 8) * 2, B + (size_t)r * 256 + c * 8);
    }
    CP_COMMIT();

    int wr = warp >> 2;          // 0..3: 16-row group
    int wc = warp & 3;           // 0..3: 64-col group
    wmma::fragment<wmma::accumulator, 16, 16, 16, float> cf[4];
    #pragma unroll
    for (int n = 0; n < 4; n++) wmma::fill_fragment(cf[n], 0.f);

    int nc = K >> 5;             // number of 32-k chunks
    for (int ci = 0; ci < nc; ci++) {
        if (ci + 1 < nc) {
            int k0n = (ci + 1) * 32;
            int buf = (ci + 1) & 1;
            for (int i = tid; i < 1024; i += 512) {
                int r = i >> 5, c = i & 31;
                cp_async16(bs_base[buf] + (r * 264 + c * 8) * 2,
                           B + (size_t)(k0n + r) * 256 + c * 8);
            }
            CP_COMMIT();
            CP_WAIT(1);
        } else {
            CP_WAIT(0);
        }
        __syncthreads();
        __half* Bs = BsGen[ci & 1];
        int k0 = ci * 32;
        #pragma unroll
        for (int ks = 0; ks < 32; ks += 16) {
            wmma::fragment<wmma::matrix_a, 16, 16, 16, __half, wmma::row_major> af;
            wmma::load_matrix_sync(af, As + (wr * 16) * lda + k0 + ks, lda);
            #pragma unroll
            for (int n = 0; n < 4; n++) {
                wmma::fragment<wmma::matrix_b, 16, 16, 16, __half, wmma::row_major> bf;
                wmma::load_matrix_sync(bf, Bs + ks * 264 + wc * 64 + n * 16, 264);
                wmma::mma_sync(cf[n], af, bf, cf[n]);
            }
        }
        __syncthreads();
    }

    // epilogue: two waves (128 cols each) through reused smem, float4 reads
    int er = tid >> 3;           // row 0..63
    int cs8 = tid & 7;           // 16-col segment within the 128-col half
    #pragma unroll
    for (int wv = 0; wv < 2; wv++) {
        __syncthreads();
        if ((wc >> 1) == wv) {
            #pragma unroll
            for (int n = 0; n < 4; n++)
                wmma::store_matrix_sync(Cs + (wr * 16) * 132 + (wc & 1) * 64 + n * 16,
                                        cf[n], 132, wmma::mem_row_major);
        }
        __syncthreads();
        int gcol = wv * 128 + cs8 * 16;
        int head = gcol >> 6;
        int hoff = gcol & 63;
        float4 v4[4];
        #pragma unroll
        for (int q = 0; q < 4; q++)
            v4[q] = *(float4*)(Cs + er * 132 + cs8 * 16 + q * 4);
        float s = 0.f, d = 0.f;
        __half h16[16];
        const float* vv = (const float*)v4;
        #pragma unroll
        for (int c = 0; c < 16; c++) {
            float v = vv[c];
            s += v * __ldg(att_src + head * 64 + hoff + c);
            d += v * __ldg(att_dst + head * 64 + hoff + c);
            h16[c] = __float2half(v);
        }
        uint4* dst = C + (size_t)(row0 + er) * 32 + (gcol >> 3);
        uint4* srcp = (uint4*)h16;
        dst[0] = srcp[0];
        dst[1] = srcp[1];
        s += __shfl_xor_sync(0xFFFFFFFFu, s, 1);
        d += __shfl_xor_sync(0xFFFFFFFFu, d, 1);
        s += __shfl_xor_sync(0xFFFFFFFFu, s, 2);
        d += __shfl_xor_sync(0xFFFFFFFFu, d, 2);
        if ((tid & 3) == 0) {
            asrc[(row0 + er) * 4 + head] = s;
            adst[(row0 + er) * 4 + head] = d;
        }
    }
}

// ---------------- GAT aggregation: chunked smem-broadcast, gather-only inner loop ----------------
__device__ __forceinline__ void fma_half8(float* a, uint4 v, float w) {
    __half2* p = (__half2*)&v;
    #pragma unroll
    for (int q = 0; q < 4; q++) {
        float2 f = __half22float2(p[q]);
        a[2 * q]     += w * f.x;
        a[2 * q + 1] += w * f.y;
    }
}

__device__ __forceinline__ float lrelu(float e) { return (e > 0.f) ? e : NEG_SLOPE * e; }

__global__ void __launch_bounds__(256) aggregate_kernel(const uint4* __restrict__ hh,
                                                        const float* __restrict__ asrc,
                                                        const float* __restrict__ adst,
                                                        const float* __restrict__ bias,
                                                        float* __restrict__ out,
                                                        uint4* __restrict__ out16,
                                                        int N) {
    __shared__ int   ss[8][32];
    __shared__ float swt[8][4][32];
    int gw = (blockIdx.x * blockDim.x + threadIdx.x) >> 5;
    if (gw >= N) return;
    int wslot = (threadIdx.x >> 5);
    int lane = threadIdx.x & 31;
    int start = g_row[gw], end = g_row[gw + 1];
    int deg = end - start;
    float4 ad = *(const float4*)(adst + 4 * gw);
    int head = lane >> 3;

    float acc0[8], acc1[8];
    #pragma unroll
    for (int k = 0; k < 8; k++) { acc0[k] = 0.f; acc1[k] = 0.f; }
    float den = 0.f;

    if (deg <= 32) {
        int myj = start + lane;
        int mys = 0;
        float e0 = -1e30f, e1 = -1e30f, e2 = -1e30f, e3 = -1e30f;
        if (myj < end) {
            mys = g_col[myj];
            float4 q = *(const float4*)(asrc + 4 * mys);
            e0 = lrelu(q.x + ad.x); e1 = lrelu(q.y + ad.y);
            e2 = lrelu(q.z + ad.z); e3 = lrelu(q.w + ad.w);
        }
        float m0 = e0, m1 = e1, m2 = e2, m3 = e3;
        #pragma unroll
        for (int o = 16; o; o >>= 1) {
            m0 = fmaxf(m0, __shfl_xor_sync(0xFFFFFFFFu, m0, o));
            m1 = fmaxf(m1, __shfl_xor_sync(0xFFFFFFFFu, m1, o));
            m2 = fmaxf(m2, __shfl_xor_sync(0xFFFFFFFFu, m2, o));
            m3 = fmaxf(m3, __shfl_xor_sync(0xFFFFFFFFu, m3, o));
        }
        ss[wslot][lane] = mys;
        swt[wslot][0][lane] = (myj < end) ? expf(e0 - m0) : 0.f;
        swt[wslot][1][lane] = (myj < end) ? expf(e1 - m1) : 0.f;
        swt[wslot][2][lane] = (myj < end) ? expf(e2 - m2) : 0.f;
        swt[wslot][3][lane] = (myj < end) ? expf(e3 - m3) : 0.f;
        __syncwarp();
        int j = 0;
        for (; j + 4 <= deg; j += 4) {
            int s0 = ss[wslot][j], s1 = ss[wslot][j + 1];
            int s2 = ss[wslot][j + 2], s3 = ss[wslot][j + 3];
            float w0 = swt[wslot][head][j],     w1 = swt[wslot][head][j + 1];
            float w2 = swt[wslot][head][j + 2], w3 = swt[wslot][head][j + 3];
            uint4 v0 = hh[(size_t)s0 * 32 + lane];
            uint4 v1 = hh[(size_t)s1 * 32 + lane];
            uint4 v2 = hh[(size_t)s2 * 32 + lane];
            uint4 v3 = hh[(size_t)s3 * 32 + lane];
            den += (w0 + w1) + (w2 + w3);
            fma_half8(acc0, v0, w0);
            fma_half8(acc1, v1, w1);
            fma_half8(acc0, v2, w2);
            fma_half8(acc1, v3, w3);
        }
        for (; j < deg; j++) {
            int s0 = ss[wslot][j];
            float w0 = swt[wslot][head][j];
            uint4 v0 = hh[(size_t)s0 * 32 + lane];
            den += w0;
            fma_half8(acc0, v0, w0);
        }
        __syncwarp();
    } else {
        float m0 = -1e30f, m1 = -1e30f, m2 = -1e30f, m3 = -1e30f;
        for (int j = start + lane; j < end; j += 32) {
            int s = g_col[j];
            float4 q = *(const float4*)(asrc + 4 * s);
            m0 = fmaxf(m0, lrelu(q.x + ad.x));
            m1 = fmaxf(m1, lrelu(q.y + ad.y));
            m2 = fmaxf(m2, lrelu(q.z + ad.z));
            m3 = fmaxf(m3, lrelu(q.w + ad.w));
        }
        #pragma unroll
        for (int o = 16; o; o >>= 1) {
            m0 = fmaxf(m0, __shfl_xor_sync(0xFFFFFFFFu, m0, o));
            m1 = fmaxf(m1, __shfl_xor_sync(0xFFFFFFFFu, m1, o));
            m2 = fmaxf(m2, __shfl_xor_sync(0xFFFFFFFFu, m2, o));
            m3 = fmaxf(m3, __shfl_xor_sync(0xFFFFFFFFu, m3, o));
        }
        for (int base = start; base < end; base += 32) {
            int nn = min(32, end - base);
            int myj = base + lane;
            int mys = 0;
            float w0v = 0.f, w1v = 0.f, w2v = 0.f, w3v = 0.f;
            if (myj < end) {
                mys = g_col[myj];
                float4 q = *(const float4*)(asrc + 4 * mys);
                w0v = expf(lrelu(q.x + ad.x) - m0);
                w1v = expf(lrelu(q.y + ad.y) - m1);
                w2v = expf(lrelu(q.z + ad.z) - m2);
                w3v = expf(lrelu(q.w + ad.w) - m3);
            }
            ss[wslot][lane] = mys;
            swt[wslot][0][lane] = w0v;
            swt[wslot][1][lane] = w1v;
            swt[wslot][2][lane] = w2v;
            swt[wslot][3][lane] = w3v;
            __syncwarp();
            int j = 0;
            for (; j + 4 <= nn; j += 4) {
                int s0 = ss[wslot][j], s1 = ss[wslot][j + 1];
                int s2 = ss[wslot][j + 2], s3 = ss[wslot][j + 3];
                float w0 = swt[wslot][head][j],     w1 = swt[wslot][head][j + 1];
                float w2 = swt[wslot][head][j + 2], w3 = swt[wslot][head][j + 3];
                uint4 v0 = hh[(size_t)s0 * 32 + lane];
                uint4 v1 = hh[(size_t)s1 * 32 + lane];
                uint4 v2 = hh[(size_t)s2 * 32 + lane];
                uint4 v3 = hh[(size_t)s3 * 32 + lane];
                den += (w0 + w1) + (w2 + w3);
                fma_half8(acc0, v0, w0);
                fma_half8(acc1, v1, w1);
                fma_half8(acc0, v2, w2);
                fma_half8(acc1, v3, w3);
            }
            for (; j < nn; j++) {
                int s0 = ss[wslot][j];
                float w0 = swt[wslot][head][j];
                uint4 v0 = hh[(size_t)s0 * 32 + lane];
                den += w0;
                fma_half8(acc0, v0, w0);
            }
            __syncwarp();
        }
    }

    float inv = 1.f / (den + 1e-16f);
    float r[8];
    #pragma unroll
    for (int k = 0; k < 8; k++) r[k] = (acc0[k] + acc1[k]) * inv;
    #pragma unroll
    for (int k = 0; k < 8; ++k) {
        r[k] += __shfl_xor_sync(0xFFFFFFFFu, r[k], 8);
        r[k] += __shfl_xor_sync(0xFFFFFFFFu, r[k], 16);
    }
    if (lane < 8) {
        float o_[8];
        __half h8[8];
        #pragma unroll
        for (int k = 0; k < 8; ++k) {
            float v = 0.25f * r[k] + bias[lane * 8 + k];
            float sg = 1.f / (1.f + expf(-v));
            o_[k] = sg;
            h8[k] = __float2half(sg);
        }
        float4* op = (float4*)(out + (size_t)gw * 64 + lane * 8);
        op[0] = make_float4(o_[0], o_[1], o_[2], o_[3]);
        op[1] = make_float4(o_[4], o_[5], o_[6], o_[7]);
        out16[(size_t)gw * 8 + lane] = *(uint4*)h8;
    }
}

// ---------------- gate via wmma ----------------
__global__ void __launch_bounds__(128) gate_wmma_kernel(const __half* __restrict__ A,
                                                        const __half* __restrict__ B,
                                                        const float* __restrict__ gb1,
                                                        const float* __restrict__ gamma,
                                                        const float* __restrict__ beta,
                                                        const float* __restrict__ gw2,
                                                        const float* __restrict__ gb2,
                                                        float* __restrict__ gout, int N) {
    __shared__ float Cs[64 * 68];
    int tid = threadIdx.x;
    int warp = tid >> 5;
    int by = blockIdx.x;
    int row0 = by * 64 + warp * 16;

    wmma::fragment<wmma::accumulator, 16, 16, 16, float> cf[4];
    #pragma unroll
    for (int n = 0; n < 4; n++) wmma::fill_fragment(cf[n], 0.f);
    for (int k0 = 0; k0 < 64; k0 += 16) {
        wmma::fragment<wmma::matrix_a, 16, 16, 16, __half, wmma::row_major> af;
        wmma::load_matrix_sync(af, A + (size_t)row0 * 64 + k0, 64);
        #pragma unroll
        for (int n = 0; n < 4; n++) {
            wmma::fragment<wmma::matrix_b, 16, 16, 16, __half, wmma::row_major> bf;
            wmma::load_matrix_sync(bf, B + (size_t)k0 * 64 + n * 16, 64);
            wmma::mma_sync(cf[n], af, bf, cf[n]);
        }
    }
    #pragma unroll
    for (int n = 0; n < 4; n++)
        wmma::store_matrix_sync(Cs + warp * 16 * 68 + n * 16, cf[n], 68, wmma::mem_row_major);
    __syncthreads();

    int r = tid >> 1;
    int ch = (tid & 1) * 32;
    int row = by * 64 + r;
    float kinv = rsqrtf(1.0f + 1e-5f);
    float s = 0.f;
    #pragma unroll
    for (int c = 0; c < 32; c++) {
        float t = (Cs[r * 68 + ch + c] + __ldg(gb1 + ch + c)) * kinv * __ldg(gamma + ch + c)
                  + __ldg(beta + ch + c);
        t = fmaxf(t, 0.f);
        s += t * __ldg(gw2 + ch + c);
    }
    s += __shfl_xor_sync(0xFFFFFFFFu, s, 1);
    if ((tid & 1) == 0 && row < N) gout[row] = s + gb2[0];
}

// ---------------- per-graph boundaries (batch sorted) ----------------
__global__ void gptr_kernel(int N) {
    int v = blockIdx.x * blockDim.x + threadIdx.x;
    if (v >= N) return;
    int b = g_batch[v];
    if (v == 0) {
        for (int i = 0; i <= b; i++) g_gptr[i] = 0;
    } else {
        int bp = g_batch[v - 1];
        for (int i = bp + 1; i <= b; i++) g_gptr[i] = v;
    }
    if (v == N - 1) {
        for (int i = b + 1; i <= GNUM; i++) g_gptr[i] = N;
    }
}

// ---------------- pooling + final, fused ----------------
__global__ void __launch_bounds__(256) pool_kernel(const float* __restrict__ out2,
                                                   const float* __restrict__ lw,
                                                   const float* __restrict__ lb,
                                                   float* __restrict__ result, int N) {
    int b = blockIdx.x;
    int start = g_gptr[b], end = g_gptr[b + 1];
    __shared__ float smax[256];
    __shared__ float sacc[256];
    __shared__ float sden[4];
    int tid = threadIdx.x;
    float m = -1e30f;
    for (int v = start + tid; v < end; v += 256) m = fmaxf(m, g_gate[v]);
    smax[tid] = m;
    __syncthreads();
    for (int s = 128; s; s >>= 1) {
        if (tid < s) smax[tid] = fmaxf(smax[tid], smax[tid + s]);
        __syncthreads();
    }
    float mx = smax[0];
    __syncthreads();
    int c = tid & 63;
    int sub = tid >> 6;
    float acc = 0.f, dacc = 0.f;
    for (int v = start + sub; v < end; v += 4) {
        float w = expf(g_gate[v] - mx);
        acc += w * out2[(size_t)v * 64 + c];
        if (c == 0) dacc += w;
    }
    sacc[tid] = acc;
    if (c == 0) sden[sub] = dacc;
    __syncthreads();
    if (sub == 0) {
        float p = sacc[c] + sacc[64 + c] + sacc[128 + c] + sacc[192 + c];
        sacc[c] = p * __ldg(lw + c);
    }
    __syncthreads();
    if (tid < 32) {
        float t = sacc[tid] + sacc[tid + 32];
        #pragma unroll
        for (int o = 16; o; o >>= 1) t += __shfl_xor_sync(0xFFFFFFFFu, t, o);
        if (tid == 0) {
            float dt = sden[0] + sden[1] + sden[2] + sden[3];
            float s = t / (dt + 1e-16f) + lb[0];
            result[b] = 1.f / (1.f + expf(-s));
        }
    }
}

// ---------------- launch ----------------
extern "C" void kernel_launch(void* const* d_in, const int* in_sizes, int n_in,
                              void* d_out, int out_size) {
    const float* x  = (const float*)d_in[0];
    const void*  ei = d_in[1];
    const void*  bt = d_in[2];
    int o = (in_sizes[3] == 1) ? 1 : 0;
    const float* W1  = (const float*)d_in[3 + o];
    const float* as1 = (const float*)d_in[4 + o];
    const float* ad1 = (const float*)d_in[5 + o];
    const float* b1  = (const float*)d_in[6 + o];
    const float* W2  = (const float*)d_in[7 + o];
    const float* as2 = (const float*)d_in[8 + o];
    const float* ad2 = (const float*)d_in[9 + o];
    const float* b2  = (const float*)d_in[10 + o];
    const float* gw1 = (const float*)d_in[11 + o];
    const float* gb1 = (const float*)d_in[12 + o];
    const float* gam = (const float*)d_in[13 + o];
    const float* bet = (const float*)d_in[14 + o];
    const float* gw2 = (const float*)d_in[15 + o];
    const float* gb2 = (const float*)d_in[16 + o];
    const float* lw  = (const float*)d_in[17 + o];
    const float* lb  = (const float*)d_in[18 + o];

    int N = in_sizes[0] / 128;
    int E = in_sizes[1] / 2;

    __half *x16b, *w1hb, *w2hb, *gw1hb, *o16b;
    uint4* hhbuf;
    float *asrcb, *adstb, *out1b, *out2b, *gateb;
    cudaGetSymbolAddress((void**)&x16b,  g_x16);
    cudaGetSymbolAddress((void**)&w1hb,  g_w1h);
    cudaGetSymbolAddress((void**)&w2hb,  g_w2h);
    cudaGetSymbolAddress((void**)&gw1hb, g_gw1h);
    cudaGetSymbolAddress((void**)&o16b,  g_o16);
    cudaGetSymbolAddress((void**)&hhbuf, g_hh);
    cudaGetSymbolAddress((void**)&asrcb, g_asrc);
    cudaGetSymbolAddress((void**)&adstb, g_adst);
    cudaGetSymbolAddress((void**)&out1b, g_out1);
    cudaGetSymbolAddress((void**)&out2b, g_out2);
    cudaGetSymbolAddress((void**)&gateb, g_gate);

    int x8 = N * 128 / 8;
    int prepT = (x8 > 128 * 256) ? x8 : 128 * 256;

    // 0: prep
    prep_kernel<<<(prepT + 255) / 256, 256>>>((const long long*)ei, x, W1, W2, gw1, N, x8);
    // 1: convert
    int convT = 2 * E + N;
    convert_kernel<<<(convT + 255) / 256, 256>>>(ei, bt, E, N);
    // 2: fused CSR
    csr_kernel<<<CSRB, 256>>>(N, E);
    // 3: layer-1 GEMM (profiled slot)
    gemm_attn_kernel<<<NPAD / 64, 512>>>(x16b, w1hb, hhbuf, as1, ad1, asrcb, adstb, 128);
    // 4: layer-1 aggregate
    int wblocks = (N + 7) / 8;
    aggregate_kernel<<<wblocks, 256>>>(hhbuf, asrcb, adstb, b1, out1b, (uint4*)o16b, N);
    // 5-6: layer 2
    gemm_attn_kernel<<<NPAD / 64, 512>>>(o16b, w2hb, hhbuf, as2, ad2, asrcb, adstb, 64);
    aggregate_kernel<<<wblocks, 256>>>(hhbuf, asrcb, adstb, b2, out2b, (uint4*)o16b, N);
    // 7-9: gate, boundaries, pool+final
    gate_wmma_kernel<<<NPAD / 64, 128>>>(o16b, gw1hb, gb1, gam, bet, gw2, gb2, gateb, N);
    gptr_kernel<<<(N + 255) / 256, 256>>>(N);
    pool_kernel<<<GNUM, 256>>>(out2b, lw, lb, (float*)d_out, N);
}

// round 12
// speedup vs baseline: 1.5362x; 1.5362x over previous
#include <cuda_runtime.h>
#include <cuda_fp16.h>
#include <mma.h>
#include <math.h>
#include <stdint.h>

using namespace nvcuda;

#define NNODES 50000
#define NPAD   50048
#define NEDGES 800000
#define TOTE   (NEDGES + NNODES)
#define GNUM   64
#define NEG_SLOPE 0.2f
#define CSRB   ((NNODES + 255) / 256)   // 196 blocks, all resident

// ---------------- static device scratch ----------------
static __device__ int      g_is64;
static __device__ unsigned g_barcnt;
static __device__ unsigned g_bargen;
static __device__ int    g_src[NEDGES];
static __device__ int    g_dst[NEDGES];
static __device__ int    g_batch[NNODES];
static __device__ int    g_deg[NNODES];
static __device__ int    g_row[NNODES + 1];
static __device__ int    g_cur[NNODES];
static __device__ int    g_col[TOTE];
static __device__ int    g_bsum[CSRB];
static __device__ int    g_gptr[GNUM + 1];
static __device__ __half g_x16[(size_t)NPAD * 128];
static __device__ __half g_w1h[128 * 256];
static __device__ __half g_w2h[64 * 256];
static __device__ __half g_gw1h[64 * 64];
static __device__ __half g_o16[(size_t)NPAD * 64];
static __device__ uint4  g_hh[(size_t)NPAD * 32];
static __device__ float  g_asrc[NPAD * 4];
static __device__ float  g_adst[NPAD * 4];
static __device__ float  g_out1[(size_t)NNODES * 64];
static __device__ float  g_out2[(size_t)NNODES * 64];
static __device__ float  g_gate[NNODES];

// ---------------- prep: zero deg, detect dtype, fp16 weights, fp16 x ----------------
__global__ void prep_kernel(const long long* __restrict__ ei,
                            const float* __restrict__ x,
                            const float* __restrict__ W1,
                            const float* __restrict__ W2,
                            const float* __restrict__ gw1,
                            int N, int total8) {
    int i = blockIdx.x * blockDim.x + threadIdx.x;
    if (i < N) g_deg[i] = 0;
    if (i < 128 * 256) g_w1h[i] = __float2half(W1[i]);
    if (i < 64 * 256)  g_w2h[i] = __float2half(W2[i]);
    if (i < 64 * 64)   g_gw1h[i] = __float2half(gw1[i]);
    if (i < total8) {
        float4 a = ((const float4*)x)[2 * i];
        float4 b = ((const float4*)x)[2 * i + 1];
        __half h8[8] = {__float2half(a.x), __float2half(a.y), __float2half(a.z), __float2half(a.w),
                        __float2half(b.x), __float2half(b.y), __float2half(b.z), __float2half(b.w)};
        ((uint4*)g_x16)[i] = *(uint4*)h8;
    }
    if (blockIdx.x == 0 && threadIdx.x < 32) {
        long long v = ei[threadIdx.x];
        int ok = (v >= 0 && v < (long long)N);
        unsigned all = __all_sync(0xFFFFFFFFu, ok);
        if (threadIdx.x == 0) g_is64 = all ? 1 : 0;
    }
}

// ---------------- convert indices + batch + fused degree ----------------
__global__ void convert_kernel(const void* __restrict__ ei, const void* __restrict__ bt,
                               int E, int N) {
    int i = blockIdx.x * blockDim.x + threadIdx.x;
    int total = 2 * E + N;
    if (i >= total) return;
    int is64 = g_is64;
    if (i < 2 * E) {
        int v = is64 ? (int)((const long long*)ei)[i] : ((const int*)ei)[i];
        if (i < E) g_src[i] = v;
        else { g_dst[i - E] = v; atomicAdd(&g_deg[v], 1); }
    } else {
        int j = i - 2 * E;
        int v = is64 ? (int)((const long long*)bt)[j] : ((const int*)bt)[j];
        g_batch[j] = v;
    }
}

// ---------------- fused CSR: scan + offsets + scatter (grid barriers) ----------------
__device__ __forceinline__ void grid_barrier(int nblocks) {
    __threadfence();
    __syncthreads();
    if (threadIdx.x == 0) {
        unsigned gen = atomicAdd(&g_bargen, 0u);
        unsigned prev = atomicAdd(&g_barcnt, 1u);
        if (prev == (unsigned)(nblocks - 1)) {
            atomicExch(&g_barcnt, 0u);
            __threadfence();
            atomicAdd(&g_bargen, 1u);
        } else {
            while (atomicAdd(&g_bargen, 0u) == gen) { }
        }
    }
    __syncthreads();
}

__global__ void __launch_bounds__(256) csr_kernel(int N, int E) {
    __shared__ int ws[8];
    __shared__ int red[32];
    int tid = threadIdx.x, lane = tid & 31, wid = tid >> 5;
    int bid = blockIdx.x;
    int i = bid * 256 + tid;

    int x = (i < N) ? g_deg[i] + 1 : 0;
    int v = x;
    #pragma unroll
    for (int o = 1; o < 32; o <<= 1) {
        int u = __shfl_up_sync(0xFFFFFFFFu, v, o);
        if (lane >= o) v += u;
    }
    if (lane == 31) ws[wid] = v;
    __syncthreads();
    if (wid == 0) {
        int w = (lane < 8) ? ws[lane] : 0;
        #pragma unroll
        for (int o = 1; o < 8; o <<= 1) {
            int u = __shfl_up_sync(0xFFFFFFFFu, w, o);
            if (lane >= o) w += u;
        }
        if (lane < 8) ws[lane] = w;
    }
    __syncthreads();
    int incl = v + (wid ? ws[wid - 1] : 0);
    if (tid == 255) g_bsum[bid] = incl;

    grid_barrier(CSRB);

    int part = (tid < bid) ? g_bsum[tid] : 0;
    #pragma unroll
    for (int o = 16; o; o >>= 1) part += __shfl_xor_sync(0xFFFFFFFFu, part, o);
    if (lane == 0) red[wid] = part;
    __syncthreads();
    int off;
    {
        int t = (lane < 8) ? red[lane] : 0;
        #pragma unroll
        for (int o = 4; o; o >>= 1) t += __shfl_xor_sync(0xFFFFFFFFu, t, o);
        off = __shfl_sync(0xFFFFFFFFu, t, 0);
    }
    int r = incl - x + off;
    if (i < N) { g_row[i] = r; g_cur[i] = r; }
    if (i == 0) g_row[N] = E + N;

    grid_barrier(CSRB);

    for (int e = bid * 256 + tid; e < E + N; e += CSRB * 256) {
        int s, d;
        if (e < E) { s = g_src[e]; d = g_dst[e]; }
        else       { s = d = e - E; }
        int pos = atomicAdd(&g_cur[d], 1);
        g_col[pos] = s;
    }
}

// ---------------- smem-staged tensor-core GEMM, 16 warps, 16x64 warp tile ----------------
// Block: 512 thr (16 warps), 64 rows x 256 cols; forced 2 blocks/SM (64-reg cap) -> 50% occ.
// Synchronous LDG->STS staging (cp.async measured SLOWER on sm_103a for L2-hot tiles).
#define SM_AS_BYTES 17408                 // 64 * 136 halves (K=128 worst case)
#define SM_BS_BYTES 33792                 // 64 * 264 halves
__global__ void __launch_bounds__(512, 2) gemm_attn_kernel(const __half* __restrict__ A,
                                                           const __half* __restrict__ B,
                                                           uint4* __restrict__ C,
                                                           const float* __restrict__ att_src,
                                                           const float* __restrict__ att_dst,
                                                           float* __restrict__ asrc,
                                                           float* __restrict__ adst,
                                                           int K) {
    __shared__ __align__(16) char smbuf[SM_AS_BYTES + SM_BS_BYTES];
    __half* As = (__half*)smbuf;                       // [64][K+8]
    __half* Bs = (__half*)(smbuf + SM_AS_BYTES);       // [64][264]
    float*  Cs = (float*)smbuf;                        // [64][132] (epilogue reuse)
    int tid = threadIdx.x;
    int warp = tid >> 5;
    int by = blockIdx.x;
    int lda = K + 8;
    int row0 = by * 64;

    // stage A tile (64 x K)
    int kv = K >> 3;
    int nA = 64 * kv;
    for (int i = tid; i < nA; i += 512) {
        int r = i / kv, c = i - r * kv;
        uint4 v = ((const uint4*)(A + (size_t)(row0 + r) * K))[c];
        *(uint4*)(As + r * lda + c * 8) = v;
    }

    int wr = warp >> 2;          // 0..3: 16-row group
    int wc = warp & 3;           // 0..3: 64-col group
    wmma::fragment<wmma::accumulator, 16, 16, 16, float> cf[4];
    #pragma unroll
    for (int n = 0; n < 4; n++) wmma::fill_fragment(cf[n], 0.f);

    for (int k0 = 0; k0 < K; k0 += 64) {
        __syncthreads();
        // stage B chunk (64 x 256) = 2048 uint4
        for (int i = tid; i < 2048; i += 512) {
            int r = i >> 5, c = i & 31;
            uint4 v = ((const uint4*)(B + (size_t)(k0 + r) * 256))[c];
            *(uint4*)(Bs + r * 264 + c * 8) = v;
        }
        __syncthreads();
        #pragma unroll
        for (int ks = 0; ks < 64; ks += 16) {
            wmma::fragment<wmma::matrix_a, 16, 16, 16, __half, wmma::row_major> af;
            wmma::load_matrix_sync(af, As + (wr * 16) * lda + k0 + ks, lda);
            #pragma unroll
            for (int n = 0; n < 4; n++) {
                wmma::fragment<wmma::matrix_b, 16, 16, 16, __half, wmma::row_major> bf;
                wmma::load_matrix_sync(bf, Bs + ks * 264 + wc * 64 + n * 16, 264);
                wmma::mma_sync(cf[n], af, bf, cf[n]);
            }
        }
    }

    // epilogue: two waves (128 cols each) through reused smem, float4 reads
    int er = tid >> 3;           // row 0..63
    int cs8 = tid & 7;           // 16-col segment within the 128-col half
    #pragma unroll
    for (int wv = 0; wv < 2; wv++) {
        __syncthreads();
        if ((wc >> 1) == wv) {
            #pragma unroll
            for (int n = 0; n < 4; n++)
                wmma::store_matrix_sync(Cs + (wr * 16) * 132 + (wc & 1) * 64 + n * 16,
                                        cf[n], 132, wmma::mem_row_major);
        }
        __syncthreads();
        int gcol = wv * 128 + cs8 * 16;
        int head = gcol >> 6;
        int hoff = gcol & 63;
        float4 v4[4];
        #pragma unroll
        for (int q = 0; q < 4; q++)
            v4[q] = *(float4*)(Cs + er * 132 + cs8 * 16 + q * 4);
        const float* vv = (const float*)v4;
        float s = 0.f, d = 0.f;
        __half h16[16];
        #pragma unroll
        for (int c = 0; c < 16; c++) {
            float v = vv[c];
            s += v * __ldg(att_src + head * 64 + hoff + c);
            d += v * __ldg(att_dst + head * 64 + hoff + c);
            h16[c] = __float2half(v);
        }
        uint4* dst = C + (size_t)(row0 + er) * 32 + (gcol >> 3);
        uint4* srcp = (uint4*)h16;
        dst[0] = srcp[0];
        dst[1] = srcp[1];
        s += __shfl_xor_sync(0xFFFFFFFFu, s, 1);
        d += __shfl_xor_sync(0xFFFFFFFFu, d, 1);
        s += __shfl_xor_sync(0xFFFFFFFFu, s, 2);
        d += __shfl_xor_sync(0xFFFFFFFFu, d, 2);
        if ((tid & 3) == 0) {
            asrc[(row0 + er) * 4 + head] = s;
            adst[(row0 + er) * 4 + head] = d;
        }
    }
}

// ---------------- GAT aggregation: chunked smem-broadcast, gather-only inner loop ----------------
__device__ __forceinline__ void fma_half8(float* a, uint4 v, float w) {
    __half2* p = (__half2*)&v;
    #pragma unroll
    for (int q = 0; q < 4; q++) {
        float2 f = __half22float2(p[q]);
        a[2 * q]     += w * f.x;
        a[2 * q + 1] += w * f.y;
    }
}

__device__ __forceinline__ float lrelu(float e) { return (e > 0.f) ? e : NEG_SLOPE * e; }

__global__ void __launch_bounds__(256) aggregate_kernel(const uint4* __restrict__ hh,
                                                        const float* __restrict__ asrc,
                                                        const float* __restrict__ adst,
                                                        const float* __restrict__ bias,
                                                        float* __restrict__ out,
                                                        uint4* __restrict__ out16,
                                                        int N) {
    __shared__ int   ss[8][32];
    __shared__ float swt[8][4][32];
    int gw = (blockIdx.x * blockDim.x + threadIdx.x) >> 5;
    if (gw >= N) return;
    int wslot = (threadIdx.x >> 5);
    int lane = threadIdx.x & 31;
    int start = g_row[gw], end = g_row[gw + 1];
    int deg = end - start;
    float4 ad = *(const float4*)(adst + 4 * gw);
    int head = lane >> 3;

    float acc0[8], acc1[8];
    #pragma unroll
    for (int k = 0; k < 8; k++) { acc0[k] = 0.f; acc1[k] = 0.f; }
    float den = 0.f;

    if (deg <= 32) {
        int myj = start + lane;
        int mys = 0;
        float e0 = -1e30f, e1 = -1e30f, e2 = -1e30f, e3 = -1e30f;
        if (myj < end) {
            mys = g_col[myj];
            float4 q = *(const float4*)(asrc + 4 * mys);
            e0 = lrelu(q.x + ad.x); e1 = lrelu(q.y + ad.y);
            e2 = lrelu(q.z + ad.z); e3 = lrelu(q.w + ad.w);
        }
        float m0 = e0, m1 = e1, m2 = e2, m3 = e3;
        #pragma unroll
        for (int o = 16; o; o >>= 1) {
            m0 = fmaxf(m0, __shfl_xor_sync(0xFFFFFFFFu, m0, o));
            m1 = fmaxf(m1, __shfl_xor_sync(0xFFFFFFFFu, m1, o));
            m2 = fmaxf(m2, __shfl_xor_sync(0xFFFFFFFFu, m2, o));
            m3 = fmaxf(m3, __shfl_xor_sync(0xFFFFFFFFu, m3, o));
        }
        ss[wslot][lane] = mys;
        swt[wslot][0][lane] = (myj < end) ? expf(e0 - m0) : 0.f;
        swt[wslot][1][lane] = (myj < end) ? expf(e1 - m1) : 0.f;
        swt[wslot][2][lane] = (myj < end) ? expf(e2 - m2) : 0.f;
        swt[wslot][3][lane] = (myj < end) ? expf(e3 - m3) : 0.f;
        __syncwarp();
        int j = 0;
        for (; j + 4 <= deg; j += 4) {
            int s0 = ss[wslot][j], s1 = ss[wslot][j + 1];
            int s2 = ss[wslot][j + 2], s3 = ss[wslot][j + 3];
            float w0 = swt[wslot][head][j],     w1 = swt[wslot][head][j + 1];
            float w2 = swt[wslot][head][j + 2], w3 = swt[wslot][head][j + 3];
            uint4 v0 = hh[(size_t)s0 * 32 + lane];
            uint4 v1 = hh[(size_t)s1 * 32 + lane];
            uint4 v2 = hh[(size_t)s2 * 32 + lane];
            uint4 v3 = hh[(size_t)s3 * 32 + lane];
            den += (w0 + w1) + (w2 + w3);
            fma_half8(acc0, v0, w0);
            fma_half8(acc1, v1, w1);
            fma_half8(acc0, v2, w2);
            fma_half8(acc1, v3, w3);
        }
        for (; j < deg; j++) {
            int s0 = ss[wslot][j];
            float w0 = swt[wslot][head][j];
            uint4 v0 = hh[(size_t)s0 * 32 + lane];
            den += w0;
            fma_half8(acc0, v0, w0);
        }
        __syncwarp();
    } else {
        float m0 = -1e30f, m1 = -1e30f, m2 = -1e30f, m3 = -1e30f;
        for (int j = start + lane; j < end; j += 32) {
            int s = g_col[j];
            float4 q = *(const float4*)(asrc + 4 * s);
            m0 = fmaxf(m0, lrelu(q.x + ad.x));
            m1 = fmaxf(m1, lrelu(q.y + ad.y));
            m2 = fmaxf(m2, lrelu(q.z + ad.z));
            m3 = fmaxf(m3, lrelu(q.w + ad.w));
        }
        #pragma unroll
        for (int o = 16; o; o >>= 1) {
            m0 = fmaxf(m0, __shfl_xor_sync(0xFFFFFFFFu, m0, o));
            m1 = fmaxf(m1, __shfl_xor_sync(0xFFFFFFFFu, m1, o));
            m2 = fmaxf(m2, __shfl_xor_sync(0xFFFFFFFFu, m2, o));
            m3 = fmaxf(m3, __shfl_xor_sync(0xFFFFFFFFu, m3, o));
        }
        for (int base = start; base < end; base += 32) {
            int nn = min(32, end - base);
            int myj = base + lane;
            int mys = 0;
            float w0v = 0.f, w1v = 0.f, w2v = 0.f, w3v = 0.f;
            if (myj < end) {
                mys = g_col[myj];
                float4 q = *(const float4*)(asrc + 4 * mys);
                w0v = expf(lrelu(q.x + ad.x) - m0);
                w1v = expf(lrelu(q.y + ad.y) - m1);
                w2v = expf(lrelu(q.z + ad.z) - m2);
                w3v = expf(lrelu(q.w + ad.w) - m3);
            }
            ss[wslot][lane] = mys;
            swt[wslot][0][lane] = w0v;
            swt[wslot][1][lane] = w1v;
            swt[wslot][2][lane] = w2v;
            swt[wslot][3][lane] = w3v;
            __syncwarp();
            int j = 0;
            for (; j + 4 <= nn; j += 4) {
                int s0 = ss[wslot][j], s1 = ss[wslot][j + 1];
                int s2 = ss[wslot][j + 2], s3 = ss[wslot][j + 3];
                float w0 = swt[wslot][head][j],     w1 = swt[wslot][head][j + 1];
                float w2 = swt[wslot][head][j + 2], w3 = swt[wslot][head][j + 3];
                uint4 v0 = hh[(size_t)s0 * 32 + lane];
                uint4 v1 = hh[(size_t)s1 * 32 + lane];
                uint4 v2 = hh[(size_t)s2 * 32 + lane];
                uint4 v3 = hh[(size_t)s3 * 32 + lane];
                den += (w0 + w1) + (w2 + w3);
                fma_half8(acc0, v0, w0);
                fma_half8(acc1, v1, w1);
                fma_half8(acc0, v2, w2);
                fma_half8(acc1, v3, w3);
            }
            for (; j < nn; j++) {
                int s0 = ss[wslot][j];
                float w0 = swt[wslot][head][j];
                uint4 v0 = hh[(size_t)s0 * 32 + lane];
                den += w0;
                fma_half8(acc0, v0, w0);
            }
            __syncwarp();
        }
    }

    float inv = 1.f / (den + 1e-16f);
    float r[8];
    #pragma unroll
    for (int k = 0; k < 8; k++) r[k] = (acc0[k] + acc1[k]) * inv;
    #pragma unroll
    for (int k = 0; k < 8; ++k) {
        r[k] += __shfl_xor_sync(0xFFFFFFFFu, r[k], 8);
        r[k] += __shfl_xor_sync(0xFFFFFFFFu, r[k], 16);
    }
    if (lane < 8) {
        float o_[8];
        __half h8[8];
        #pragma unroll
        for (int k = 0; k < 8; ++k) {
            float v = 0.25f * r[k] + bias[lane * 8 + k];
            float sg = 1.f / (1.f + expf(-v));
            o_[k] = sg;
            h8[k] = __float2half(sg);
        }
        float4* op = (float4*)(out + (size_t)gw * 64 + lane * 8);
        op[0] = make_float4(o_[0], o_[1], o_[2], o_[3]);
        op[1] = make_float4(o_[4], o_[5], o_[6], o_[7]);
        out16[(size_t)gw * 8 + lane] = *(uint4*)h8;
    }
}

// ---------------- gate via wmma ----------------
__global__ void __launch_bounds__(128) gate_wmma_kernel(const __half* __restrict__ A,
                                                        const __half* __restrict__ B,
                                                        const float* __restrict__ gb1,
                                                        const float* __restrict__ gamma,
                                                        const float* __restrict__ beta,
                                                        const float* __restrict__ gw2,
                                                        const float* __restrict__ gb2,
                                                        float* __restrict__ gout, int N) {
    __shared__ float Cs[64 * 68];
    int tid = threadIdx.x;
    int warp = tid >> 5;
    int by = blockIdx.x;
    int row0 = by * 64 + warp * 16;

    wmma::fragment<wmma::accumulator, 16, 16, 16, float> cf[4];
    #pragma unroll
    for (int n = 0; n < 4; n++) wmma::fill_fragment(cf[n], 0.f);
    for (int k0 = 0; k0 < 64; k0 += 16) {
        wmma::fragment<wmma::matrix_a, 16, 16, 16, __half, wmma::row_major> af;
        wmma::load_matrix_sync(af, A + (size_t)row0 * 64 + k0, 64);
        #pragma unroll
        for (int n = 0; n < 4; n++) {
            wmma::fragment<wmma::matrix_b, 16, 16, 16, __half, wmma::row_major> bf;
            wmma::load_matrix_sync(bf, B + (size_t)k0 * 64 + n * 16, 64);
            wmma::mma_sync(cf[n], af, bf, cf[n]);
        }
    }
    #pragma unroll
    for (int n = 0; n < 4; n++)
        wmma::store_matrix_sync(Cs + warp * 16 * 68 + n * 16, cf[n], 68, wmma::mem_row_major);
    __syncthreads();

    int r = tid >> 1;
    int ch = (tid & 1) * 32;
    int row = by * 64 + r;
    float kinv = rsqrtf(1.0f + 1e-5f);
    float s = 0.f;
    #pragma unroll
    for (int c = 0; c < 32; c++) {
        float t = (Cs[r * 68 + ch + c] + __ldg(gb1 + ch + c)) * kinv * __ldg(gamma + ch + c)
                  + __ldg(beta + ch + c);
        t = fmaxf(t, 0.f);
        s += t * __ldg(gw2 + ch + c);
    }
    s += __shfl_xor_sync(0xFFFFFFFFu, s, 1);
    if ((tid & 1) == 0 && row < N) gout[row] = s + gb2[0];
}

// ---------------- per-graph boundaries (batch sorted) ----------------
__global__ void gptr_kernel(int N) {
    int v = blockIdx.x * blockDim.x + threadIdx.x;
    if (v >= N) return;
    int b = g_batch[v];
    if (v == 0) {
        for (int i = 0; i <= b; i++) g_gptr[i] = 0;
    } else {
        int bp = g_batch[v - 1];
        for (int i = bp + 1; i <= b; i++) g_gptr[i] = v;
    }
    if (v == N - 1) {
        for (int i = b + 1; i <= GNUM; i++) g_gptr[i] = N;
    }
}

// ---------------- pooling + final, fused ----------------
__global__ void __launch_bounds__(256) pool_kernel(const float* __restrict__ out2,
                                                   const float* __restrict__ lw,
                                                   const float* __restrict__ lb,
                                                   float* __restrict__ result, int N) {
    int b = blockIdx.x;
    int start = g_gptr[b], end = g_gptr[b + 1];
    __shared__ float smax[256];
    __shared__ float sacc[256];
    __shared__ float sden[4];
    int tid = threadIdx.x;
    float m = -1e30f;
    for (int v = start + tid; v < end; v += 256) m = fmaxf(m, g_gate[v]);
    smax[tid] = m;
    __syncthreads();
    for (int s = 128; s; s >>= 1) {
        if (tid < s) smax[tid] = fmaxf(smax[tid], smax[tid + s]);
        __syncthreads();
    }
    float mx = smax[0];
    __syncthreads();
    int c = tid & 63;
    int sub = tid >> 6;
    float acc = 0.f, dacc = 0.f;
    for (int v = start + sub; v < end; v += 4) {
        float w = expf(g_gate[v] - mx);
        acc += w * out2[(size_t)v * 64 + c];
        if (c == 0) dacc += w;
    }
    sacc[tid] = acc;
    if (c == 0) sden[sub] = dacc;
    __syncthreads();
    if (sub == 0) {
        float p = sacc[c] + sacc[64 + c] + sacc[128 + c] + sacc[192 + c];
        sacc[c] = p * __ldg(lw + c);
    }
    __syncthreads();
    if (tid < 32) {
        float t = sacc[tid] + sacc[tid + 32];
        #pragma unroll
        for (int o = 16; o; o >>= 1) t += __shfl_xor_sync(0xFFFFFFFFu, t, o);
        if (tid == 0) {
            float dt = sden[0] + sden[1] + sden[2] + sden[3];
            float s = t / (dt + 1e-16f) + lb[0];
            result[b] = 1.f / (1.f + expf(-s));
        }
    }
}

// ---------------- launch ----------------
extern "C" void kernel_launch(void* const* d_in, const int* in_sizes, int n_in,
                              void* d_out, int out_size) {
    const float* x  = (const float*)d_in[0];
    const void*  ei = d_in[1];
    const void*  bt = d_in[2];
    int o = (in_sizes[3] == 1) ? 1 : 0;
    const float* W1  = (const float*)d_in[3 + o];
    const float* as1 = (const float*)d_in[4 + o];
    const float* ad1 = (const float*)d_in[5 + o];
    const float* b1  = (const float*)d_in[6 + o];
    const float* W2  = (const float*)d_in[7 + o];
    const float* as2 = (const float*)d_in[8 + o];
    const float* ad2 = (const float*)d_in[9 + o];
    const float* b2  = (const float*)d_in[10 + o];
    const float* gw1 = (const float*)d_in[11 + o];
    const float* gb1 = (const float*)d_in[12 + o];
    const float* gam = (const float*)d_in[13 + o];
    const float* bet = (const float*)d_in[14 + o];
    const float* gw2 = (const float*)d_in[15 + o];
    const float* gb2 = (const float*)d_in[16 + o];
    const float* lw  = (const float*)d_in[17 + o];
    const float* lb  = (const float*)d_in[18 + o];

    int N = in_sizes[0] / 128;
    int E = in_sizes[1] / 2;

    __half *x16b, *w1hb, *w2hb, *gw1hb, *o16b;
    uint4* hhbuf;
    float *asrcb, *adstb, *out1b, *out2b, *gateb;
    cudaGetSymbolAddress((void**)&x16b,  g_x16);
    cudaGetSymbolAddress((void**)&w1hb,  g_w1h);
    cudaGetSymbolAddress((void**)&w2hb,  g_w2h);
    cudaGetSymbolAddress((void**)&gw1hb, g_gw1h);
    cudaGetSymbolAddress((void**)&o16b,  g_o16);
    cudaGetSymbolAddress((void**)&hhbuf, g_hh);
    cudaGetSymbolAddress((void**)&asrcb, g_asrc);
    cudaGetSymbolAddress((void**)&adstb, g_adst);
    cudaGetSymbolAddress((void**)&out1b, g_out1);
    cudaGetSymbolAddress((void**)&out2b, g_out2);
    cudaGetSymbolAddress((void**)&gateb, g_gate);

    int x8 = N * 128 / 8;
    int prepT = (x8 > 128 * 256) ? x8 : 128 * 256;

    // 0: prep
    prep_kernel<<<(prepT + 255) / 256, 256>>>((const long long*)ei, x, W1, W2, gw1, N, x8);
    // 1: convert
    int convT = 2 * E + N;
    convert_kernel<<<(convT + 255) / 256, 256>>>(ei, bt, E, N);
    // 2: fused CSR
    csr_kernel<<<CSRB, 256>>>(N, E);
    // 3: layer-1 GEMM (profiled slot)
    gemm_attn_kernel<<<NPAD / 64, 512>>>(x16b, w1hb, hhbuf, as1, ad1, asrcb, adstb, 128);
    // 4: layer-1 aggregate
    int wblocks = (N + 7) / 8;
    aggregate_kernel<<<wblocks, 256>>>(hhbuf, asrcb, adstb, b1, out1b, (uint4*)o16b, N);
    // 5-6: layer 2
    gemm_attn_kernel<<<NPAD / 64, 512>>>(o16b, w2hb, hhbuf, as2, ad2, asrcb, adstb, 64);
    aggregate_kernel<<<wblocks, 256>>>(hhbuf, asrcb, adstb, b2, out2b, (uint4*)o16b, N);
    // 7-9: gate, boundaries, pool+final
    gate_wmma_kernel<<<NPAD / 64, 128>>>(o16b, gw1hb, gb1, gam, bet, gw2, gb2, gateb, N);
    gptr_kernel<<<(N + 255) / 256, 256>>>(N);
    pool_kernel<<<GNUM, 256>>>(out2b, lw, lb, (float*)d_out, N);
}

// round 13
// speedup vs baseline: 1.5616x; 1.0165x over previous
#include <cuda_runtime.h>
#include <cuda_fp16.h>
#include <mma.h>
#include <math.h>
#include <stdint.h>

using namespace nvcuda;

#define NNODES 50000
#define NPAD   50048
#define NTILES (NPAD / 64)      // 782 row tiles
#define GEMMG  296              // persistent grid: 2 blocks/SM
#define NEDGES 800000
#define TOTE   (NEDGES + NNODES)
#define GNUM   64
#define NEG_SLOPE 0.2f
#define CSRB   ((NNODES + 255) / 256)

// ---------------- static device scratch ----------------
static __device__ int      g_is64;
static __device__ unsigned g_barcnt;
static __device__ unsigned g_bargen;
static __device__ int    g_src[NEDGES];
static __device__ int    g_dst[NEDGES];
static __device__ int    g_batch[NNODES];
static __device__ int    g_deg[NNODES];
static __device__ int    g_row[NNODES + 1];
static __device__ int    g_cur[NNODES];
static __device__ int    g_col[TOTE];
static __device__ int    g_bsum[CSRB];
static __device__ int    g_gptr[GNUM + 1];
static __device__ __half g_x16[(size_t)NPAD * 128];
static __device__ __half g_w1h[128 * 256];
static __device__ __half g_w2h[64 * 256];
static __device__ __half g_gw1h[64 * 64];
static __device__ __half g_o16[(size_t)NPAD * 64];
static __device__ uint4  g_hh[(size_t)NPAD * 32];
static __device__ float  g_asrc[NPAD * 4];
static __device__ float  g_adst[NPAD * 4];
static __device__ float  g_out1[(size_t)NNODES * 64];
static __device__ float  g_out2[(size_t)NNODES * 64];
static __device__ float  g_gate[NNODES];

// ---------------- prep: zero deg, detect dtype, fp16 weights, fp16 x ----------------
__global__ void prep_kernel(const long long* __restrict__ ei,
                            const float* __restrict__ x,
                            const float* __restrict__ W1,
                            const float* __restrict__ W2,
                            const float* __restrict__ gw1,
                            int N, int total8) {
    int i = blockIdx.x * blockDim.x + threadIdx.x;
    if (i < N) g_deg[i] = 0;
    if (i < 128 * 256) g_w1h[i] = __float2half(W1[i]);
    if (i < 64 * 256)  g_w2h[i] = __float2half(W2[i]);
    if (i < 64 * 64)   g_gw1h[i] = __float2half(gw1[i]);
    if (i < total8) {
        float4 a = ((const float4*)x)[2 * i];
        float4 b = ((const float4*)x)[2 * i + 1];
        __half h8[8] = {__float2half(a.x), __float2half(a.y), __float2half(a.z), __float2half(a.w),
                        __float2half(b.x), __float2half(b.y), __float2half(b.z), __float2half(b.w)};
        ((uint4*)g_x16)[i] = *(uint4*)h8;
    }
    if (blockIdx.x == 0 && threadIdx.x < 32) {
        long long v = ei[threadIdx.x];
        int ok = (v >= 0 && v < (long long)N);
        unsigned all = __all_sync(0xFFFFFFFFu, ok);
        if (threadIdx.x == 0) g_is64 = all ? 1 : 0;
    }
}

// ---------------- convert indices + batch + fused degree ----------------
__global__ void convert_kernel(const void* __restrict__ ei, const void* __restrict__ bt,
                               int E, int N) {
    int i = blockIdx.x * blockDim.x + threadIdx.x;
    int total = 2 * E + N;
    if (i >= total) return;
    int is64 = g_is64;
    if (i < 2 * E) {
        int v = is64 ? (int)((const long long*)ei)[i] : ((const int*)ei)[i];
        if (i < E) g_src[i] = v;
        else { g_dst[i - E] = v; atomicAdd(&g_deg[v], 1); }
    } else {
        int j = i - 2 * E;
        int v = is64 ? (int)((const long long*)bt)[j] : ((const int*)bt)[j];
        g_batch[j] = v;
    }
}

// ---------------- fused CSR: scan + offsets + scatter (grid barriers) ----------------
__device__ __forceinline__ void grid_barrier(int nblocks) {
    __threadfence();
    __syncthreads();
    if (threadIdx.x == 0) {
        unsigned gen = atomicAdd(&g_bargen, 0u);
        unsigned prev = atomicAdd(&g_barcnt, 1u);
        if (prev == (unsigned)(nblocks - 1)) {
            atomicExch(&g_barcnt, 0u);
            __threadfence();
            atomicAdd(&g_bargen, 1u);
        } else {
            while (atomicAdd(&g_bargen, 0u) == gen) { }
        }
    }
    __syncthreads();
}

__global__ void __launch_bounds__(256) csr_kernel(int N, int E) {
    __shared__ int ws[8];
    __shared__ int red[32];
    int tid = threadIdx.x, lane = tid & 31, wid = tid >> 5;
    int bid = blockIdx.x;
    int i = bid * 256 + tid;

    int x = (i < N) ? g_deg[i] + 1 : 0;
    int v = x;
    #pragma unroll
    for (int o = 1; o < 32; o <<= 1) {
        int u = __shfl_up_sync(0xFFFFFFFFu, v, o);
        if (lane >= o) v += u;
    }
    if (lane == 31) ws[wid] = v;
    __syncthreads();
    if (wid == 0) {
        int w = (lane < 8) ? ws[lane] : 0;
        #pragma unroll
        for (int o = 1; o < 8; o <<= 1) {
            int u = __shfl_up_sync(0xFFFFFFFFu, w, o);
            if (lane >= o) w += u;
        }
        if (lane < 8) ws[lane] = w;
    }
    __syncthreads();
    int incl = v + (wid ? ws[wid - 1] : 0);
    if (tid == 255) g_bsum[bid] = incl;

    grid_barrier(CSRB);

    int part = (tid < bid) ? g_bsum[tid] : 0;
    #pragma unroll
    for (int o = 16; o; o >>= 1) part += __shfl_xor_sync(0xFFFFFFFFu, part, o);
    if (lane == 0) red[wid] = part;
    __syncthreads();
    int off;
    {
        int t = (lane < 8) ? red[lane] : 0;
        #pragma unroll
        for (int o = 4; o; o >>= 1) t += __shfl_xor_sync(0xFFFFFFFFu, t, o);
        off = __shfl_sync(0xFFFFFFFFu, t, 0);
    }
    int r = incl - x + off;
    if (i < N) { g_row[i] = r; g_cur[i] = r; }
    if (i == 0) g_row[N] = E + N;

    grid_barrier(CSRB);

    for (int e = bid * 256 + tid; e < E + N; e += CSRB * 256) {
        int s, d;
        if (e < E) { s = g_src[e]; d = g_dst[e]; }
        else       { s = d = e - E; }
        int pos = atomicAdd(&g_cur[d], 1);
        g_col[pos] = s;
    }
}

// ---------------- persistent tensor-core GEMM: B staged ONCE per block ----------------
// Grid = 296 (2 blocks/SM). Dynamic smem: Bs[K][264] then scratch {As[64][K+8] | Cs[64][132]}.
// Each block loops over row tiles t = bid, bid+296, ... B survives (Cs never overlaps Bs).
extern __shared__ char dynsm[];
__global__ void __launch_bounds__(512, 2) gemm_attn_kernel(const __half* __restrict__ A,
                                                           const __half* __restrict__ B,
                                                           uint4* __restrict__ C,
                                                           const float* __restrict__ att_src,
                                                           const float* __restrict__ att_dst,
                                                           float* __restrict__ asrc,
                                                           float* __restrict__ adst,
                                                           int K) {
    __half* Bs = (__half*)dynsm;                           // [K][264]
    char* scratch = dynsm + (size_t)K * 264 * 2;
    __half* As = (__half*)scratch;                         // [64][K+8]
    float*  Cs = (float*)scratch;                          // [64][132]
    int tid = threadIdx.x;
    int warp = tid >> 5;
    int lda = K + 8;

    // stage full B once: K rows x 32 uint4
    int nB = K * 32;
    for (int i = tid; i < nB; i += 512) {
        int r = i >> 5, c = i & 31;
        uint4 v = ((const uint4*)(B + (size_t)r * 256))[c];
        *(uint4*)(Bs + r * 264 + c * 8) = v;
    }

    int wr = warp >> 2;          // 0..3: 16-row group
    int wc = warp & 3;           // 0..3: 64-col group
    int kv = K >> 3;
    int nA = 64 * kv;

    for (int t = blockIdx.x; t < NTILES; t += GEMMG) {
        int row0 = t * 64;
        __syncthreads();         // Bs ready (1st iter) / prior epilogue reads done
        for (int i = tid; i < nA; i += 512) {
            int r = i / kv, c = i - r * kv;
            uint4 v = ((const uint4*)(A + (size_t)(row0 + r) * K))[c];
            *(uint4*)(As + r * lda + c * 8) = v;
        }
        __syncthreads();

        wmma::fragment<wmma::accumulator, 16, 16, 16, float> cf[4];
        #pragma unroll
        for (int n = 0; n < 4; n++) wmma::fill_fragment(cf[n], 0.f);
        for (int ks = 0; ks < K; ks += 16) {
            wmma::fragment<wmma::matrix_a, 16, 16, 16, __half, wmma::row_major> af;
            wmma::load_matrix_sync(af, As + (wr * 16) * lda + ks, lda);
            #pragma unroll
            for (int n = 0; n < 4; n++) {
                wmma::fragment<wmma::matrix_b, 16, 16, 16, __half, wmma::row_major> bf;
                wmma::load_matrix_sync(bf, Bs + ks * 264 + wc * 64 + n * 16, 264);
                wmma::mma_sync(cf[n], af, bf, cf[n]);
            }
        }
        __syncthreads();         // MMA done reading As before Cs overwrite

        // epilogue: two waves (128 cols each) through scratch, float4 reads
        int er = tid >> 3;
        int cs8 = tid & 7;
        #pragma unroll
        for (int wv = 0; wv < 2; wv++) {
            if (wv) __syncthreads();
            if ((wc >> 1) == wv) {
                #pragma unroll
                for (int n = 0; n < 4; n++)
                    wmma::store_matrix_sync(Cs + (wr * 16) * 132 + (wc & 1) * 64 + n * 16,
                                            cf[n], 132, wmma::mem_row_major);
            }
            __syncthreads();
            int gcol = wv * 128 + cs8 * 16;
            int head = gcol >> 6;
            int hoff = gcol & 63;
            float4 v4[4];
            #pragma unroll
            for (int q = 0; q < 4; q++)
                v4[q] = *(float4*)(Cs + er * 132 + cs8 * 16 + q * 4);
            const float* vv = (const float*)v4;
            float s = 0.f, d = 0.f;
            __half h16[16];
            #pragma unroll
            for (int c = 0; c < 16; c++) {
                float v = vv[c];
                s += v * __ldg(att_src + head * 64 + hoff + c);
                d += v * __ldg(att_dst + head * 64 + hoff + c);
                h16[c] = __float2half(v);
            }
            uint4* dst = C + (size_t)(row0 + er) * 32 + (gcol >> 3);
            uint4* srcp = (uint4*)h16;
            dst[0] = srcp[0];
            dst[1] = srcp[1];
            s += __shfl_xor_sync(0xFFFFFFFFu, s, 1);
            d += __shfl_xor_sync(0xFFFFFFFFu, d, 1);
            s += __shfl_xor_sync(0xFFFFFFFFu, s, 2);
            d += __shfl_xor_sync(0xFFFFFFFFu, d, 2);
            if ((tid & 3) == 0) {
                asrc[(row0 + er) * 4 + head] = s;
                adst[(row0 + er) * 4 + head] = d;
            }
        }
    }
}

// ---------------- GAT aggregation: chunked smem-broadcast, gather-only inner loop ----------------
__device__ __forceinline__ void fma_half8(float* a, uint4 v, float w) {
    __half2* p = (__half2*)&v;
    #pragma unroll
    for (int q = 0; q < 4; q++) {
        float2 f = __half22float2(p[q]);
        a[2 * q]     += w * f.x;
        a[2 * q + 1] += w * f.y;
    }
}

__device__ __forceinline__ float lrelu(float e) { return (e > 0.f) ? e : NEG_SLOPE * e; }

__global__ void __launch_bounds__(256) aggregate_kernel(const uint4* __restrict__ hh,
                                                        const float* __restrict__ asrc,
                                                        const float* __restrict__ adst,
                                                        const float* __restrict__ bias,
                                                        float* __restrict__ out,
                                                        uint4* __restrict__ out16,
                                                        int N) {
    __shared__ int   ss[8][32];
    __shared__ float swt[8][4][32];
    int gw = (blockIdx.x * blockDim.x + threadIdx.x) >> 5;
    if (gw >= N) return;
    int wslot = (threadIdx.x >> 5);
    int lane = threadIdx.x & 31;
    int start = g_row[gw], end = g_row[gw + 1];
    int deg = end - start;
    float4 ad = *(const float4*)(adst + 4 * gw);
    int head = lane >> 3;

    float acc0[8], acc1[8];
    #pragma unroll
    for (int k = 0; k < 8; k++) { acc0[k] = 0.f; acc1[k] = 0.f; }
    float den = 0.f;

    if (deg <= 32) {
        int myj = start + lane;
        int mys = 0;
        float e0 = -1e30f, e1 = -1e30f, e2 = -1e30f, e3 = -1e30f;
        if (myj < end) {
            mys = g_col[myj];
            float4 q = *(const float4*)(asrc + 4 * mys);
            e0 = lrelu(q.x + ad.x); e1 = lrelu(q.y + ad.y);
            e2 = lrelu(q.z + ad.z); e3 = lrelu(q.w + ad.w);
        }
        float m0 = e0, m1 = e1, m2 = e2, m3 = e3;
        #pragma unroll
        for (int o = 16; o; o >>= 1) {
            m0 = fmaxf(m0, __shfl_xor_sync(0xFFFFFFFFu, m0, o));
            m1 = fmaxf(m1, __shfl_xor_sync(0xFFFFFFFFu, m1, o));
            m2 = fmaxf(m2, __shfl_xor_sync(0xFFFFFFFFu, m2, o));
            m3 = fmaxf(m3, __shfl_xor_sync(0xFFFFFFFFu, m3, o));
        }
        ss[wslot][lane] = mys;
        swt[wslot][0][lane] = (myj < end) ? expf(e0 - m0) : 0.f;
        swt[wslot][1][lane] = (myj < end) ? expf(e1 - m1) : 0.f;
        swt[wslot][2][lane] = (myj < end) ? expf(e2 - m2) : 0.f;
        swt[wslot][3][lane] = (myj < end) ? expf(e3 - m3) : 0.f;
        __syncwarp();
        int j = 0;
        for (; j + 4 <= deg; j += 4) {
            int s0 = ss[wslot][j], s1 = ss[wslot][j + 1];
            int s2 = ss[wslot][j + 2], s3 = ss[wslot][j + 3];
            float w0 = swt[wslot][head][j],     w1 = swt[wslot][head][j + 1];
            float w2 = swt[wslot][head][j + 2], w3 = swt[wslot][head][j + 3];
            uint4 v0 = hh[(size_t)s0 * 32 + lane];
            uint4 v1 = hh[(size_t)s1 * 32 + lane];
            uint4 v2 = hh[(size_t)s2 * 32 + lane];
            uint4 v3 = hh[(size_t)s3 * 32 + lane];
            den += (w0 + w1) + (w2 + w3);
            fma_half8(acc0, v0, w0);
            fma_half8(acc1, v1, w1);
            fma_half8(acc0, v2, w2);
            fma_half8(acc1, v3, w3);
        }
        for (; j < deg; j++) {
            int s0 = ss[wslot][j];
            float w0 = swt[wslot][head][j];
            uint4 v0 = hh[(size_t)s0 * 32 + lane];
            den += w0;
            fma_half8(acc0, v0, w0);
        }
        __syncwarp();
    } else {
        float m0 = -1e30f, m1 = -1e30f, m2 = -1e30f, m3 = -1e30f;
        for (int j = start + lane; j < end; j += 32) {
            int s = g_col[j];
            float4 q = *(const float4*)(asrc + 4 * s);
            m0 = fmaxf(m0, lrelu(q.x + ad.x));
            m1 = fmaxf(m1, lrelu(q.y + ad.y));
            m2 = fmaxf(m2, lrelu(q.z + ad.z));
            m3 = fmaxf(m3, lrelu(q.w + ad.w));
        }
        #pragma unroll
        for (int o = 16; o; o >>= 1) {
            m0 = fmaxf(m0, __shfl_xor_sync(0xFFFFFFFFu, m0, o));
            m1 = fmaxf(m1, __shfl_xor_sync(0xFFFFFFFFu, m1, o));
            m2 = fmaxf(m2, __shfl_xor_sync(0xFFFFFFFFu, m2, o));
            m3 = fmaxf(m3, __shfl_xor_sync(0xFFFFFFFFu, m3, o));
        }
        for (int base = start; base < end; base += 32) {
            int nn = min(32, end - base);
            int myj = base + lane;
            int mys = 0;
            float w0v = 0.f, w1v = 0.f, w2v = 0.f, w3v = 0.f;
            if (myj < end) {
                mys = g_col[myj];
                float4 q = *(const float4*)(asrc + 4 * mys);
                w0v = expf(lrelu(q.x + ad.x) - m0);
                w1v = expf(lrelu(q.y + ad.y) - m1);
                w2v = expf(lrelu(q.z + ad.z) - m2);
                w3v = expf(lrelu(q.w + ad.w) - m3);
            }
            ss[wslot][lane] = mys;
            swt[wslot][0][lane] = w0v;
            swt[wslot][1][lane] = w1v;
            swt[wslot][2][lane] = w2v;
            swt[wslot][3][lane] = w3v;
            __syncwarp();
            int j = 0;
            for (; j + 4 <= nn; j += 4) {
                int s0 = ss[wslot][j], s1 = ss[wslot][j + 1];
                int s2 = ss[wslot][j + 2], s3 = ss[wslot][j + 3];
                float w0 = swt[wslot][head][j],     w1 = swt[wslot][head][j + 1];
                float w2 = swt[wslot][head][j + 2], w3 = swt[wslot][head][j + 3];
                uint4 v0 = hh[(size_t)s0 * 32 + lane];
                uint4 v1 = hh[(size_t)s1 * 32 + lane];
                uint4 v2 = hh[(size_t)s2 * 32 + lane];
                uint4 v3 = hh[(size_t)s3 * 32 + lane];
                den += (w0 + w1) + (w2 + w3);
                fma_half8(acc0, v0, w0);
                fma_half8(acc1, v1, w1);
                fma_half8(acc0, v2, w2);
                fma_half8(acc1, v3, w3);
            }
            for (; j < nn; j++) {
                int s0 = ss[wslot][j];
                float w0 = swt[wslot][head][j];
                uint4 v0 = hh[(size_t)s0 * 32 + lane];
                den += w0;
                fma_half8(acc0, v0, w0);
            }
            __syncwarp();
        }
    }

    float inv = 1.f / (den + 1e-16f);
    float r[8];
    #pragma unroll
    for (int k = 0; k < 8; k++) r[k] = (acc0[k] + acc1[k]) * inv;
    #pragma unroll
    for (int k = 0; k < 8; ++k) {
        r[k] += __shfl_xor_sync(0xFFFFFFFFu, r[k], 8);
        r[k] += __shfl_xor_sync(0xFFFFFFFFu, r[k], 16);
    }
    if (lane < 8) {
        float o_[8];
        __half h8[8];
        #pragma unroll
        for (int k = 0; k < 8; ++k) {
            float v = 0.25f * r[k] + bias[lane * 8 + k];
            float sg = 1.f / (1.f + expf(-v));
            o_[k] = sg;
            h8[k] = __float2half(sg);
        }
        float4* op = (float4*)(out + (size_t)gw * 64 + lane * 8);
        op[0] = make_float4(o_[0], o_[1], o_[2], o_[3]);
        op[1] = make_float4(o_[4], o_[5], o_[6], o_[7]);
        out16[(size_t)gw * 8 + lane] = *(uint4*)h8;
    }
}

// ---------------- gate via wmma ----------------
__global__ void __launch_bounds__(128) gate_wmma_kernel(const __half* __restrict__ A,
                                                        const __half* __restrict__ B,
                                                        const float* __restrict__ gb1,
                                                        const float* __restrict__ gamma,
                                                        const float* __restrict__ beta,
                                                        const float* __restrict__ gw2,
                                                        const float* __restrict__ gb2,
                                                        float* __restrict__ gout, int N) {
    __shared__ float Cs[64 * 68];
    int tid = threadIdx.x;
    int warp = tid >> 5;
    int by = blockIdx.x;
    int row0 = by * 64 + warp * 16;

    wmma::fragment<wmma::accumulator, 16, 16, 16, float> cf[4];
    #pragma unroll
    for (int n = 0; n < 4; n++) wmma::fill_fragment(cf[n], 0.f);
    for (int k0 = 0; k0 < 64; k0 += 16) {
        wmma::fragment<wmma::matrix_a, 16, 16, 16, __half, wmma::row_major> af;
        wmma::load_matrix_sync(af, A + (size_t)row0 * 64 + k0, 64);
        #pragma unroll
        for (int n = 0; n < 4; n++) {
            wmma::fragment<wmma::matrix_b, 16, 16, 16, __half, wmma::row_major> bf;
            wmma::load_matrix_sync(bf, B + (size_t)k0 * 64 + n * 16, 64);
            wmma::mma_sync(cf[n], af, bf, cf[n]);
        }
    }
    #pragma unroll
    for (int n = 0; n < 4; n++)
        wmma::store_matrix_sync(Cs + warp * 16 * 68 + n * 16, cf[n], 68, wmma::mem_row_major);
    __syncthreads();

    int r = tid >> 1;
    int ch = (tid & 1) * 32;
    int row = by * 64 + r;
    float kinv = rsqrtf(1.0f + 1e-5f);
    float s = 0.f;
    #pragma unroll
    for (int c = 0; c < 32; c++) {
        float t = (Cs[r * 68 + ch + c] + __ldg(gb1 + ch + c)) * kinv * __ldg(gamma + ch + c)
                  + __ldg(beta + ch + c);
        t = fmaxf(t, 0.f);
        s += t * __ldg(gw2 + ch + c);
    }
    s += __shfl_xor_sync(0xFFFFFFFFu, s, 1);
    if ((tid & 1) == 0 && row < N) gout[row] = s + gb2[0];
}

// ---------------- per-graph boundaries (batch sorted) ----------------
__global__ void gptr_kernel(int N) {
    int v = blockIdx.x * blockDim.x + threadIdx.x;
    if (v >= N) return;
    int b = g_batch[v];
    if (v == 0) {
        for (int i = 0; i <= b; i++) g_gptr[i] = 0;
    } else {
        int bp = g_batch[v - 1];
        for (int i = bp + 1; i <= b; i++) g_gptr[i] = v;
    }
    if (v == N - 1) {
        for (int i = b + 1; i <= GNUM; i++) g_gptr[i] = N;
    }
}

// ---------------- pooling + final, fused ----------------
__global__ void __launch_bounds__(256) pool_kernel(const float* __restrict__ out2,
                                                   const float* __restrict__ lw,
                                                   const float* __restrict__ lb,
                                                   float* __restrict__ result, int N) {
    int b = blockIdx.x;
    int start = g_gptr[b], end = g_gptr[b + 1];
    __shared__ float smax[256];
    __shared__ float sacc[256];
    __shared__ float sden[4];
    int tid = threadIdx.x;
    float m = -1e30f;
    for (int v = start + tid; v < end; v += 256) m = fmaxf(m, g_gate[v]);
    smax[tid] = m;
    __syncthreads();
    for (int s = 128; s; s >>= 1) {
        if (tid < s) smax[tid] = fmaxf(smax[tid], smax[tid + s]);
        __syncthreads();
    }
    float mx = smax[0];
    __syncthreads();
    int c = tid & 63;
    int sub = tid >> 6;
    float acc = 0.f, dacc = 0.f;
    for (int v = start + sub; v < end; v += 4) {
        float w = expf(g_gate[v] - mx);
        acc += w * out2[(size_t)v * 64 + c];
        if (c == 0) dacc += w;
    }
    sacc[tid] = acc;
    if (c == 0) sden[sub] = dacc;
    __syncthreads();
    if (sub == 0) {
        float p = sacc[c] + sacc[64 + c] + sacc[128 + c] + sacc[192 + c];
        sacc[c] = p * __ldg(lw + c);
    }
    __syncthreads();
    if (tid < 32) {
        float t = sacc[tid] + sacc[tid + 32];
        #pragma unroll
        for (int o = 16; o; o >>= 1) t += __shfl_xor_sync(0xFFFFFFFFu, t, o);
        if (tid == 0) {
            float dt = sden[0] + sden[1] + sden[2] + sden[3];
            float s = t / (dt + 1e-16f) + lb[0];
            result[b] = 1.f / (1.f + expf(-s));
        }
    }
}

// ---------------- launch ----------------
extern "C" void kernel_launch(void* const* d_in, const int* in_sizes, int n_in,
                              void* d_out, int out_size) {
    const float* x  = (const float*)d_in[0];
    const void*  ei = d_in[1];
    const void*  bt = d_in[2];
    int o = (in_sizes[3] == 1) ? 1 : 0;
    const float* W1  = (const float*)d_in[3 + o];
    const float* as1 = (const float*)d_in[4 + o];
    const float* ad1 = (const float*)d_in[5 + o];
    const float* b1  = (const float*)d_in[6 + o];
    const float* W2  = (const float*)d_in[7 + o];
    const float* as2 = (const float*)d_in[8 + o];
    const float* ad2 = (const float*)d_in[9 + o];
    const float* b2  = (const float*)d_in[10 + o];
    const float* gw1 = (const float*)d_in[11 + o];
    const float* gb1 = (const float*)d_in[12 + o];
    const float* gam = (const float*)d_in[13 + o];
    const float* bet = (const float*)d_in[14 + o];
    const float* gw2 = (const float*)d_in[15 + o];
    const float* gb2 = (const float*)d_in[16 + o];
    const float* lw  = (const float*)d_in[17 + o];
    const float* lb  = (const float*)d_in[18 + o];

    int N = in_sizes[0] / 128;
    int E = in_sizes[1] / 2;

    __half *x16b, *w1hb, *w2hb, *gw1hb, *o16b;
    uint4* hhbuf;
    float *asrcb, *adstb, *out1b, *out2b, *gateb;
    cudaGetSymbolAddress((void**)&x16b,  g_x16);
    cudaGetSymbolAddress((void**)&w1hb,  g_w1h);
    cudaGetSymbolAddress((void**)&w2hb,  g_w2h);
    cudaGetSymbolAddress((void**)&gw1hb, g_gw1h);
    cudaGetSymbolAddress((void**)&o16b,  g_o16);
    cudaGetSymbolAddress((void**)&hhbuf, g_hh);
    cudaGetSymbolAddress((void**)&asrcb, g_asrc);
    cudaGetSymbolAddress((void**)&adstb, g_adst);
    cudaGetSymbolAddress((void**)&out1b, g_out1);
    cudaGetSymbolAddress((void**)&out2b, g_out2);
    cudaGetSymbolAddress((void**)&gateb, g_gate);

    // dynamic smem sizes: Bs[K][264] halves + scratch max(As, Cs[64][132] fp32)
    int smem1 = 128 * 264 * 2 + 64 * 132 * 4;   // 101376 (K=128)
    int smem2 = 64 * 264 * 2 + 64 * 132 * 4;    //  67584 (K=64)
    static int attr_set = 0;
    if (!attr_set) {
        cudaFuncSetAttribute(gemm_attn_kernel,
                             cudaFuncAttributeMaxDynamicSharedMemorySize, smem1);
        attr_set = 1;
    }

    int x8 = N * 128 / 8;
    int prepT = (x8 > 128 * 256) ? x8 : 128 * 256;

    // 0: prep
    prep_kernel<<<(prepT + 255) / 256, 256>>>((const long long*)ei, x, W1, W2, gw1, N, x8);
    // 1: convert
    int convT = 2 * E + N;
    convert_kernel<<<(convT + 255) / 256, 256>>>(ei, bt, E, N);
    // 2: fused CSR
    csr_kernel<<<CSRB, 256>>>(N, E);
    // 3: layer-1 GEMM (persistent, B staged once per block)
    gemm_attn_kernel<<<GEMMG, 512, smem1>>>(x16b, w1hb, hhbuf, as1, ad1, asrcb, adstb, 128);
    // 4: layer-1 aggregate
    int wblocks = (N + 7) / 8;
    aggregate_kernel<<<wblocks, 256>>>(hhbuf, asrcb, adstb, b1, out1b, (uint4*)o16b, N);
    // 5-6: layer 2
    gemm_attn_kernel<<<GEMMG, 512, smem2>>>(o16b, w2hb, hhbuf, as2, ad2, asrcb, adstb, 64);
    aggregate_kernel<<<wblocks, 256>>>(hhbuf, asrcb, adstb, b2, out2b, (uint4*)o16b, N);
    // 7-9: gate, boundaries, pool+final
    gate_wmma_kernel<<<NPAD / 64, 128>>>(o16b, gw1hb, gb1, gam, bet, gw2, gb2, gateb, N);
    gptr_kernel<<<(N + 255) / 256, 256>>>(N);
    pool_kernel<<<GNUM, 256>>>(out2b, lw, lb, (float*)d_out, N);
}

// round 14
// speedup vs baseline: 1.5775x; 1.0102x over previous
#include <cuda_runtime.h>
#include <cuda_fp16.h>
#include <mma.h>
#include <math.h>
#include <stdint.h>

using namespace nvcuda;

#define NNODES 50000
#define NPAD   50048
#define NTILES (NPAD / 64)      // 782 row tiles
#define GEMMG  296              // persistent grid: 2 blocks/SM
#define NEDGES 800000
#define TOTE   (NEDGES + NNODES)
#define GNUM   64
#define NEG_SLOPE 0.2f
#define CSRB   ((NNODES + 255) / 256)

// ---------------- static device scratch ----------------
static __device__ int      g_is64;
static __device__ unsigned g_barcnt;
static __device__ unsigned g_bargen;
static __device__ int    g_batch[NNODES];
static __device__ int    g_deg[NNODES];
static __device__ int    g_row[NNODES + 1];
static __device__ int    g_cur[NNODES];
static __device__ int    g_col[TOTE];
static __device__ int    g_bsum[CSRB];
static __device__ __half g_x16[(size_t)NPAD * 128];
static __device__ __half g_w1h[128 * 256];
static __device__ __half g_w2h[64 * 256];
static __device__ __half g_gw1h[64 * 64];
static __device__ __half g_o16[(size_t)NPAD * 64];
static __device__ uint4  g_hh[(size_t)NPAD * 32];
static __device__ float  g_asrc[NPAD * 4];
static __device__ float  g_adst[NPAD * 4];
static __device__ float  g_out1[(size_t)NNODES * 64];
static __device__ float  g_out2[(size_t)NNODES * 64];
static __device__ float  g_gate[NNODES];

__device__ __forceinline__ int ld_idx(const void* ei, int is64, int idx) {
    return is64 ? (int)((const long long*)ei)[idx] : ((const int*)ei)[idx];
}

// ---------------- prep: zero deg, detect dtype, fp16 weights, fp16 x ----------------
__global__ void prep_kernel(const long long* __restrict__ ei,
                            const float* __restrict__ x,
                            const float* __restrict__ W1,
                            const float* __restrict__ W2,
                            const float* __restrict__ gw1,
                            int N, int total8) {
    int i = blockIdx.x * blockDim.x + threadIdx.x;
    if (i < N) g_deg[i] = 0;
    if (i < 128 * 256) g_w1h[i] = __float2half(W1[i]);
    if (i < 64 * 256)  g_w2h[i] = __float2half(W2[i]);
    if (i < 64 * 64)   g_gw1h[i] = __float2half(gw1[i]);
    if (i < total8) {
        float4 a = ((const float4*)x)[2 * i];
        float4 b = ((const float4*)x)[2 * i + 1];
        __half h8[8] = {__float2half(a.x), __float2half(a.y), __float2half(a.z), __float2half(a.w),
                        __float2half(b.x), __float2half(b.y), __float2half(b.z), __float2half(b.w)};
        ((uint4*)g_x16)[i] = *(uint4*)h8;
    }
    if (blockIdx.x == 0 && threadIdx.x < 32) {
        long long v = ei[threadIdx.x];
        int ok = (v >= 0 && v < (long long)N);
        unsigned all = __all_sync(0xFFFFFFFFu, ok);
        if (threadIdx.x == 0) g_is64 = all ? 1 : 0;
    }
}

// ---------------- convert: batch to int + degree count (reads ei directly) ----------------
__global__ void convert_kernel(const void* __restrict__ ei, const void* __restrict__ bt,
                               int E, int N) {
    int i = blockIdx.x * blockDim.x + threadIdx.x;
    if (i >= E + N) return;
    int is64 = g_is64;
    if (i < E) {
        int d = ld_idx(ei, is64, E + i);   // dst = edge_index[1][i]
        atomicAdd(&g_deg[d], 1);
    } else {
        int j = i - E;
        int v = is64 ? (int)((const long long*)bt)[j] : ((const int*)bt)[j];
        g_batch[j] = v;
    }
}

// ---------------- fused CSR: scan + offsets + scatter (grid barriers) ----------------
__device__ __forceinline__ void grid_barrier(int nblocks) {
    __threadfence();
    __syncthreads();
    if (threadIdx.x == 0) {
        unsigned gen = atomicAdd(&g_bargen, 0u);
        unsigned prev = atomicAdd(&g_barcnt, 1u);
        if (prev == (unsigned)(nblocks - 1)) {
            atomicExch(&g_barcnt, 0u);
            __threadfence();
            atomicAdd(&g_bargen, 1u);
        } else {
            while (atomicAdd(&g_bargen, 0u) == gen) { }
        }
    }
    __syncthreads();
}

__global__ void __launch_bounds__(256) csr_kernel(const void* __restrict__ ei, int N, int E) {
    __shared__ int ws[8];
    __shared__ int red[32];
    int tid = threadIdx.x, lane = tid & 31, wid = tid >> 5;
    int bid = blockIdx.x;
    int i = bid * 256 + tid;

    int x = (i < N) ? g_deg[i] + 1 : 0;
    int v = x;
    #pragma unroll
    for (int o = 1; o < 32; o <<= 1) {
        int u = __shfl_up_sync(0xFFFFFFFFu, v, o);
        if (lane >= o) v += u;
    }
    if (lane == 31) ws[wid] = v;
    __syncthreads();
    if (wid == 0) {
        int w = (lane < 8) ? ws[lane] : 0;
        #pragma unroll
        for (int o = 1; o < 8; o <<= 1) {
            int u = __shfl_up_sync(0xFFFFFFFFu, w, o);
            if (lane >= o) w += u;
        }
        if (lane < 8) ws[lane] = w;
    }
    __syncthreads();
    int incl = v + (wid ? ws[wid - 1] : 0);
    if (tid == 255) g_bsum[bid] = incl;

    grid_barrier(CSRB);

    int part = (tid < bid) ? g_bsum[tid] : 0;
    #pragma unroll
    for (int o = 16; o; o >>= 1) part += __shfl_xor_sync(0xFFFFFFFFu, part, o);
    if (lane == 0) red[wid] = part;
    __syncthreads();
    int off;
    {
        int t = (lane < 8) ? red[lane] : 0;
        #pragma unroll
        for (int o = 4; o; o >>= 1) t += __shfl_xor_sync(0xFFFFFFFFu, t, o);
        off = __shfl_sync(0xFFFFFFFFu, t, 0);
    }
    int r = incl - x + off;
    if (i < N) { g_row[i] = r; g_cur[i] = r; }
    if (i == 0) g_row[N] = E + N;

    grid_barrier(CSRB);

    int is64 = g_is64;
    for (int e = bid * 256 + tid; e < E + N; e += CSRB * 256) {
        int s, d;
        if (e < E) { s = ld_idx(ei, is64, e); d = ld_idx(ei, is64, E + e); }
        else       { s = d = e - E; }
        int pos = atomicAdd(&g_cur[d], 1);
        g_col[pos] = s;
    }
}

// ---------------- persistent tensor-core GEMM: B staged ONCE per block ----------------
extern __shared__ char dynsm[];
__global__ void __launch_bounds__(512, 2) gemm_attn_kernel(const __half* __restrict__ A,
                                                           const __half* __restrict__ B,
                                                           uint4* __restrict__ C,
                                                           const float* __restrict__ att_src,
                                                           const float* __restrict__ att_dst,
                                                           float* __restrict__ asrc,
                                                           float* __restrict__ adst,
                                                           int K) {
    __half* Bs = (__half*)dynsm;                           // [K][264]
    char* scratch = dynsm + (size_t)K * 264 * 2;
    __half* As = (__half*)scratch;                         // [64][K+8]
    float*  Cs = (float*)scratch;                          // [64][132]
    int tid = threadIdx.x;
    int warp = tid >> 5;
    int lda = K + 8;

    int nB = K * 32;
    for (int i = tid; i < nB; i += 512) {
        int r = i >> 5, c = i & 31;
        uint4 v = ((const uint4*)(B + (size_t)r * 256))[c];
        *(uint4*)(Bs + r * 264 + c * 8) = v;
    }

    int wr = warp >> 2;
    int wc = warp & 3;
    int kv = K >> 3;
    int nA = 64 * kv;

    for (int t = blockIdx.x; t < NTILES; t += GEMMG) {
        int row0 = t * 64;
        __syncthreads();
        for (int i = tid; i < nA; i += 512) {
            int r = i / kv, c = i - r * kv;
            uint4 v = ((const uint4*)(A + (size_t)(row0 + r) * K))[c];
            *(uint4*)(As + r * lda + c * 8) = v;
        }
        __syncthreads();

        wmma::fragment<wmma::accumulator, 16, 16, 16, float> cf[4];
        #pragma unroll
        for (int n = 0; n < 4; n++) wmma::fill_fragment(cf[n], 0.f);
        for (int ks = 0; ks < K; ks += 16) {
            wmma::fragment<wmma::matrix_a, 16, 16, 16, __half, wmma::row_major> af;
            wmma::load_matrix_sync(af, As + (wr * 16) * lda + ks, lda);
            #pragma unroll
            for (int n = 0; n < 4; n++) {
                wmma::fragment<wmma::matrix_b, 16, 16, 16, __half, wmma::row_major> bf;
                wmma::load_matrix_sync(bf, Bs + ks * 264 + wc * 64 + n * 16, 264);
                wmma::mma_sync(cf[n], af, bf, cf[n]);
            }
        }
        __syncthreads();

        int er = tid >> 3;
        int cs8 = tid & 7;
        #pragma unroll
        for (int wv = 0; wv < 2; wv++) {
            if (wv) __syncthreads();
            if ((wc >> 1) == wv) {
                #pragma unroll
                for (int n = 0; n < 4; n++)
                    wmma::store_matrix_sync(Cs + (wr * 16) * 132 + (wc & 1) * 64 + n * 16,
                                            cf[n], 132, wmma::mem_row_major);
            }
            __syncthreads();
            int gcol = wv * 128 + cs8 * 16;
            int head = gcol >> 6;
            int hoff = gcol & 63;
            float4 v4[4];
            #pragma unroll
            for (int q = 0; q < 4; q++)
                v4[q] = *(float4*)(Cs + er * 132 + cs8 * 16 + q * 4);
            const float* vv = (const float*)v4;
            float s = 0.f, d = 0.f;
            __half h16[16];
            #pragma unroll
            for (int c = 0; c < 16; c++) {
                float v = vv[c];
                s += v * __ldg(att_src + head * 64 + hoff + c);
                d += v * __ldg(att_dst + head * 64 + hoff + c);
                h16[c] = __float2half(v);
            }
            uint4* dst = C + (size_t)(row0 + er) * 32 + (gcol >> 3);
            uint4* srcp = (uint4*)h16;
            dst[0] = srcp[0];
            dst[1] = srcp[1];
            s += __shfl_xor_sync(0xFFFFFFFFu, s, 1);
            d += __shfl_xor_sync(0xFFFFFFFFu, d, 1);
            s += __shfl_xor_sync(0xFFFFFFFFu, s, 2);
            d += __shfl_xor_sync(0xFFFFFFFFu, d, 2);
            if ((tid & 3) == 0) {
                asrc[(row0 + er) * 4 + head] = s;
                adst[(row0 + er) * 4 + head] = d;
            }
        }
    }
}

// ---------------- GAT aggregation ----------------
__device__ __forceinline__ void fma_half8(float* a, uint4 v, float w) {
    __half2* p = (__half2*)&v;
    #pragma unroll
    for (int q = 0; q < 4; q++) {
        float2 f = __half22float2(p[q]);
        a[2 * q]     += w * f.x;
        a[2 * q + 1] += w * f.y;
    }
}

__device__ __forceinline__ float lrelu(float e) { return (e > 0.f) ? e : NEG_SLOPE * e; }

__global__ void __launch_bounds__(256) aggregate_kernel(const uint4* __restrict__ hh,
                                                        const float* __restrict__ asrc,
                                                        const float* __restrict__ adst,
                                                        const float* __restrict__ bias,
                                                        float* __restrict__ out,
                                                        uint4* __restrict__ out16,
                                                        int N) {
    __shared__ int   ss[8][32];
    __shared__ float swt[8][4][32];
    int gw = (blockIdx.x * blockDim.x + threadIdx.x) >> 5;
    if (gw >= N) return;
    int wslot = (threadIdx.x >> 5);
    int lane = threadIdx.x & 31;
    int start = g_row[gw], end = g_row[gw + 1];
    int deg = end - start;
    float4 ad = *(const float4*)(adst + 4 * gw);
    int head = lane >> 3;

    float acc0[8], acc1[8];
    #pragma unroll
    for (int k = 0; k < 8; k++) { acc0[k] = 0.f; acc1[k] = 0.f; }
    float den = 0.f;

    if (deg <= 32) {
        int myj = start + lane;
        int mys = 0;
        float e0 = -1e30f, e1 = -1e30f, e2 = -1e30f, e3 = -1e30f;
        if (myj < end) {
            mys = g_col[myj];
            float4 q = *(const float4*)(asrc + 4 * mys);
            e0 = lrelu(q.x + ad.x); e1 = lrelu(q.y + ad.y);
            e2 = lrelu(q.z + ad.z); e3 = lrelu(q.w + ad.w);
        }
        float m0 = e0, m1 = e1, m2 = e2, m3 = e3;
        #pragma unroll
        for (int o = 16; o; o >>= 1) {
            m0 = fmaxf(m0, __shfl_xor_sync(0xFFFFFFFFu, m0, o));
            m1 = fmaxf(m1, __shfl_xor_sync(0xFFFFFFFFu, m1, o));
            m2 = fmaxf(m2, __shfl_xor_sync(0xFFFFFFFFu, m2, o));
            m3 = fmaxf(m3, __shfl_xor_sync(0xFFFFFFFFu, m3, o));
        }
        ss[wslot][lane] = mys;
        swt[wslot][0][lane] = (myj < end) ? expf(e0 - m0) : 0.f;
        swt[wslot][1][lane] = (myj < end) ? expf(e1 - m1) : 0.f;
        swt[wslot][2][lane] = (myj < end) ? expf(e2 - m2) : 0.f;
        swt[wslot][3][lane] = (myj < end) ? expf(e3 - m3) : 0.f;
        __syncwarp();
        int j = 0;
        for (; j + 4 <= deg; j += 4) {
            int s0 = ss[wslot][j], s1 = ss[wslot][j + 1];
            int s2 = ss[wslot][j + 2], s3 = ss[wslot][j + 3];
            float w0 = swt[wslot][head][j],     w1 = swt[wslot][head][j + 1];
            float w2 = swt[wslot][head][j + 2], w3 = swt[wslot][head][j + 3];
            uint4 v0 = hh[(size_t)s0 * 32 + lane];
            uint4 v1 = hh[(size_t)s1 * 32 + lane];
            uint4 v2 = hh[(size_t)s2 * 32 + lane];
            uint4 v3 = hh[(size_t)s3 * 32 + lane];
            den += (w0 + w1) + (w2 + w3);
            fma_half8(acc0, v0, w0);
            fma_half8(acc1, v1, w1);
            fma_half8(acc0, v2, w2);
            fma_half8(acc1, v3, w3);
        }
        for (; j < deg; j++) {
            int s0 = ss[wslot][j];
            float w0 = swt[wslot][head][j];
            uint4 v0 = hh[(size_t)s0 * 32 + lane];
            den += w0;
            fma_half8(acc0, v0, w0);
        }
        __syncwarp();
    } else {
        float m0 = -1e30f, m1 = -1e30f, m2 = -1e30f, m3 = -1e30f;
        for (int j = start + lane; j < end; j += 32) {
            int s = g_col[j];
            float4 q = *(const float4*)(asrc + 4 * s);
            m0 = fmaxf(m0, lrelu(q.x + ad.x));
            m1 = fmaxf(m1, lrelu(q.y + ad.y));
            m2 = fmaxf(m2, lrelu(q.z + ad.z));
            m3 = fmaxf(m3, lrelu(q.w + ad.w));
        }
        #pragma unroll
        for (int o = 16; o; o >>= 1) {
            m0 = fmaxf(m0, __shfl_xor_sync(0xFFFFFFFFu, m0, o));
            m1 = fmaxf(m1, __shfl_xor_sync(0xFFFFFFFFu, m1, o));
            m2 = fmaxf(m2, __shfl_xor_sync(0xFFFFFFFFu, m2, o));
            m3 = fmaxf(m3, __shfl_xor_sync(0xFFFFFFFFu, m3, o));
        }
        for (int base = start; base < end; base += 32) {
            int nn = min(32, end - base);
            int myj = base + lane;
            int mys = 0;
            float w0v = 0.f, w1v = 0.f, w2v = 0.f, w3v = 0.f;
            if (myj < end) {
                mys = g_col[myj];
                float4 q = *(const float4*)(asrc + 4 * mys);
                w0v = expf(lrelu(q.x + ad.x) - m0);
                w1v = expf(lrelu(q.y + ad.y) - m1);
                w2v = expf(lrelu(q.z + ad.z) - m2);
                w3v = expf(lrelu(q.w + ad.w) - m3);
            }
            ss[wslot][lane] = mys;
            swt[wslot][0][lane] = w0v;
            swt[wslot][1][lane] = w1v;
            swt[wslot][2][lane] = w2v;
            swt[wslot][3][lane] = w3v;
            __syncwarp();
            int j = 0;
            for (; j + 4 <= nn; j += 4) {
                int s0 = ss[wslot][j], s1 = ss[wslot][j + 1];
                int s2 = ss[wslot][j + 2], s3 = ss[wslot][j + 3];
                float w0 = swt[wslot][head][j],     w1 = swt[wslot][head][j + 1];
                float w2 = swt[wslot][head][j + 2], w3 = swt[wslot][head][j + 3];
                uint4 v0 = hh[(size_t)s0 * 32 + lane];
                uint4 v1 = hh[(size_t)s1 * 32 + lane];
                uint4 v2 = hh[(size_t)s2 * 32 + lane];
                uint4 v3 = hh[(size_t)s3 * 32 + lane];
                den += (w0 + w1) + (w2 + w3);
                fma_half8(acc0, v0, w0);
                fma_half8(acc1, v1, w1);
                fma_half8(acc0, v2, w2);
                fma_half8(acc1, v3, w3);
            }
            for (; j < nn; j++) {
                int s0 = ss[wslot][j];
                float w0 = swt[wslot][head][j];
                uint4 v0 = hh[(size_t)s0 * 32 + lane];
                den += w0;
                fma_half8(acc0, v0, w0);
            }
            __syncwarp();
        }
    }

    float inv = 1.f / (den + 1e-16f);
    float r[8];
    #pragma unroll
    for (int k = 0; k < 8; k++) r[k] = (acc0[k] + acc1[k]) * inv;
    #pragma unroll
    for (int k = 0; k < 8; ++k) {
        r[k] += __shfl_xor_sync(0xFFFFFFFFu, r[k], 8);
        r[k] += __shfl_xor_sync(0xFFFFFFFFu, r[k], 16);
    }
    if (lane < 8) {
        float o_[8];
        __half h8[8];
        #pragma unroll
        for (int k = 0; k < 8; ++k) {
            float v = 0.25f * r[k] + bias[lane * 8 + k];
            float sg = 1.f / (1.f + expf(-v));
            o_[k] = sg;
            h8[k] = __float2half(sg);
        }
        float4* op = (float4*)(out + (size_t)gw * 64 + lane * 8);
        op[0] = make_float4(o_[0], o_[1], o_[2], o_[3]);
        op[1] = make_float4(o_[4], o_[5], o_[6], o_[7]);
        out16[(size_t)gw * 8 + lane] = *(uint4*)h8;
    }
}

// ---------------- gate via wmma ----------------
__global__ void __launch_bounds__(128) gate_wmma_kernel(const __half* __restrict__ A,
                                                        const __half* __restrict__ B,
                                                        const float* __restrict__ gb1,
                                                        const float* __restrict__ gamma,
                                                        const float* __restrict__ beta,
                                                        const float* __restrict__ gw2,
                                                        const float* __restrict__ gb2,
                                                        float* __restrict__ gout, int N) {
    __shared__ float Cs[64 * 68];
    int tid = threadIdx.x;
    int warp = tid >> 5;
    int by = blockIdx.x;
    int row0 = by * 64 + warp * 16;

    wmma::fragment<wmma::accumulator, 16, 16, 16, float> cf[4];
    #pragma unroll
    for (int n = 0; n < 4; n++) wmma::fill_fragment(cf[n], 0.f);
    for (int k0 = 0; k0 < 64; k0 += 16) {
        wmma::fragment<wmma::matrix_a, 16, 16, 16, __half, wmma::row_major> af;
        wmma::load_matrix_sync(af, A + (size_t)row0 * 64 + k0, 64);
        #pragma unroll
        for (int n = 0; n < 4; n++) {
            wmma::fragment<wmma::matrix_b, 16, 16, 16, __half, wmma::row_major> bf;
            wmma::load_matrix_sync(bf, B + (size_t)k0 * 64 + n * 16, 64);
            wmma::mma_sync(cf[n], af, bf, cf[n]);
        }
    }
    #pragma unroll
    for (int n = 0; n < 4; n++)
        wmma::store_matrix_sync(Cs + warp * 16 * 68 + n * 16, cf[n], 68, wmma::mem_row_major);
    __syncthreads();

    int r = tid >> 1;
    int ch = (tid & 1) * 32;
    int row = by * 64 + r;
    float kinv = rsqrtf(1.0f + 1e-5f);
    float s = 0.f;
    #pragma unroll
    for (int c = 0; c < 32; c++) {
        float t = (Cs[r * 68 + ch + c] + __ldg(gb1 + ch + c)) * kinv * __ldg(gamma + ch + c)
                  + __ldg(beta + ch + c);
        t = fmaxf(t, 0.f);
        s += t * __ldg(gw2 + ch + c);
    }
    s += __shfl_xor_sync(0xFFFFFFFFu, s, 1);
    if ((tid & 1) == 0 && row < N) gout[row] = s + gb2[0];
}

// ---------------- pooling + final, fused (graph bounds via binary search) ----------------
__global__ void __launch_bounds__(256) pool_kernel(const float* __restrict__ out2,
                                                   const float* __restrict__ lw,
                                                   const float* __restrict__ lb,
                                                   float* __restrict__ result, int N) {
    int b = blockIdx.x;
    __shared__ int sbound[2];
    __shared__ float smax[256];
    __shared__ float sacc[256];
    __shared__ float sden[4];
    int tid = threadIdx.x;
    if (tid < 2) {
        int val = b + tid;           // lower_bound(val)
        int lo = 0, hi = N;
        while (lo < hi) {
            int mid = (lo + hi) >> 1;
            if (g_batch[mid] < val) lo = mid + 1; else hi = mid;
        }
        sbound[tid] = lo;
    }
    __syncthreads();
    int start = sbound[0], end = sbound[1];

    float m = -1e30f;
    for (int v = start + tid; v < end; v += 256) m = fmaxf(m, g_gate[v]);
    smax[tid] = m;
    __syncthreads();
    for (int s = 128; s; s >>= 1) {
        if (tid < s) smax[tid] = fmaxf(smax[tid], smax[tid + s]);
        __syncthreads();
    }
    float mx = smax[0];
    __syncthreads();
    int c = tid & 63;
    int sub = tid >> 6;
    float acc = 0.f, dacc = 0.f;
    for (int v = start + sub; v < end; v += 4) {
        float w = expf(g_gate[v] - mx);
        acc += w * out2[(size_t)v * 64 + c];
        if (c == 0) dacc += w;
    }
    sacc[tid] = acc;
    if (c == 0) sden[sub] = dacc;
    __syncthreads();
    if (sub == 0) {
        float p = sacc[c] + sacc[64 + c] + sacc[128 + c] + sacc[192 + c];
        sacc[c] = p * __ldg(lw + c);
    }
    __syncthreads();
    if (tid < 32) {
        float t = sacc[tid] + sacc[tid + 32];
        #pragma unroll
        for (int o = 16; o; o >>= 1) t += __shfl_xor_sync(0xFFFFFFFFu, t, o);
        if (tid == 0) {
            float dt = sden[0] + sden[1] + sden[2] + sden[3];
            float s = t / (dt + 1e-16f) + lb[0];
            result[b] = 1.f / (1.f + expf(-s));
        }
    }
}

// ---------------- launch ----------------
extern "C" void kernel_launch(void* const* d_in, const int* in_sizes, int n_in,
                              void* d_out, int out_size) {
    const float* x  = (const float*)d_in[0];
    const void*  ei = d_in[1];
    const void*  bt = d_in[2];
    int o = (in_sizes[3] == 1) ? 1 : 0;
    const float* W1  = (const float*)d_in[3 + o];
    const float* as1 = (const float*)d_in[4 + o];
    const float* ad1 = (const float*)d_in[5 + o];
    const float* b1  = (const float*)d_in[6 + o];
    const float* W2  = (const float*)d_in[7 + o];
    const float* as2 = (const float*)d_in[8 + o];
    const float* ad2 = (const float*)d_in[9 + o];
    const float* b2  = (const float*)d_in[10 + o];
    const float* gw1 = (const float*)d_in[11 + o];
    const float* gb1 = (const float*)d_in[12 + o];
    const float* gam = (const float*)d_in[13 + o];
    const float* bet = (const float*)d_in[14 + o];
    const float* gw2 = (const float*)d_in[15 + o];
    const float* gb2 = (const float*)d_in[16 + o];
    const float* lw  = (const float*)d_in[17 + o];
    const float* lb  = (const float*)d_in[18 + o];

    int N = in_sizes[0] / 128;
    int E = in_sizes[1] / 2;

    __half *x16b, *w1hb, *w2hb, *gw1hb, *o16b;
    uint4* hhbuf;
    float *asrcb, *adstb, *out1b, *out2b, *gateb;
    cudaGetSymbolAddress((void**)&x16b,  g_x16);
    cudaGetSymbolAddress((void**)&w1hb,  g_w1h);
    cudaGetSymbolAddress((void**)&w2hb,  g_w2h);
    cudaGetSymbolAddress((void**)&gw1hb, g_gw1h);
    cudaGetSymbolAddress((void**)&o16b,  g_o16);
    cudaGetSymbolAddress((void**)&hhbuf, g_hh);
    cudaGetSymbolAddress((void**)&asrcb, g_asrc);
    cudaGetSymbolAddress((void**)&adstb, g_adst);
    cudaGetSymbolAddress((void**)&out1b, g_out1);
    cudaGetSymbolAddress((void**)&out2b, g_out2);
    cudaGetSymbolAddress((void**)&gateb, g_gate);

    int smem1 = 128 * 264 * 2 + 64 * 132 * 4;   // 101376 (K=128)
    int smem2 = 64 * 264 * 2 + 64 * 132 * 4;    //  67584 (K=64)
    static int attr_set = 0;
    if (!attr_set) {
        cudaFuncSetAttribute(gemm_attn_kernel,
                             cudaFuncAttributeMaxDynamicSharedMemorySize, smem1);
        attr_set = 1;
    }

    int x8 = N * 128 / 8;
    int prepT = (x8 > 128 * 256) ? x8 : 128 * 256;

    // 0: prep
    prep_kernel<<<(prepT + 255) / 256, 256>>>((const long long*)ei, x, W1, W2, gw1, N, x8);
    // 1: convert (degree from ei directly + batch)
    convert_kernel<<<(E + N + 255) / 256, 256>>>(ei, bt, E, N);
    // 2: fused CSR (scatter reads ei directly)
    csr_kernel<<<CSRB, 256>>>(ei, N, E);
    // 3: layer-1 GEMM
    gemm_attn_kernel<<<GEMMG, 512, smem1>>>(x16b, w1hb, hhbuf, as1, ad1, asrcb, adstb, 128);
    // 4: layer-1 aggregate
    int wblocks = (N + 7) / 8;
    aggregate_kernel<<<wblocks, 256>>>(hhbuf, asrcb, adstb, b1, out1b, (uint4*)o16b, N);
    // 5-6: layer 2
    gemm_attn_kernel<<<GEMMG, 512, smem2>>>(o16b, w2hb, hhbuf, as2, ad2, asrcb, adstb, 64);
    aggregate_kernel<<<wblocks, 256>>>(hhbuf, asrcb, adstb, b2, out2b, (uint4*)o16b, N);
    // 7-8: gate, pool+final (graph bounds computed in-kernel)
    gate_wmma_kernel<<<NPAD / 64, 128>>>(o16b, gw1hb, gb1, gam, bet, gw2, gb2, gateb, N);
    pool_kernel<<<GNUM, 256>>>(out2b, lw, lb, (float*)d_out, N);
}

// round 15
// speedup vs baseline: 1.6021x; 1.0156x over previous
#include <cuda_runtime.h>
#include <cuda_fp16.h>
#include <mma.h>
#include <math.h>
#include <stdint.h>

using namespace nvcuda;

#define NNODES 50000
#define NPAD   50048
#define NTILES (NPAD / 64)      // 782 row tiles
#define GEMMG  296              // persistent grid: 2 blocks/SM, all resident
#define CSRNB  98               // blocks 0..97 build CSR inside layer-1 GEMM launch
#define NEDGES 800000
#define TOTE   (NEDGES + NNODES)
#define GNUM   64
#define NEG_SLOPE 0.2f

// ---------------- static device scratch ----------------
static __device__ int      g_is64;
static __device__ unsigned g_barcnt;
static __device__ unsigned g_bargen;
static __device__ int    g_tilec[2];
static __device__ int    g_batch[NNODES];
static __device__ int    g_deg[NNODES];
static __device__ int    g_row[NNODES + 1];
static __device__ int    g_cur[NNODES];
static __device__ int    g_col[TOTE];
static __device__ int    g_bsum[CSRNB];
static __device__ __half g_x16[(size_t)NPAD * 128];
static __device__ __half g_w1h[128 * 256];
static __device__ __half g_w2h[64 * 256];
static __device__ __half g_gw1h[64 * 64];
static __device__ __half g_o16[(size_t)NPAD * 64];
static __device__ uint4  g_hh[(size_t)NPAD * 32];
static __device__ float  g_asrc[NPAD * 4];
static __device__ float  g_adst[NPAD * 4];
static __device__ float  g_out1[(size_t)NNODES * 64];
static __device__ float  g_out2[(size_t)NNODES * 64];
static __device__ float  g_gate[NNODES];

__device__ __forceinline__ int ld_idx(const void* ei, int is64, int idx) {
    return is64 ? (int)((const long long*)ei)[idx] : ((const int*)ei)[idx];
}

// ---------------- prep: zero deg + tile counters, detect dtype, fp16 weights, fp16 x ----------------
__global__ void prep_kernel(const long long* __restrict__ ei,
                            const float* __restrict__ x,
                            const float* __restrict__ W1,
                            const float* __restrict__ W2,
                            const float* __restrict__ gw1,
                            int N, int total8) {
    int i = blockIdx.x * blockDim.x + threadIdx.x;
    if (i < N) g_deg[i] = 0;
    if (i < 2) g_tilec[i] = 0;
    if (i < 128 * 256) g_w1h[i] = __float2half(W1[i]);
    if (i < 64 * 256)  g_w2h[i] = __float2half(W2[i]);
    if (i < 64 * 64)   g_gw1h[i] = __float2half(gw1[i]);
    if (i < total8) {
        float4 a = ((const float4*)x)[2 * i];
        float4 b = ((const float4*)x)[2 * i + 1];
        __half h8[8] = {__float2half(a.x), __float2half(a.y), __float2half(a.z), __float2half(a.w),
                        __float2half(b.x), __float2half(b.y), __float2half(b.z), __float2half(b.w)};
        ((uint4*)g_x16)[i] = *(uint4*)h8;
    }
    if (blockIdx.x == 0 && threadIdx.x < 32) {
        long long v = ei[threadIdx.x];
        int ok = (v >= 0 && v < (long long)N);
        unsigned all = __all_sync(0xFFFFFFFFu, ok);
        if (threadIdx.x == 0) g_is64 = all ? 1 : 0;
    }
}

// ---------------- grid barrier (among the CSRNB CSR blocks only; all resident) ----------------
__device__ __forceinline__ void grid_barrier(int nblocks) {
    __threadfence();
    __syncthreads();
    if (threadIdx.x == 0) {
        unsigned gen = atomicAdd(&g_bargen, 0u);
        unsigned prev = atomicAdd(&g_barcnt, 1u);
        if (prev == (unsigned)(nblocks - 1)) {
            atomicExch(&g_barcnt, 0u);
            __threadfence();
            atomicAdd(&g_bargen, 1u);
        } else {
            while (atomicAdd(&g_bargen, 0u) == gen) { }
        }
    }
    __syncthreads();
}

// ---------------- persistent GEMM + embedded CSR build (layer 1) ----------------
// All blocks stage B once. If do_csr, blocks 0..CSRNB-1 first build the CSR
// (degree+batch -> scan -> offsets -> scatter with subset grid barriers), then
// join the GEMM tile work-queue that the other blocks have been draining.
extern __shared__ char dynsm[];
__global__ void __launch_bounds__(512, 2) gemm_attn_kernel(const __half* __restrict__ A,
                                                           const __half* __restrict__ B,
                                                           uint4* __restrict__ C,
                                                           const float* __restrict__ att_src,
                                                           const float* __restrict__ att_dst,
                                                           float* __restrict__ asrc,
                                                           float* __restrict__ adst,
                                                           int K, int do_csr, int which,
                                                           const void* __restrict__ ei,
                                                           const void* __restrict__ bt,
                                                           int N, int E) {
    __half* Bs = (__half*)dynsm;                           // [K][264]
    char* scratch = dynsm + (size_t)K * 264 * 2;
    __half* As = (__half*)scratch;                         // [64][K+8]
    float*  Cs = (float*)scratch;                          // [64][132]
    __shared__ int ws[16];
    __shared__ int red[16];
    __shared__ int sm_t;
    int tid = threadIdx.x;
    int warp = tid >> 5;
    int lane = tid & 31;
    int lda = K + 8;

    // stage full B once (every block)
    int nB = K * 32;
    for (int i = tid; i < nB; i += 512) {
        int r = i >> 5, c = i & 31;
        uint4 v = ((const uint4*)(B + (size_t)r * 256))[c];
        *(uint4*)(Bs + r * 264 + c * 8) = v;
    }

    if (do_csr && blockIdx.x < CSRNB) {
        int bid = blockIdx.x;
        int is64 = g_is64;
        // phase 0: degree count + batch conversion
        for (int idx = bid * 512 + tid; idx < E + N; idx += CSRNB * 512) {
            if (idx < E) {
                atomicAdd(&g_deg[ld_idx(ei, is64, E + idx)], 1);
            } else {
                int j = idx - E;
                g_batch[j] = is64 ? (int)((const long long*)bt)[j] : ((const int*)bt)[j];
            }
        }
        grid_barrier(CSRNB);
        // phase 1: block-local exclusive scan of deg+1 (512 nodes per block)
        int i = bid * 512 + tid;
        int x = (i < N) ? g_deg[i] + 1 : 0;
        int v = x;
        #pragma unroll
        for (int o = 1; o < 32; o <<= 1) {
            int u = __shfl_up_sync(0xFFFFFFFFu, v, o);
            if (lane >= o) v += u;
        }
        if (lane == 31) ws[warp] = v;
        __syncthreads();
        if (warp == 0) {
            int w = (lane < 16) ? ws[lane] : 0;
            #pragma unroll
            for (int o = 1; o < 16; o <<= 1) {
                int u = __shfl_up_sync(0xFFFFFFFFu, w, o);
                if (lane >= o) w += u;
            }
            if (lane < 16) ws[lane] = w;
        }
        __syncthreads();
        int incl = v + (warp ? ws[warp - 1] : 0);
        if (tid == 511) g_bsum[bid] = incl;
        grid_barrier(CSRNB);
        // phase 2: per-block offset = sum of bsum[0..bid)
        int part = (tid < bid) ? g_bsum[tid] : 0;   // bid < CSRNB <= 512
        #pragma unroll
        for (int o = 16; o; o >>= 1) part += __shfl_xor_sync(0xFFFFFFFFu, part, o);
        if (lane == 0) red[warp] = part;
        __syncthreads();
        int off;
        {
            int t = (lane < 16) ? red[lane] : 0;
            #pragma unroll
            for (int o = 8; o; o >>= 1) t += __shfl_xor_sync(0xFFFFFFFFu, t, o);
            off = __shfl_sync(0xFFFFFFFFu, t, 0);
        }
        int r = incl - x + off;
        if (i < N) { g_row[i] = r; g_cur[i] = r; }
        if (i == 0) g_row[N] = E + N;
        grid_barrier(CSRNB);
        // phase 3: scatter edges + self-loops
        for (int e = bid * 512 + tid; e < E + N; e += CSRNB * 512) {
            int s, d;
            if (e < E) { s = ld_idx(ei, is64, e); d = ld_idx(ei, is64, E + e); }
            else       { s = d = e - E; }
            int pos = atomicAdd(&g_cur[d], 1);
            g_col[pos] = s;
        }
    }

    // GEMM tile work-queue
    int wr = warp >> 2;
    int wc = warp & 3;
    int kv = K >> 3;
    int nA = 64 * kv;
    for (;;) {
        if (tid == 0) sm_t = atomicAdd(&g_tilec[which], 1);
        __syncthreads();                 // broadcast tile + protect scratch reuse
        int t = sm_t;
        if (t >= NTILES) break;
        int row0 = t * 64;

        for (int i = tid; i < nA; i += 512) {
            int r = i / kv, c = i - r * kv;
            uint4 v = ((const uint4*)(A + (size_t)(row0 + r) * K))[c];
            *(uint4*)(As + r * lda + c * 8) = v;
        }
        __syncthreads();

        wmma::fragment<wmma::accumulator, 16, 16, 16, float> cf[4];
        #pragma unroll
        for (int n = 0; n < 4; n++) wmma::fill_fragment(cf[n], 0.f);
        for (int ks = 0; ks < K; ks += 16) {
            wmma::fragment<wmma::matrix_a, 16, 16, 16, __half, wmma::row_major> af;
            wmma::load_matrix_sync(af, As + (wr * 16) * lda + ks, lda);
            #pragma unroll
            for (int n = 0; n < 4; n++) {
                wmma::fragment<wmma::matrix_b, 16, 16, 16, __half, wmma::row_major> bf;
                wmma::load_matrix_sync(bf, Bs + ks * 264 + wc * 64 + n * 16, 264);
                wmma::mma_sync(cf[n], af, bf, cf[n]);
            }
        }
        __syncthreads();

        int er = tid >> 3;
        int cs8 = tid & 7;
        #pragma unroll
        for (int wv = 0; wv < 2; wv++) {
            if (wv) __syncthreads();
            if ((wc >> 1) == wv) {
                #pragma unroll
                for (int n = 0; n < 4; n++)
                    wmma::store_matrix_sync(Cs + (wr * 16) * 132 + (wc & 1) * 64 + n * 16,
                                            cf[n], 132, wmma::mem_row_major);
            }
            __syncthreads();
            int gcol = wv * 128 + cs8 * 16;
            int head = gcol >> 6;
            int hoff = gcol & 63;
            float4 v4[4];
            #pragma unroll
            for (int q = 0; q < 4; q++)
                v4[q] = *(float4*)(Cs + er * 132 + cs8 * 16 + q * 4);
            const float* vv = (const float*)v4;
            float s = 0.f, d = 0.f;
            __half h16[16];
            #pragma unroll
            for (int c = 0; c < 16; c++) {
                float v = vv[c];
                s += v * __ldg(att_src + head * 64 + hoff + c);
                d += v * __ldg(att_dst + head * 64 + hoff + c);
                h16[c] = __float2half(v);
            }
            uint4* dst = C + (size_t)(row0 + er) * 32 + (gcol >> 3);
            uint4* srcp = (uint4*)h16;
            dst[0] = srcp[0];
            dst[1] = srcp[1];
            s += __shfl_xor_sync(0xFFFFFFFFu, s, 1);
            d += __shfl_xor_sync(0xFFFFFFFFu, d, 1);
            s += __shfl_xor_sync(0xFFFFFFFFu, s, 2);
            d += __shfl_xor_sync(0xFFFFFFFFu, d, 2);
            if ((tid & 3) == 0) {
                asrc[(row0 + er) * 4 + head] = s;
                adst[(row0 + er) * 4 + head] = d;
            }
        }
    }
}

// ---------------- GAT aggregation ----------------
__device__ __forceinline__ void fma_half8(float* a, uint4 v, float w) {
    __half2* p = (__half2*)&v;
    #pragma unroll
    for (int q = 0; q < 4; q++) {
        float2 f = __half22float2(p[q]);
        a[2 * q]     += w * f.x;
        a[2 * q + 1] += w * f.y;
    }
}

__device__ __forceinline__ float lrelu(float e) { return (e > 0.f) ? e : NEG_SLOPE * e; }

__global__ void __launch_bounds__(256) aggregate_kernel(const uint4* __restrict__ hh,
                                                        const float* __restrict__ asrc,
                                                        const float* __restrict__ adst,
                                                        const float* __restrict__ bias,
                                                        float* __restrict__ out,
                                                        uint4* __restrict__ out16,
                                                        int N) {
    __shared__ int   ss[8][32];
    __shared__ float swt[8][4][32];
    int gw = (blockIdx.x * blockDim.x + threadIdx.x) >> 5;
    if (gw >= N) return;
    int wslot = (threadIdx.x >> 5);
    int lane = threadIdx.x & 31;
    int start = g_row[gw], end = g_row[gw + 1];
    int deg = end - start;
    float4 ad = *(const float4*)(adst + 4 * gw);
    int head = lane >> 3;

    float acc0[8], acc1[8];
    #pragma unroll
    for (int k = 0; k < 8; k++) { acc0[k] = 0.f; acc1[k] = 0.f; }
    float den = 0.f;

    if (deg <= 32) {
        int myj = start + lane;
        int mys = 0;
        float e0 = -1e30f, e1 = -1e30f, e2 = -1e30f, e3 = -1e30f;
        if (myj < end) {
            mys = g_col[myj];
            float4 q = *(const float4*)(asrc + 4 * mys);
            e0 = lrelu(q.x + ad.x); e1 = lrelu(q.y + ad.y);
            e2 = lrelu(q.z + ad.z); e3 = lrelu(q.w + ad.w);
        }
        float m0 = e0, m1 = e1, m2 = e2, m3 = e3;
        #pragma unroll
        for (int o = 16; o; o >>= 1) {
            m0 = fmaxf(m0, __shfl_xor_sync(0xFFFFFFFFu, m0, o));
            m1 = fmaxf(m1, __shfl_xor_sync(0xFFFFFFFFu, m1, o));
            m2 = fmaxf(m2, __shfl_xor_sync(0xFFFFFFFFu, m2, o));
            m3 = fmaxf(m3, __shfl_xor_sync(0xFFFFFFFFu, m3, o));
        }
        ss[wslot][lane] = mys;
        swt[wslot][0][lane] = (myj < end) ? expf(e0 - m0) : 0.f;
        swt[wslot][1][lane] = (myj < end) ? expf(e1 - m1) : 0.f;
        swt[wslot][2][lane] = (myj < end) ? expf(e2 - m2) : 0.f;
        swt[wslot][3][lane] = (myj < end) ? expf(e3 - m3) : 0.f;
        __syncwarp();
        int j = 0;
        for (; j + 4 <= deg; j += 4) {
            int s0 = ss[wslot][j], s1 = ss[wslot][j + 1];
            int s2 = ss[wslot][j + 2], s3 = ss[wslot][j + 3];
            float w0 = swt[wslot][head][j],     w1 = swt[wslot][head][j + 1];
            float w2 = swt[wslot][head][j + 2], w3 = swt[wslot][head][j + 3];
            uint4 v0 = hh[(size_t)s0 * 32 + lane];
            uint4 v1 = hh[(size_t)s1 * 32 + lane];
            uint4 v2 = hh[(size_t)s2 * 32 + lane];
            uint4 v3 = hh[(size_t)s3 * 32 + lane];
            den += (w0 + w1) + (w2 + w3);
            fma_half8(acc0, v0, w0);
            fma_half8(acc1, v1, w1);
            fma_half8(acc0, v2, w2);
            fma_half8(acc1, v3, w3);
        }
        for (; j < deg; j++) {
            int s0 = ss[wslot][j];
            float w0 = swt[wslot][head][j];
            uint4 v0 = hh[(size_t)s0 * 32 + lane];
            den += w0;
            fma_half8(acc0, v0, w0);
        }
        __syncwarp();
    } else {
        float m0 = -1e30f, m1 = -1e30f, m2 = -1e30f, m3 = -1e30f;
        for (int j = start + lane; j < end; j += 32) {
            int s = g_col[j];
            float4 q = *(const float4*)(asrc + 4 * s);
            m0 = fmaxf(m0, lrelu(q.x + ad.x));
            m1 = fmaxf(m1, lrelu(q.y + ad.y));
            m2 = fmaxf(m2, lrelu(q.z + ad.z));
            m3 = fmaxf(m3, lrelu(q.w + ad.w));
        }
        #pragma unroll
        for (int o = 16; o; o >>= 1) {
            m0 = fmaxf(m0, __shfl_xor_sync(0xFFFFFFFFu, m0, o));
            m1 = fmaxf(m1, __shfl_xor_sync(0xFFFFFFFFu, m1, o));
            m2 = fmaxf(m2, __shfl_xor_sync(0xFFFFFFFFu, m2, o));
            m3 = fmaxf(m3, __shfl_xor_sync(0xFFFFFFFFu, m3, o));
        }
        for (int base = start; base < end; base += 32) {
            int nn = min(32, end - base);
            int myj = base + lane;
            int mys = 0;
            float w0v = 0.f, w1v = 0.f, w2v = 0.f, w3v = 0.f;
            if (myj < end) {
                mys = g_col[myj];
                float4 q = *(const float4*)(asrc + 4 * mys);
                w0v = expf(lrelu(q.x + ad.x) - m0);
                w1v = expf(lrelu(q.y + ad.y) - m1);
                w2v = expf(lrelu(q.z + ad.z) - m2);
                w3v = expf(lrelu(q.w + ad.w) - m3);
            }
            ss[wslot][lane] = mys;
            swt[wslot][0][lane] = w0v;
            swt[wslot][1][lane] = w1v;
            swt[wslot][2][lane] = w2v;
            swt[wslot][3][lane] = w3v;
            __syncwarp();
            int j = 0;
            for (; j + 4 <= nn; j += 4) {
                int s0 = ss[wslot][j], s1 = ss[wslot][j + 1];
                int s2 = ss[wslot][j + 2], s3 = ss[wslot][j + 3];
                float w0 = swt[wslot][head][j],     w1 = swt[wslot][head][j + 1];
                float w2 = swt[wslot][head][j + 2], w3 = swt[wslot][head][j + 3];
                uint4 v0 = hh[(size_t)s0 * 32 + lane];
                uint4 v1 = hh[(size_t)s1 * 32 + lane];
                uint4 v2 = hh[(size_t)s2 * 32 + lane];
                uint4 v3 = hh[(size_t)s3 * 32 + lane];
                den += (w0 + w1) + (w2 + w3);
                fma_half8(acc0, v0, w0);
                fma_half8(acc1, v1, w1);
                fma_half8(acc0, v2, w2);
                fma_half8(acc1, v3, w3);
            }
            for (; j < nn; j++) {
                int s0 = ss[wslot][j];
                float w0 = swt[wslot][head][j];
                uint4 v0 = hh[(size_t)s0 * 32 + lane];
                den += w0;
                fma_half8(acc0, v0, w0);
            }
            __syncwarp();
        }
    }

    float inv = 1.f / (den + 1e-16f);
    float r[8];
    #pragma unroll
    for (int k = 0; k < 8; k++) r[k] = (acc0[k] + acc1[k]) * inv;
    #pragma unroll
    for (int k = 0; k < 8; ++k) {
        r[k] += __shfl_xor_sync(0xFFFFFFFFu, r[k], 8);
        r[k] += __shfl_xor_sync(0xFFFFFFFFu, r[k], 16);
    }
    if (lane < 8) {
        float o_[8];
        __half h8[8];
        #pragma unroll
        for (int k = 0; k < 8; ++k) {
            float v = 0.25f * r[k] + bias[lane * 8 + k];
            float sg = 1.f / (1.f + expf(-v));
            o_[k] = sg;
            h8[k] = __float2half(sg);
        }
        float4* op = (float4*)(out + (size_t)gw * 64 + lane * 8);
        op[0] = make_float4(o_[0], o_[1], o_[2], o_[3]);
        op[1] = make_float4(o_[4], o_[5], o_[6], o_[7]);
        out16[(size_t)gw * 8 + lane] = *(uint4*)h8;
    }
}

// ---------------- gate via wmma ----------------
__global__ void __launch_bounds__(128) gate_wmma_kernel(const __half* __restrict__ A,
                                                        const __half* __restrict__ B,
                                                        const float* __restrict__ gb1,
                                                        const float* __restrict__ gamma,
                                                        const float* __restrict__ beta,
                                                        const float* __restrict__ gw2,
                                                        const float* __restrict__ gb2,
                                                        float* __restrict__ gout, int N) {
    __shared__ float Cs[64 * 68];
    int tid = threadIdx.x;
    int warp = tid >> 5;
    int by = blockIdx.x;
    int row0 = by * 64 + warp * 16;

    wmma::fragment<wmma::accumulator, 16, 16, 16, float> cf[4];
    #pragma unroll
    for (int n = 0; n < 4; n++) wmma::fill_fragment(cf[n], 0.f);
    for (int k0 = 0; k0 < 64; k0 += 16) {
        wmma::fragment<wmma::matrix_a, 16, 16, 16, __half, wmma::row_major> af;
        wmma::load_matrix_sync(af, A + (size_t)row0 * 64 + k0, 64);
        #pragma unroll
        for (int n = 0; n < 4; n++) {
            wmma::fragment<wmma::matrix_b, 16, 16, 16, __half, wmma::row_major> bf;
            wmma::load_matrix_sync(bf, B + (size_t)k0 * 64 + n * 16, 64);
            wmma::mma_sync(cf[n], af, bf, cf[n]);
        }
    }
    #pragma unroll
    for (int n = 0; n < 4; n++)
        wmma::store_matrix_sync(Cs + warp * 16 * 68 + n * 16, cf[n], 68, wmma::mem_row_major);
    __syncthreads();

    int r = tid >> 1;
    int ch = (tid & 1) * 32;
    int row = by * 64 + r;
    float kinv = rsqrtf(1.0f + 1e-5f);
    float s = 0.f;
    #pragma unroll
    for (int c = 0; c < 32; c++) {
        float t = (Cs[r * 68 + ch + c] + __ldg(gb1 + ch + c)) * kinv * __ldg(gamma + ch + c)
                  + __ldg(beta + ch + c);
        t = fmaxf(t, 0.f);
        s += t * __ldg(gw2 + ch + c);
    }
    s += __shfl_xor_sync(0xFFFFFFFFu, s, 1);
    if ((tid & 1) == 0 && row < N) gout[row] = s + gb2[0];
}

// ---------------- pooling + final, fused (graph bounds via binary search) ----------------
__global__ void __launch_bounds__(256) pool_kernel(const float* __restrict__ out2,
                                                   const float* __restrict__ lw,
                                                   const float* __restrict__ lb,
                                                   float* __restrict__ result, int N) {
    int b = blockIdx.x;
    __shared__ int sbound[2];
    __shared__ float smax[256];
    __shared__ float sacc[256];
    __shared__ float sden[4];
    int tid = threadIdx.x;
    if (tid < 2) {
        int val = b + tid;
        int lo = 0, hi = N;
        while (lo < hi) {
            int mid = (lo + hi) >> 1;
            if (g_batch[mid] < val) lo = mid + 1; else hi = mid;
        }
        sbound[tid] = lo;
    }
    __syncthreads();
    int start = sbound[0], end = sbound[1];

    float m = -1e30f;
    for (int v = start + tid; v < end; v += 256) m = fmaxf(m, g_gate[v]);
    smax[tid] = m;
    __syncthreads();
    for (int s = 128; s; s >>= 1) {
        if (tid < s) smax[tid] = fmaxf(smax[tid], smax[tid + s]);
        __syncthreads();
    }
    float mx = smax[0];
    __syncthreads();
    int c = tid & 63;
    int sub = tid >> 6;
    float acc = 0.f, dacc = 0.f;
    for (int v = start + sub; v < end; v += 4) {
        float w = expf(g_gate[v] - mx);
        acc += w * out2[(size_t)v * 64 + c];
        if (c == 0) dacc += w;
    }
    sacc[tid] = acc;
    if (c == 0) sden[sub] = dacc;
    __syncthreads();
    if (sub == 0) {
        float p = sacc[c] + sacc[64 + c] + sacc[128 + c] + sacc[192 + c];
        sacc[c] = p * __ldg(lw + c);
    }
    __syncthreads();
    if (tid < 32) {
        float t = sacc[tid] + sacc[tid + 32];
        #pragma unroll
        for (int o = 16; o; o >>= 1) t += __shfl_xor_sync(0xFFFFFFFFu, t, o);
        if (tid == 0) {
            float dt = sden[0] + sden[1] + sden[2] + sden[3];
            float s = t / (dt + 1e-16f) + lb[0];
            result[b] = 1.f / (1.f + expf(-s));
        }
    }
}

// ---------------- launch ----------------
extern "C" void kernel_launch(void* const* d_in, const int* in_sizes, int n_in,
                              void* d_out, int out_size) {
    const float* x  = (const float*)d_in[0];
    const void*  ei = d_in[1];
    const void*  bt = d_in[2];
    int o = (in_sizes[3] == 1) ? 1 : 0;
    const float* W1  = (const float*)d_in[3 + o];
    const float* as1 = (const float*)d_in[4 + o];
    const float* ad1 = (const float*)d_in[5 + o];
    const float* b1  = (const float*)d_in[6 + o];
    const float* W2  = (const float*)d_in[7 + o];
    const float* as2 = (const float*)d_in[8 + o];
    const float* ad2 = (const float*)d_in[9 + o];
    const float* b2  = (const float*)d_in[10 + o];
    const float* gw1 = (const float*)d_in[11 + o];
    const float* gb1 = (const float*)d_in[12 + o];
    const float* gam = (const float*)d_in[13 + o];
    const float* bet = (const float*)d_in[14 + o];
    const float* gw2 = (const float*)d_in[15 + o];
    const float* gb2 = (const float*)d_in[16 + o];
    const float* lw  = (const float*)d_in[17 + o];
    const float* lb  = (const float*)d_in[18 + o];

    int N = in_sizes[0] / 128;
    int E = in_sizes[1] / 2;

    __half *x16b, *w1hb, *w2hb, *gw1hb, *o16b;
    uint4* hhbuf;
    float *asrcb, *adstb, *out1b, *out2b, *gateb;
    cudaGetSymbolAddress((void**)&x16b,  g_x16);
    cudaGetSymbolAddress((void**)&w1hb,  g_w1h);
    cudaGetSymbolAddress((void**)&w2hb,  g_w2h);
    cudaGetSymbolAddress((void**)&gw1hb, g_gw1h);
    cudaGetSymbolAddress((void**)&o16b,  g_o16);
    cudaGetSymbolAddress((void**)&hhbuf, g_hh);
    cudaGetSymbolAddress((void**)&asrcb, g_asrc);
    cudaGetSymbolAddress((void**)&adstb, g_adst);
    cudaGetSymbolAddress((void**)&out1b, g_out1);
    cudaGetSymbolAddress((void**)&out2b, g_out2);
    cudaGetSymbolAddress((void**)&gateb, g_gate);

    int smem1 = 128 * 264 * 2 + 64 * 132 * 4;   // 101376 (K=128)
    int smem2 = 64 * 264 * 2 + 64 * 132 * 4;    //  67584 (K=64)
    static int attr_set = 0;
    if (!attr_set) {
        cudaFuncSetAttribute(gemm_attn_kernel,
                             cudaFuncAttributeMaxDynamicSharedMemorySize, smem1);
        attr_set = 1;
    }

    int x8 = N * 128 / 8;
    int prepT = (x8 > 128 * 256) ? x8 : 128 * 256;

    // 0: prep (deg zero, tile counters, dtype, fp16 weights + x)
    prep_kernel<<<(prepT + 255) / 256, 256>>>((const long long*)ei, x, W1, W2, gw1, N, x8);
    // 1: layer-1 GEMM with embedded CSR build (block-specialized, work-queued)
    gemm_attn_kernel<<<GEMMG, 512, smem1>>>(x16b, w1hb, hhbuf, as1, ad1, asrcb, adstb,
                                            128, 1, 0, ei, bt, N, E);
    // 2: layer-1 aggregate
    int wblocks = (N + 7) / 8;
    aggregate_kernel<<<wblocks, 256>>>(hhbuf, asrcb, adstb, b1, out1b, (uint4*)o16b, N);
    // 3-4: layer 2 (no CSR, second tile counter)
    gemm_attn_kernel<<<GEMMG, 512, smem2>>>(o16b, w2hb, hhbuf, as2, ad2, asrcb, adstb,
                                            64, 0, 1, ei, bt, N, E);
    aggregate_kernel<<<wblocks, 256>>>(hhbuf, asrcb, adstb, b2, out2b, (uint4*)o16b, N);
    // 5-6: gate, pool+final
    gate_wmma_kernel<<<NPAD / 64, 128>>>(o16b, gw1hb, gb1, gam, bet, gw2, gb2, gateb, N);
    pool_kernel<<<GNUM, 256>>>(out2b, lw, lb, (float*)d_out, N);
}

// round 16
// speedup vs baseline: 1.6140x; 1.0074x over previous
#include <cuda_runtime.h>
#include <cuda_fp16.h>
#include <mma.h>
#include <math.h>
#include <stdint.h>

using namespace nvcuda;

#define NNODES 50000
#define NPAD   50048
#define NTILES (NPAD / 64)      // 782 row tiles
#define GEMMG  296              // persistent grid: 2 blocks/SM, all resident
#define CSRNB  98               // blocks 0..97 build CSR inside layer-1 GEMM launch
#define NEDGES 800000
#define TOTE   (NEDGES + NNODES)
#define GNUM   64
#define NEG_SLOPE 0.2f

// ---------------- static device scratch ----------------
static __device__ int      g_is64;
static __device__ unsigned g_barcnt;
static __device__ unsigned g_bargen;
static __device__ int    g_tilec[2];
static __device__ int    g_batch[NNODES];
static __device__ int    g_deg[NNODES];
static __device__ int    g_row[NNODES + 1];
static __device__ int    g_cur[NNODES];
static __device__ int    g_col[TOTE];
static __device__ int    g_bsum[CSRNB];
static __device__ __half g_x16[(size_t)NPAD * 128];
static __device__ __half g_w1h[128 * 256];
static __device__ __half g_w2h[64 * 256];
static __device__ __half g_gw1h[64 * 64];
static __device__ __half g_o16[(size_t)NPAD * 64];
static __device__ uint4  g_hh[(size_t)NPAD * 32];
static __device__ float  g_asrc[NPAD * 4];
static __device__ float  g_adst[NPAD * 4];
static __device__ float  g_out1[(size_t)NNODES * 64];
static __device__ float  g_out2[(size_t)NNODES * 64];
static __device__ float  g_gate[NNODES];

__device__ __forceinline__ int ld_idx(const void* ei, int is64, int idx) {
    return is64 ? (int)((const long long*)ei)[idx] : ((const int*)ei)[idx];
}

// ---------------- prep ----------------
__global__ void prep_kernel(const long long* __restrict__ ei,
                            const float* __restrict__ x,
                            const float* __restrict__ W1,
                            const float* __restrict__ W2,
                            const float* __restrict__ gw1,
                            int N, int total8) {
    int i = blockIdx.x * blockDim.x + threadIdx.x;
    if (i < N) g_deg[i] = 0;
    if (i < 2) g_tilec[i] = 0;
    if (i < 128 * 256) g_w1h[i] = __float2half(W1[i]);
    if (i < 64 * 256)  g_w2h[i] = __float2half(W2[i]);
    if (i < 64 * 64)   g_gw1h[i] = __float2half(gw1[i]);
    if (i < total8) {
        float4 a = ((const float4*)x)[2 * i];
        float4 b = ((const float4*)x)[2 * i + 1];
        __half h8[8] = {__float2half(a.x), __float2half(a.y), __float2half(a.z), __float2half(a.w),
                        __float2half(b.x), __float2half(b.y), __float2half(b.z), __float2half(b.w)};
        ((uint4*)g_x16)[i] = *(uint4*)h8;
    }
    if (blockIdx.x == 0 && threadIdx.x < 32) {
        long long v = ei[threadIdx.x];
        int ok = (v >= 0 && v < (long long)N);
        unsigned all = __all_sync(0xFFFFFFFFu, ok);
        if (threadIdx.x == 0) g_is64 = all ? 1 : 0;
    }
}

// ---------------- grid barrier (CSR subset; all resident) ----------------
__device__ __forceinline__ void grid_barrier(int nblocks) {
    __threadfence();
    __syncthreads();
    if (threadIdx.x == 0) {
        unsigned gen = atomicAdd(&g_bargen, 0u);
        unsigned prev = atomicAdd(&g_barcnt, 1u);
        if (prev == (unsigned)(nblocks - 1)) {
            atomicExch(&g_barcnt, 0u);
            __threadfence();
            atomicAdd(&g_bargen, 1u);
        } else {
            while (atomicAdd(&g_bargen, 0u) == gen) { }
        }
    }
    __syncthreads();
}

// ---------------- persistent GEMM + embedded CSR build ----------------
extern __shared__ char dynsm[];
__global__ void __launch_bounds__(512, 2) gemm_attn_kernel(const __half* __restrict__ A,
                                                           const __half* __restrict__ B,
                                                           uint4* __restrict__ C,
                                                           const float* __restrict__ att_src,
                                                           const float* __restrict__ att_dst,
                                                           float* __restrict__ asrc,
                                                           float* __restrict__ adst,
                                                           int K, int do_csr, int which,
                                                           const void* __restrict__ ei,
                                                           const void* __restrict__ bt,
                                                           int N, int E) {
    __half* Bs = (__half*)dynsm;                           // [K][264]
    char* scratch = dynsm + (size_t)K * 264 * 2;
    __half* As = (__half*)scratch;                         // [64][K+8]
    float*  Cs = (float*)scratch;                          // [64][132]
    __shared__ int ws[16];
    __shared__ int red[16];
    __shared__ int sm_t;
    int tid = threadIdx.x;
    int warp = tid >> 5;
    int lane = tid & 31;
    int lda = K + 8;

    int nB = K * 32;
    for (int i = tid; i < nB; i += 512) {
        int r = i >> 5, c = i & 31;
        uint4 v = ((const uint4*)(B + (size_t)r * 256))[c];
        *(uint4*)(Bs + r * 264 + c * 8) = v;
    }

    if (do_csr && blockIdx.x < CSRNB) {
        int bid = blockIdx.x;
        int is64 = g_is64;
        for (int idx = bid * 512 + tid; idx < E + N; idx += CSRNB * 512) {
            if (idx < E) {
                atomicAdd(&g_deg[ld_idx(ei, is64, E + idx)], 1);
            } else {
                int j = idx - E;
                g_batch[j] = is64 ? (int)((const long long*)bt)[j] : ((const int*)bt)[j];
            }
        }
        grid_barrier(CSRNB);
        int i = bid * 512 + tid;
        int x = (i < N) ? g_deg[i] + 1 : 0;
        int v = x;
        #pragma unroll
        for (int o = 1; o < 32; o <<= 1) {
            int u = __shfl_up_sync(0xFFFFFFFFu, v, o);
            if (lane >= o) v += u;
        }
        if (lane == 31) ws[warp] = v;
        __syncthreads();
        if (warp == 0) {
            int w = (lane < 16) ? ws[lane] : 0;
            #pragma unroll
            for (int o = 1; o < 16; o <<= 1) {
                int u = __shfl_up_sync(0xFFFFFFFFu, w, o);
                if (lane >= o) w += u;
            }
            if (lane < 16) ws[lane] = w;
        }
        __syncthreads();
        int incl = v + (warp ? ws[warp - 1] : 0);
        if (tid == 511) g_bsum[bid] = incl;
        grid_barrier(CSRNB);
        int part = (tid < bid) ? g_bsum[tid] : 0;
        #pragma unroll
        for (int o = 16; o; o >>= 1) part += __shfl_xor_sync(0xFFFFFFFFu, part, o);
        if (lane == 0) red[warp] = part;
        __syncthreads();
        int off;
        {
            int t = (lane < 16) ? red[lane] : 0;
            #pragma unroll
            for (int o = 8; o; o >>= 1) t += __shfl_xor_sync(0xFFFFFFFFu, t, o);
            off = __shfl_sync(0xFFFFFFFFu, t, 0);
        }
        int r = incl - x + off;
        if (i < N) { g_row[i] = r; g_cur[i] = r; }
        if (i == 0) g_row[N] = E + N;
        grid_barrier(CSRNB);
        for (int e = bid * 512 + tid; e < E + N; e += CSRNB * 512) {
            int s, d;
            if (e < E) { s = ld_idx(ei, is64, e); d = ld_idx(ei, is64, E + e); }
            else       { s = d = e - E; }
            int pos = atomicAdd(&g_cur[d], 1);
            g_col[pos] = s;
        }
    }

    int wr = warp >> 2;
    int wc = warp & 3;
    int kv = K >> 3;
    int nA = 64 * kv;
    for (;;) {
        if (tid == 0) sm_t = atomicAdd(&g_tilec[which], 1);
        __syncthreads();
        int t = sm_t;
        if (t >= NTILES) break;
        int row0 = t * 64;

        for (int i = tid; i < nA; i += 512) {
            int r = i / kv, c = i - r * kv;
            uint4 v = ((const uint4*)(A + (size_t)(row0 + r) * K))[c];
            *(uint4*)(As + r * lda + c * 8) = v;
        }
        __syncthreads();

        wmma::fragment<wmma::accumulator, 16, 16, 16, float> cf[4];
        #pragma unroll
        for (int n = 0; n < 4; n++) wmma::fill_fragment(cf[n], 0.f);
        for (int ks = 0; ks < K; ks += 16) {
            wmma::fragment<wmma::matrix_a, 16, 16, 16, __half, wmma::row_major> af;
            wmma::load_matrix_sync(af, As + (wr * 16) * lda + ks, lda);
            #pragma unroll
            for (int n = 0; n < 4; n++) {
                wmma::fragment<wmma::matrix_b, 16, 16, 16, __half, wmma::row_major> bf;
                wmma::load_matrix_sync(bf, Bs + ks * 264 + wc * 64 + n * 16, 264);
                wmma::mma_sync(cf[n], af, bf, cf[n]);
            }
        }
        __syncthreads();

        int er = tid >> 3;
        int cs8 = tid & 7;
        #pragma unroll
        for (int wv = 0; wv < 2; wv++) {
            if (wv) __syncthreads();
            if ((wc >> 1) == wv) {
                #pragma unroll
                for (int n = 0; n < 4; n++)
                    wmma::store_matrix_sync(Cs + (wr * 16) * 132 + (wc & 1) * 64 + n * 16,
                                            cf[n], 132, wmma::mem_row_major);
            }
            __syncthreads();
            int gcol = wv * 128 + cs8 * 16;
            int head = gcol >> 6;
            int hoff = gcol & 63;
            float4 v4[4];
            #pragma unroll
            for (int q = 0; q < 4; q++)
                v4[q] = *(float4*)(Cs + er * 132 + cs8 * 16 + q * 4);
            const float* vv = (const float*)v4;
            float s = 0.f, d = 0.f;
            __half h16[16];
            #pragma unroll
            for (int c = 0; c < 16; c++) {
                float v = vv[c];
                s += v * __ldg(att_src + head * 64 + hoff + c);
                d += v * __ldg(att_dst + head * 64 + hoff + c);
                h16[c] = __float2half(v);
            }
            uint4* dst = C + (size_t)(row0 + er) * 32 + (gcol >> 3);
            uint4* srcp = (uint4*)h16;
            dst[0] = srcp[0];
            dst[1] = srcp[1];
            s += __shfl_xor_sync(0xFFFFFFFFu, s, 1);
            d += __shfl_xor_sync(0xFFFFFFFFu, d, 1);
            s += __shfl_xor_sync(0xFFFFFFFFu, s, 2);
            d += __shfl_xor_sync(0xFFFFFFFFu, d, 2);
            if ((tid & 3) == 0) {
                asrc[(row0 + er) * 4 + head] = s;
                adst[(row0 + er) * 4 + head] = d;
            }
        }
    }
}

// ---------------- GAT aggregation: 8 gathers in flight ----------------
__device__ __forceinline__ void fma_half8(float* a, uint4 v, float w) {
    __half2* p = (__half2*)&v;
    #pragma unroll
    for (int q = 0; q < 4; q++) {
        float2 f = __half22float2(p[q]);
        a[2 * q]     += w * f.x;
        a[2 * q + 1] += w * f.y;
    }
}

__device__ __forceinline__ float lrelu(float e) { return (e > 0.f) ? e : NEG_SLOPE * e; }

__global__ void __launch_bounds__(256) aggregate_kernel(const uint4* __restrict__ hh,
                                                        const float* __restrict__ asrc,
                                                        const float* __restrict__ adst,
                                                        const float* __restrict__ bias,
                                                        float* __restrict__ out,
                                                        uint4* __restrict__ out16,
                                                        int N) {
    __shared__ int   ss[8][32];
    __shared__ float swt[8][4][32];
    int gw = (blockIdx.x * blockDim.x + threadIdx.x) >> 5;
    if (gw >= N) return;
    int wslot = (threadIdx.x >> 5);
    int lane = threadIdx.x & 31;
    int start = g_row[gw], end = g_row[gw + 1];
    int deg = end - start;
    float4 ad = *(const float4*)(adst + 4 * gw);
    int head = lane >> 3;

    float acc0[8], acc1[8];
    #pragma unroll
    for (int k = 0; k < 8; k++) { acc0[k] = 0.f; acc1[k] = 0.f; }
    float den = 0.f;

    if (deg <= 32) {
        int myj = start + lane;
        int mys = 0;
        float e0 = -1e30f, e1 = -1e30f, e2 = -1e30f, e3 = -1e30f;
        if (myj < end) {
            mys = g_col[myj];
            float4 q = *(const float4*)(asrc + 4 * mys);
            e0 = lrelu(q.x + ad.x); e1 = lrelu(q.y + ad.y);
            e2 = lrelu(q.z + ad.z); e3 = lrelu(q.w + ad.w);
        }
        float m0 = e0, m1 = e1, m2 = e2, m3 = e3;
        #pragma unroll
        for (int o = 16; o; o >>= 1) {
            m0 = fmaxf(m0, __shfl_xor_sync(0xFFFFFFFFu, m0, o));
            m1 = fmaxf(m1, __shfl_xor_sync(0xFFFFFFFFu, m1, o));
            m2 = fmaxf(m2, __shfl_xor_sync(0xFFFFFFFFu, m2, o));
            m3 = fmaxf(m3, __shfl_xor_sync(0xFFFFFFFFu, m3, o));
        }
        ss[wslot][lane] = mys;
        swt[wslot][0][lane] = (myj < end) ? expf(e0 - m0) : 0.f;
        swt[wslot][1][lane] = (myj < end) ? expf(e1 - m1) : 0.f;
        swt[wslot][2][lane] = (myj < end) ? expf(e2 - m2) : 0.f;
        swt[wslot][3][lane] = (myj < end) ? expf(e3 - m3) : 0.f;
        __syncwarp();
        int j = 0;
        for (; j + 8 <= deg; j += 8) {
            int   sI[8];
            float wI[8];
            uint4 vI[8];
            #pragma unroll
            for (int q = 0; q < 8; q++) {
                sI[q] = ss[wslot][j + q];
                wI[q] = swt[wslot][head][j + q];
            }
            #pragma unroll
            for (int q = 0; q < 8; q++) vI[q] = hh[(size_t)sI[q] * 32 + lane];
            #pragma unroll
            for (int q = 0; q < 8; q++) {
                den += wI[q];
                fma_half8((q & 1) ? acc1 : acc0, vI[q], wI[q]);
            }
        }
        for (; j + 4 <= deg; j += 4) {
            int s0 = ss[wslot][j], s1 = ss[wslot][j + 1];
            int s2 = ss[wslot][j + 2], s3 = ss[wslot][j + 3];
            float w0 = swt[wslot][head][j],     w1 = swt[wslot][head][j + 1];
            float w2 = swt[wslot][head][j + 2], w3 = swt[wslot][head][j + 3];
            uint4 v0 = hh[(size_t)s0 * 32 + lane];
            uint4 v1 = hh[(size_t)s1 * 32 + lane];
            uint4 v2 = hh[(size_t)s2 * 32 + lane];
            uint4 v3 = hh[(size_t)s3 * 32 + lane];
            den += (w0 + w1) + (w2 + w3);
            fma_half8(acc0, v0, w0);
            fma_half8(acc1, v1, w1);
            fma_half8(acc0, v2, w2);
            fma_half8(acc1, v3, w3);
        }
        for (; j < deg; j++) {
            int s0 = ss[wslot][j];
            float w0 = swt[wslot][head][j];
            uint4 v0 = hh[(size_t)s0 * 32 + lane];
            den += w0;
            fma_half8(acc0, v0, w0);
        }
        __syncwarp();
    } else {
        float m0 = -1e30f, m1 = -1e30f, m2 = -1e30f, m3 = -1e30f;
        for (int j = start + lane; j < end; j += 32) {
            int s = g_col[j];
            float4 q = *(const float4*)(asrc + 4 * s);
            m0 = fmaxf(m0, lrelu(q.x + ad.x));
            m1 = fmaxf(m1, lrelu(q.y + ad.y));
            m2 = fmaxf(m2, lrelu(q.z + ad.z));
            m3 = fmaxf(m3, lrelu(q.w + ad.w));
        }
        #pragma unroll
        for (int o = 16; o; o >>= 1) {
            m0 = fmaxf(m0, __shfl_xor_sync(0xFFFFFFFFu, m0, o));
            m1 = fmaxf(m1, __shfl_xor_sync(0xFFFFFFFFu, m1, o));
            m2 = fmaxf(m2, __shfl_xor_sync(0xFFFFFFFFu, m2, o));
            m3 = fmaxf(m3, __shfl_xor_sync(0xFFFFFFFFu, m3, o));
        }
        for (int base = start; base < end; base += 32) {
            int nn = min(32, end - base);
            int myj = base + lane;
            int mys = 0;
            float w0v = 0.f, w1v = 0.f, w2v = 0.f, w3v = 0.f;
            if (myj < end) {
                mys = g_col[myj];
                float4 q = *(const float4*)(asrc + 4 * mys);
                w0v = expf(lrelu(q.x + ad.x) - m0);
                w1v = expf(lrelu(q.y + ad.y) - m1);
                w2v = expf(lrelu(q.z + ad.z) - m2);
                w3v = expf(lrelu(q.w + ad.w) - m3);
            }
            ss[wslot][lane] = mys;
            swt[wslot][0][lane] = w0v;
            swt[wslot][1][lane] = w1v;
            swt[wslot][2][lane] = w2v;
            swt[wslot][3][lane] = w3v;
            __syncwarp();
            int j = 0;
            for (; j + 8 <= nn; j += 8) {
                int   sI[8];
                float wI[8];
                uint4 vI[8];
                #pragma unroll
                for (int q = 0; q < 8; q++) {
                    sI[q] = ss[wslot][j + q];
                    wI[q] = swt[wslot][head][j + q];
                }
                #pragma unroll
                for (int q = 0; q < 8; q++) vI[q] = hh[(size_t)sI[q] * 32 + lane];
                #pragma unroll
                for (int q = 0; q < 8; q++) {
                    den += wI[q];
                    fma_half8((q & 1) ? acc1 : acc0, vI[q], wI[q]);
                }
            }
            for (; j + 4 <= nn; j += 4) {
                int s0 = ss[wslot][j], s1 = ss[wslot][j + 1];
                int s2 = ss[wslot][j + 2], s3 = ss[wslot][j + 3];
                float w0 = swt[wslot][head][j],     w1 = swt[wslot][head][j + 1];
                float w2 = swt[wslot][head][j + 2], w3 = swt[wslot][head][j + 3];
                uint4 v0 = hh[(size_t)s0 * 32 + lane];
                uint4 v1 = hh[(size_t)s1 * 32 + lane];
                uint4 v2 = hh[(size_t)s2 * 32 + lane];
                uint4 v3 = hh[(size_t)s3 * 32 + lane];
                den += (w0 + w1) + (w2 + w3);
                fma_half8(acc0, v0, w0);
                fma_half8(acc1, v1, w1);
                fma_half8(acc0, v2, w2);
                fma_half8(acc1, v3, w3);
            }
            for (; j < nn; j++) {
                int s0 = ss[wslot][j];
                float w0 = swt[wslot][head][j];
                uint4 v0 = hh[(size_t)s0 * 32 + lane];
                den += w0;
                fma_half8(acc0, v0, w0);
            }
            __syncwarp();
        }
    }

    float inv = 1.f / (den + 1e-16f);
    float r[8];
    #pragma unroll
    for (int k = 0; k < 8; k++) r[k] = (acc0[k] + acc1[k]) * inv;
    #pragma unroll
    for (int k = 0; k < 8; ++k) {
        r[k] += __shfl_xor_sync(0xFFFFFFFFu, r[k], 8);
        r[k] += __shfl_xor_sync(0xFFFFFFFFu, r[k], 16);
    }
    if (lane < 8) {
        float o_[8];
        __half h8[8];
        #pragma unroll
        for (int k = 0; k < 8; ++k) {
            float v = 0.25f * r[k] + bias[lane * 8 + k];
            float sg = 1.f / (1.f + expf(-v));
            o_[k] = sg;
            h8[k] = __float2half(sg);
        }
        float4* op = (float4*)(out + (size_t)gw * 64 + lane * 8);
        op[0] = make_float4(o_[0], o_[1], o_[2], o_[3]);
        op[1] = make_float4(o_[4], o_[5], o_[6], o_[7]);
        out16[(size_t)gw * 8 + lane] = *(uint4*)h8;
    }
}

// ---------------- gate via wmma ----------------
__global__ void __launch_bounds__(128) gate_wmma_kernel(const __half* __restrict__ A,
                                                        const __half* __restrict__ B,
                                                        const float* __restrict__ gb1,
                                                        const float* __restrict__ gamma,
                                                        const float* __restrict__ beta,
                                                        const float* __restrict__ gw2,
                                                        const float* __restrict__ gb2,
                                                        float* __restrict__ gout, int N) {
    __shared__ float Cs[64 * 68];
    int tid = threadIdx.x;
    int warp = tid >> 5;
    int by = blockIdx.x;
    int row0 = by * 64 + warp * 16;

    wmma::fragment<wmma::accumulator, 16, 16, 16, float> cf[4];
    #pragma unroll
    for (int n = 0; n < 4; n++) wmma::fill_fragment(cf[n], 0.f);
    for (int k0 = 0; k0 < 64; k0 += 16) {
        wmma::fragment<wmma::matrix_a, 16, 16, 16, __half, wmma::row_major> af;
        wmma::load_matrix_sync(af, A + (size_t)row0 * 64 + k0, 64);
        #pragma unroll
        for (int n = 0; n < 4; n++) {
            wmma::fragment<wmma::matrix_b, 16, 16, 16, __half, wmma::row_major> bf;
            wmma::load_matrix_sync(bf, B + (size_t)k0 * 64 + n * 16, 64);
            wmma::mma_sync(cf[n], af, bf, cf[n]);
        }
    }
    #pragma unroll
    for (int n = 0; n < 4; n++)
        wmma::store_matrix_sync(Cs + warp * 16 * 68 + n * 16, cf[n], 68, wmma::mem_row_major);
    __syncthreads();

    int r = tid >> 1;
    int ch = (tid & 1) * 32;
    int row = by * 64 + r;
    float kinv = rsqrtf(1.0f + 1e-5f);
    float s = 0.f;
    #pragma unroll
    for (int c = 0; c < 32; c++) {
        float t = (Cs[r * 68 + ch + c] + __ldg(gb1 + ch + c)) * kinv * __ldg(gamma + ch + c)
                  + __ldg(beta + ch + c);
        t = fmaxf(t, 0.f);
        s += t * __ldg(gw2 + ch + c);
    }
    s += __shfl_xor_sync(0xFFFFFFFFu, s, 1);
    if ((tid & 1) == 0 && row < N) gout[row] = s + gb2[0];
}

// ---------------- pooling + final ----------------
__global__ void __launch_bounds__(256) pool_kernel(const float* __restrict__ out2,
                                                   const float* __restrict__ lw,
                                                   const float* __restrict__ lb,
                                                   float* __restrict__ result, int N) {
    int b = blockIdx.x;
    __shared__ int sbound[2];
    __shared__ float smax[256];
    __shared__ float sacc[256];
    __shared__ float sden[4];
    int tid = threadIdx.x;
    if (tid < 2) {
        int val = b + tid;
        int lo = 0, hi = N;
        while (lo < hi) {
            int mid = (lo + hi) >> 1;
            if (g_batch[mid] < val) lo = mid + 1; else hi = mid;
        }
        sbound[tid] = lo;
    }
    __syncthreads();
    int start = sbound[0], end = sbound[1];

    float m = -1e30f;
    for (int v = start + tid; v < end; v += 256) m = fmaxf(m, g_gate[v]);
    smax[tid] = m;
    __syncthreads();
    for (int s = 128; s; s >>= 1) {
        if (tid < s) smax[tid] = fmaxf(smax[tid], smax[tid + s]);
        __syncthreads();
    }
    float mx = smax[0];
    __syncthreads();
    int c = tid & 63;
    int sub = tid >> 6;
    float acc = 0.f, dacc = 0.f;
    for (int v = start + sub; v < end; v += 4) {
        float w = expf(g_gate[v] - mx);
        acc += w * out2[(size_t)v * 64 + c];
        if (c == 0) dacc += w;
    }
    sacc[tid] = acc;
    if (c == 0) sden[sub] = dacc;
    __syncthreads();
    if (sub == 0) {
        float p = sacc[c] + sacc[64 + c] + sacc[128 + c] + sacc[192 + c];
        sacc[c] = p * __ldg(lw + c);
    }
    __syncthreads();
    if (tid < 32) {
        float t = sacc[tid] + sacc[tid + 32];
        #pragma unroll
        for (int o = 16; o; o >>= 1) t += __shfl_xor_sync(0xFFFFFFFFu, t, o);
        if (tid == 0) {
            float dt = sden[0] + sden[1] + sden[2] + sden[3];
            float s = t / (dt + 1e-16f) + lb[0];
            result[b] = 1.f / (1.f + expf(-s));
        }
    }
}

// ---------------- launch ----------------
extern "C" void kernel_launch(void* const* d_in, const int* in_sizes, int n_in,
                              void* d_out, int out_size) {
    const float* x  = (const float*)d_in[0];
    const void*  ei = d_in[1];
    const void*  bt = d_in[2];
    int o = (in_sizes[3] == 1) ? 1 : 0;
    const float* W1  = (const float*)d_in[3 + o];
    const float* as1 = (const float*)d_in[4 + o];
    const float* ad1 = (const float*)d_in[5 + o];
    const float* b1  = (const float*)d_in[6 + o];
    const float* W2  = (const float*)d_in[7 + o];
    const float* as2 = (const float*)d_in[8 + o];
    const float* ad2 = (const float*)d_in[9 + o];
    const float* b2  = (const float*)d_in[10 + o];
    const float* gw1 = (const float*)d_in[11 + o];
    const float* gb1 = (const float*)d_in[12 + o];
    const float* gam = (const float*)d_in[13 + o];
    const float* bet = (const float*)d_in[14 + o];
    const float* gw2 = (const float*)d_in[15 + o];
    const float* gb2 = (const float*)d_in[16 + o];
    const float* lw  = (const float*)d_in[17 + o];
    const float* lb  = (const float*)d_in[18 + o];

    int N = in_sizes[0] / 128;
    int E = in_sizes[1] / 2;

    __half *x16b, *w1hb, *w2hb, *gw1hb, *o16b;
    uint4* hhbuf;
    float *asrcb, *adstb, *out1b, *out2b, *gateb;
    cudaGetSymbolAddress((void**)&x16b,  g_x16);
    cudaGetSymbolAddress((void**)&w1hb,  g_w1h);
    cudaGetSymbolAddress((void**)&w2hb,  g_w2h);
    cudaGetSymbolAddress((void**)&gw1hb, g_gw1h);
    cudaGetSymbolAddress((void**)&o16b,  g_o16);
    cudaGetSymbolAddress((void**)&hhbuf, g_hh);
    cudaGetSymbolAddress((void**)&asrcb, g_asrc);
    cudaGetSymbolAddress((void**)&adstb, g_adst);
    cudaGetSymbolAddress((void**)&out1b, g_out1);
    cudaGetSymbolAddress((void**)&out2b, g_out2);
    cudaGetSymbolAddress((void**)&gateb, g_gate);

    int smem1 = 128 * 264 * 2 + 64 * 132 * 4;   // 101376 (K=128)
    int smem2 = 64 * 264 * 2 + 64 * 132 * 4;    //  67584 (K=64)
    static int attr_set = 0;
    if (!attr_set) {
        cudaFuncSetAttribute(gemm_attn_kernel,
                             cudaFuncAttributeMaxDynamicSharedMemorySize, smem1);
        attr_set = 1;
    }

    int x8 = N * 128 / 8;
    int prepT = (x8 > 128 * 256) ? x8 : 128 * 256;

    prep_kernel<<<(prepT + 255) / 256, 256>>>((const long long*)ei, x, W1, W2, gw1, N, x8);
    gemm_attn_kernel<<<GEMMG, 512, smem1>>>(x16b, w1hb, hhbuf, as1, ad1, asrcb, adstb,
                                            128, 1, 0, ei, bt, N, E);
    int wblocks = (N + 7) / 8;
    aggregate_kernel<<<wblocks, 256>>>(hhbuf, asrcb, adstb, b1, out1b, (uint4*)o16b, N);
    gemm_attn_kernel<<<GEMMG, 512, smem2>>>(o16b, w2hb, hhbuf, as2, ad2, asrcb, adstb,
                                            64, 0, 1, ei, bt, N, E);
    aggregate_kernel<<<wblocks, 256>>>(hhbuf, asrcb, adstb, b2, out2b, (uint4*)o16b, N);
    gate_wmma_kernel<<<NPAD / 64, 128>>>(o16b, gw1hb, gb1, gam, bet, gw2, gb2, gateb, N);
    pool_kernel<<<GNUM, 256>>>(out2b, lw, lb, (float*)d_out, N);
}

// round 17
// speedup vs baseline: 1.6396x; 1.0159x over previous
#include <cuda_runtime.h>
#include <cuda_fp16.h>
#include <mma.h>
#include <math.h>
#include <stdint.h>

using namespace nvcuda;

#define NNODES 50000
#define NPAD   50048
#define NTILES (NPAD / 64)      // 782 row tiles
#define GEMMG  296              // persistent grid: 2 blocks/SM, all resident
#define CSRNB  98               // blocks 0..97 build CSR inside layer-1 GEMM launch
#define NEDGES 800000
#define TOTE   (NEDGES + NNODES)
#define GNUM   64
#define NEG_SLOPE 0.2f

// ---------------- static device scratch ----------------
static __device__ int      g_is64;
static __device__ unsigned g_barcnt;
static __device__ unsigned g_bargen;
static __device__ int    g_tilec[2];
static __device__ int    g_batch[NNODES];
static __device__ int    g_deg[NNODES];
static __device__ int    g_row[NNODES + 1];
static __device__ int    g_cur[NNODES];
static __device__ int    g_col[TOTE];
static __device__ int    g_bsum[CSRNB];
static __device__ __half g_w1h[128 * 256];
static __device__ __half g_w2h[64 * 256];
static __device__ __half g_gw1h[64 * 64];
static __device__ __half g_o16[(size_t)NPAD * 64];
static __device__ uint4  g_hh[(size_t)NPAD * 32];
static __device__ float  g_asrc[NPAD * 4];
static __device__ float  g_adst[NPAD * 4];
static __device__ float  g_out1[(size_t)NNODES * 64];
static __device__ float  g_out2[(size_t)NNODES * 64];
static __device__ float  g_gate[NNODES];

__device__ __forceinline__ int ld_idx(const void* ei, int is64, int idx) {
    return is64 ? (int)((const long long*)ei)[idx] : ((const int*)ei)[idx];
}

// ---------------- prep: deg zero, tile counters, dtype, fp16 weights (x untouched) ----------------
__global__ void prep_kernel(const long long* __restrict__ ei,
                            const float* __restrict__ W1,
                            const float* __restrict__ W2,
                            const float* __restrict__ gw1,
                            int N) {
    int i = blockIdx.x * blockDim.x + threadIdx.x;
    if (i < N) g_deg[i] = 0;
    if (i < 2) g_tilec[i] = 0;
    if (i < 128 * 256) g_w1h[i] = __float2half(W1[i]);
    if (i < 64 * 256)  g_w2h[i] = __float2half(W2[i]);
    if (i < 64 * 64)   g_gw1h[i] = __float2half(gw1[i]);
    if (blockIdx.x == 0 && threadIdx.x < 32) {
        long long v = ei[threadIdx.x];
        int ok = (v >= 0 && v < (long long)N);
        unsigned all = __all_sync(0xFFFFFFFFu, ok);
        if (threadIdx.x == 0) g_is64 = all ? 1 : 0;
    }
}

// ---------------- grid barrier (CSR subset; all resident) ----------------
__device__ __forceinline__ void grid_barrier(int nblocks) {
    __threadfence();
    __syncthreads();
    if (threadIdx.x == 0) {
        unsigned gen = atomicAdd(&g_bargen, 0u);
        unsigned prev = atomicAdd(&g_barcnt, 1u);
        if (prev == (unsigned)(nblocks - 1)) {
            atomicExch(&g_barcnt, 0u);
            __threadfence();
            atomicAdd(&g_bargen, 1u);
        } else {
            while (atomicAdd(&g_bargen, 0u) == gen) { }
        }
    }
    __syncthreads();
}

// ---------------- persistent GEMM + embedded CSR build ----------------
// a_fp32: layer-1 stages A directly from fp32 x (convert in staging), else fp16.
extern __shared__ char dynsm[];
__global__ void __launch_bounds__(512, 2) gemm_attn_kernel(const void* __restrict__ Ain,
                                                           const __half* __restrict__ B,
                                                           uint4* __restrict__ C,
                                                           const float* __restrict__ att_src,
                                                           const float* __restrict__ att_dst,
                                                           float* __restrict__ asrc,
                                                           float* __restrict__ adst,
                                                           int K, int a_fp32,
                                                           int do_csr, int which,
                                                           const void* __restrict__ ei,
                                                           const void* __restrict__ bt,
                                                           int N, int E) {
    __half* Bs = (__half*)dynsm;                           // [K][264]
    char* scratch = dynsm + (size_t)K * 264 * 2;
    __half* As = (__half*)scratch;                         // [64][K+8]
    float*  Cs = (float*)scratch;                          // [64][132]
    __shared__ int ws[16];
    __shared__ int red[16];
    __shared__ int sm_t;
    int tid = threadIdx.x;
    int warp = tid >> 5;
    int lane = tid & 31;
    int lda = K + 8;

    int nB = K * 32;
    for (int i = tid; i < nB; i += 512) {
        int r = i >> 5, c = i & 31;
        uint4 v = ((const uint4*)(B + (size_t)r * 256))[c];
        *(uint4*)(Bs + r * 264 + c * 8) = v;
    }

    if (do_csr && blockIdx.x < CSRNB) {
        int bid = blockIdx.x;
        int is64 = g_is64;
        for (int idx = bid * 512 + tid; idx < E + N; idx += CSRNB * 512) {
            if (idx < E) {
                atomicAdd(&g_deg[ld_idx(ei, is64, E + idx)], 1);
            } else {
                int j = idx - E;
                g_batch[j] = is64 ? (int)((const long long*)bt)[j] : ((const int*)bt)[j];
            }
        }
        grid_barrier(CSRNB);
        int i = bid * 512 + tid;
        int x = (i < N) ? g_deg[i] + 1 : 0;
        int v = x;
        #pragma unroll
        for (int o = 1; o < 32; o <<= 1) {
            int u = __shfl_up_sync(0xFFFFFFFFu, v, o);
            if (lane >= o) v += u;
        }
        if (lane == 31) ws[warp] = v;
        __syncthreads();
        if (warp == 0) {
            int w = (lane < 16) ? ws[lane] : 0;
            #pragma unroll
            for (int o = 1; o < 16; o <<= 1) {
                int u = __shfl_up_sync(0xFFFFFFFFu, w, o);
                if (lane >= o) w += u;
            }
            if (lane < 16) ws[lane] = w;
        }
        __syncthreads();
        int incl = v + (warp ? ws[warp - 1] : 0);
        if (tid == 511) g_bsum[bid] = incl;
        grid_barrier(CSRNB);
        int part = (tid < bid) ? g_bsum[tid] : 0;
        #pragma unroll
        for (int o = 16; o; o >>= 1) part += __shfl_xor_sync(0xFFFFFFFFu, part, o);
        if (lane == 0) red[warp] = part;
        __syncthreads();
        int off;
        {
            int t = (lane < 16) ? red[lane] : 0;
            #pragma unroll
            for (int o = 8; o; o >>= 1) t += __shfl_xor_sync(0xFFFFFFFFu, t, o);
            off = __shfl_sync(0xFFFFFFFFu, t, 0);
        }
        int r = incl - x + off;
        if (i < N) { g_row[i] = r; g_cur[i] = r; }
        if (i == 0) g_row[N] = E + N;
        grid_barrier(CSRNB);
        for (int e = bid * 512 + tid; e < E + N; e += CSRNB * 512) {
            int s, d;
            if (e < E) { s = ld_idx(ei, is64, e); d = ld_idx(ei, is64, E + e); }
            else       { s = d = e - E; }
            int pos = atomicAdd(&g_cur[d], 1);
            g_col[pos] = s;
        }
    }

    int wr = warp >> 2;
    int wc = warp & 3;
    int kv = K >> 3;
    int nA = 64 * kv;
    for (;;) {
        if (tid == 0) sm_t = atomicAdd(&g_tilec[which], 1);
        __syncthreads();
        int t = sm_t;
        if (t >= NTILES) break;
        int row0 = t * 64;

        if (a_fp32) {
            const float* Af = (const float*)Ain;
            for (int i = tid; i < nA; i += 512) {
                int r = i / kv, c = i - r * kv;
                __half h8[8];
                if (row0 + r < N) {
                    const float4* src = (const float4*)(Af + (size_t)(row0 + r) * K) + 2 * c;
                    float4 a = src[0];
                    float4 b = src[1];
                    h8[0] = __float2half(a.x); h8[1] = __float2half(a.y);
                    h8[2] = __float2half(a.z); h8[3] = __float2half(a.w);
                    h8[4] = __float2half(b.x); h8[5] = __float2half(b.y);
                    h8[6] = __float2half(b.z); h8[7] = __float2half(b.w);
                } else {
                    #pragma unroll
                    for (int q = 0; q < 8; q++) h8[q] = __float2half(0.f);
                }
                *(uint4*)(As + r * lda + c * 8) = *(uint4*)h8;
            }
        } else {
            const __half* Ah = (const __half*)Ain;
            for (int i = tid; i < nA; i += 512) {
                int r = i / kv, c = i - r * kv;
                uint4 v = ((const uint4*)(Ah + (size_t)(row0 + r) * K))[c];
                *(uint4*)(As + r * lda + c * 8) = v;
            }
        }
        __syncthreads();

        wmma::fragment<wmma::accumulator, 16, 16, 16, float> cf[4];
        #pragma unroll
        for (int n = 0; n < 4; n++) wmma::fill_fragment(cf[n], 0.f);
        for (int ks = 0; ks < K; ks += 16) {
            wmma::fragment<wmma::matrix_a, 16, 16, 16, __half, wmma::row_major> af;
            wmma::load_matrix_sync(af, As + (wr * 16) * lda + ks, lda);
            #pragma unroll
            for (int n = 0; n < 4; n++) {
                wmma::fragment<wmma::matrix_b, 16, 16, 16, __half, wmma::row_major> bf;
                wmma::load_matrix_sync(bf, Bs + ks * 264 + wc * 64 + n * 16, 264);
                wmma::mma_sync(cf[n], af, bf, cf[n]);
            }
        }
        __syncthreads();

        int er = tid >> 3;
        int cs8 = tid & 7;
        #pragma unroll
        for (int wv = 0; wv < 2; wv++) {
            if (wv) __syncthreads();
            if ((wc >> 1) == wv) {
                #pragma unroll
                for (int n = 0; n < 4; n++)
                    wmma::store_matrix_sync(Cs + (wr * 16) * 132 + (wc & 1) * 64 + n * 16,
                                            cf[n], 132, wmma::mem_row_major);
            }
            __syncthreads();
            int gcol = wv * 128 + cs8 * 16;
            int head = gcol >> 6;
            int hoff = gcol & 63;
            float4 v4[4];
            #pragma unroll
            for (int q = 0; q < 4; q++)
                v4[q] = *(float4*)(Cs + er * 132 + cs8 * 16 + q * 4);
            const float* vv = (const float*)v4;
            float s = 0.f, d = 0.f;
            __half h16[16];
            #pragma unroll
            for (int c = 0; c < 16; c++) {
                float v = vv[c];
                s += v * __ldg(att_src + head * 64 + hoff + c);
                d += v * __ldg(att_dst + head * 64 + hoff + c);
                h16[c] = __float2half(v);
            }
            uint4* dst = C + (size_t)(row0 + er) * 32 + (gcol >> 3);
            uint4* srcp = (uint4*)h16;
            dst[0] = srcp[0];
            dst[1] = srcp[1];
            s += __shfl_xor_sync(0xFFFFFFFFu, s, 1);
            d += __shfl_xor_sync(0xFFFFFFFFu, d, 1);
            s += __shfl_xor_sync(0xFFFFFFFFu, s, 2);
            d += __shfl_xor_sync(0xFFFFFFFFu, d, 2);
            if ((tid & 3) == 0) {
                asrc[(row0 + er) * 4 + head] = s;
                adst[(row0 + er) * 4 + head] = d;
            }
        }
    }
}

// ---------------- GAT aggregation: 8 gathers in flight ----------------
__device__ __forceinline__ void fma_half8(float* a, uint4 v, float w) {
    __half2* p = (__half2*)&v;
    #pragma unroll
    for (int q = 0; q < 4; q++) {
        float2 f = __half22float2(p[q]);
        a[2 * q]     += w * f.x;
        a[2 * q + 1] += w * f.y;
    }
}

__device__ __forceinline__ float lrelu(float e) { return (e > 0.f) ? e : NEG_SLOPE * e; }

__global__ void __launch_bounds__(256) aggregate_kernel(const uint4* __restrict__ hh,
                                                        const float* __restrict__ asrc,
                                                        const float* __restrict__ adst,
                                                        const float* __restrict__ bias,
                                                        float* __restrict__ out,
                                                        uint4* __restrict__ out16,
                                                        int N) {
    __shared__ int   ss[8][32];
    __shared__ float swt[8][4][32];
    int gw = (blockIdx.x * blockDim.x + threadIdx.x) >> 5;
    if (gw >= N) return;
    int wslot = (threadIdx.x >> 5);
    int lane = threadIdx.x & 31;
    int start = g_row[gw], end = g_row[gw + 1];
    int deg = end - start;
    float4 ad = *(const float4*)(adst + 4 * gw);
    int head = lane >> 3;

    float acc0[8], acc1[8];
    #pragma unroll
    for (int k = 0; k < 8; k++) { acc0[k] = 0.f; acc1[k] = 0.f; }
    float den = 0.f;

    if (deg <= 32) {
        int myj = start + lane;
        int mys = 0;
        float e0 = -1e30f, e1 = -1e30f, e2 = -1e30f, e3 = -1e30f;
        if (myj < end) {
            mys = g_col[myj];
            float4 q = *(const float4*)(asrc + 4 * mys);
            e0 = lrelu(q.x + ad.x); e1 = lrelu(q.y + ad.y);
            e2 = lrelu(q.z + ad.z); e3 = lrelu(q.w + ad.w);
        }
        float m0 = e0, m1 = e1, m2 = e2, m3 = e3;
        #pragma unroll
        for (int o = 16; o; o >>= 1) {
            m0 = fmaxf(m0, __shfl_xor_sync(0xFFFFFFFFu, m0, o));
            m1 = fmaxf(m1, __shfl_xor_sync(0xFFFFFFFFu, m1, o));
            m2 = fmaxf(m2, __shfl_xor_sync(0xFFFFFFFFu, m2, o));
            m3 = fmaxf(m3, __shfl_xor_sync(0xFFFFFFFFu, m3, o));
        }
        ss[wslot][lane] = mys;
        swt[wslot][0][lane] = (myj < end) ? expf(e0 - m0) : 0.f;
        swt[wslot][1][lane] = (myj < end) ? expf(e1 - m1) : 0.f;
        swt[wslot][2][lane] = (myj < end) ? expf(e2 - m2) : 0.f;
        swt[wslot][3][lane] = (myj < end) ? expf(e3 - m3) : 0.f;
        __syncwarp();
        int j = 0;
        for (; j + 8 <= deg; j += 8) {
            int   sI[8];
            float wI[8];
            uint4 vI[8];
            #pragma unroll
            for (int q = 0; q < 8; q++) {
                sI[q] = ss[wslot][j + q];
                wI[q] = swt[wslot][head][j + q];
            }
            #pragma unroll
            for (int q = 0; q < 8; q++) vI[q] = hh[(size_t)sI[q] * 32 + lane];
            #pragma unroll
            for (int q = 0; q < 8; q++) {
                den += wI[q];
                fma_half8((q & 1) ? acc1 : acc0, vI[q], wI[q]);
            }
        }
        for (; j + 4 <= deg; j += 4) {
            int s0 = ss[wslot][j], s1 = ss[wslot][j + 1];
            int s2 = ss[wslot][j + 2], s3 = ss[wslot][j + 3];
            float w0 = swt[wslot][head][j],     w1 = swt[wslot][head][j + 1];
            float w2 = swt[wslot][head][j + 2], w3 = swt[wslot][head][j + 3];
            uint4 v0 = hh[(size_t)s0 * 32 + lane];
            uint4 v1 = hh[(size_t)s1 * 32 + lane];
            uint4 v2 = hh[(size_t)s2 * 32 + lane];
            uint4 v3 = hh[(size_t)s3 * 32 + lane];
            den += (w0 + w1) + (w2 + w3);
            fma_half8(acc0, v0, w0);
            fma_half8(acc1, v1, w1);
            fma_half8(acc0, v2, w2);
            fma_half8(acc1, v3, w3);
        }
        for (; j < deg; j++) {
            int s0 = ss[wslot][j];
            float w0 = swt[wslot][head][j];
            uint4 v0 = hh[(size_t)s0 * 32 + lane];
            den += w0;
            fma_half8(acc0, v0, w0);
        }
        __syncwarp();
    } else {
        float m0 = -1e30f, m1 = -1e30f, m2 = -1e30f, m3 = -1e30f;
        for (int j = start + lane; j < end; j += 32) {
            int s = g_col[j];
            float4 q = *(const float4*)(asrc + 4 * s);
            m0 = fmaxf(m0, lrelu(q.x + ad.x));
            m1 = fmaxf(m1, lrelu(q.y + ad.y));
            m2 = fmaxf(m2, lrelu(q.z + ad.z));
            m3 = fmaxf(m3, lrelu(q.w + ad.w));
        }
        #pragma unroll
        for (int o = 16; o; o >>= 1) {
            m0 = fmaxf(m0, __shfl_xor_sync(0xFFFFFFFFu, m0, o));
            m1 = fmaxf(m1, __shfl_xor_sync(0xFFFFFFFFu, m1, o));
            m2 = fmaxf(m2, __shfl_xor_sync(0xFFFFFFFFu, m2, o));
            m3 = fmaxf(m3, __shfl_xor_sync(0xFFFFFFFFu, m3, o));
        }
        for (int base = start; base < end; base += 32) {
            int nn = min(32, end - base);
            int myj = base + lane;
            int mys = 0;
            float w0v = 0.f, w1v = 0.f, w2v = 0.f, w3v = 0.f;
            if (myj < end) {
                mys = g_col[myj];
                float4 q = *(const float4*)(asrc + 4 * mys);
                w0v = expf(lrelu(q.x + ad.x) - m0);
                w1v = expf(lrelu(q.y + ad.y) - m1);
                w2v = expf(lrelu(q.z + ad.z) - m2);
                w3v = expf(lrelu(q.w + ad.w) - m3);
            }
            ss[wslot][lane] = mys;
            swt[wslot][0][lane] = w0v;
            swt[wslot][1][lane] = w1v;
            swt[wslot][2][lane] = w2v;
            swt[wslot][3][lane] = w3v;
            __syncwarp();
            int j = 0;
            for (; j + 8 <= nn; j += 8) {
                int   sI[8];
                float wI[8];
                uint4 vI[8];
                #pragma unroll
                for (int q = 0; q < 8; q++) {
                    sI[q] = ss[wslot][j + q];
                    wI[q] = swt[wslot][head][j + q];
                }
                #pragma unroll
                for (int q = 0; q < 8; q++) vI[q] = hh[(size_t)sI[q] * 32 + lane];
                #pragma unroll
                for (int q = 0; q < 8; q++) {
                    den += wI[q];
                    fma_half8((q & 1) ? acc1 : acc0, vI[q], wI[q]);
                }
            }
            for (; j + 4 <= nn; j += 4) {
                int s0 = ss[wslot][j], s1 = ss[wslot][j + 1];
                int s2 = ss[wslot][j + 2], s3 = ss[wslot][j + 3];
                float w0 = swt[wslot][head][j],     w1 = swt[wslot][head][j + 1];
                float w2 = swt[wslot][head][j + 2], w3 = swt[wslot][head][j + 3];
                uint4 v0 = hh[(size_t)s0 * 32 + lane];
                uint4 v1 = hh[(size_t)s1 * 32 + lane];
                uint4 v2 = hh[(size_t)s2 * 32 + lane];
                uint4 v3 = hh[(size_t)s3 * 32 + lane];
                den += (w0 + w1) + (w2 + w3);
                fma_half8(acc0, v0, w0);
                fma_half8(acc1, v1, w1);
                fma_half8(acc0, v2, w2);
                fma_half8(acc1, v3, w3);
            }
            for (; j < nn; j++) {
                int s0 = ss[wslot][j];
                float w0 = swt[wslot][head][j];
                uint4 v0 = hh[(size_t)s0 * 32 + lane];
                den += w0;
                fma_half8(acc0, v0, w0);
            }
            __syncwarp();
        }
    }

    float inv = 1.f / (den + 1e-16f);
    float r[8];
    #pragma unroll
    for (int k = 0; k < 8; k++) r[k] = (acc0[k] + acc1[k]) * inv;
    #pragma unroll
    for (int k = 0; k < 8; ++k) {
        r[k] += __shfl_xor_sync(0xFFFFFFFFu, r[k], 8);
        r[k] += __shfl_xor_sync(0xFFFFFFFFu, r[k], 16);
    }
    if (lane < 8) {
        float o_[8];
        __half h8[8];
        #pragma unroll
        for (int k = 0; k < 8; ++k) {
            float v = 0.25f * r[k] + bias[lane * 8 + k];
            float sg = 1.f / (1.f + expf(-v));
            o_[k] = sg;
            h8[k] = __float2half(sg);
        }
        float4* op = (float4*)(out + (size_t)gw * 64 + lane * 8);
        op[0] = make_float4(o_[0], o_[1], o_[2], o_[3]);
        op[1] = make_float4(o_[4], o_[5], o_[6], o_[7]);
        out16[(size_t)gw * 8 + lane] = *(uint4*)h8;
    }
}

// ---------------- gate via wmma ----------------
__global__ void __launch_bounds__(128) gate_wmma_kernel(const __half* __restrict__ A,
                                                        const __half* __restrict__ B,
                                                        const float* __restrict__ gb1,
                                                        const float* __restrict__ gamma,
                                                        const float* __restrict__ beta,
                                                        const float* __restrict__ gw2,
                                                        const float* __restrict__ gb2,
                                                        float* __restrict__ gout, int N) {
    __shared__ float Cs[64 * 68];
    int tid = threadIdx.x;
    int warp = tid >> 5;
    int by = blockIdx.x;
    int row0 = by * 64 + warp * 16;

    wmma::fragment<wmma::accumulator, 16, 16, 16, float> cf[4];
    #pragma unroll
    for (int n = 0; n < 4; n++) wmma::fill_fragment(cf[n], 0.f);
    for (int k0 = 0; k0 < 64; k0 += 16) {
        wmma::fragment<wmma::matrix_a, 16, 16, 16, __half, wmma::row_major> af;
        wmma::load_matrix_sync(af, A + (size_t)row0 * 64 + k0, 64);
        #pragma unroll
        for (int n = 0; n < 4; n++) {
            wmma::fragment<wmma::matrix_b, 16, 16, 16, __half, wmma::row_major> bf;
            wmma::load_matrix_sync(bf, B + (size_t)k0 * 64 + n * 16, 64);
            wmma::mma_sync(cf[n], af, bf, cf[n]);
        }
    }
    #pragma unroll
    for (int n = 0; n < 4; n++)
        wmma::store_matrix_sync(Cs + warp * 16 * 68 + n * 16, cf[n], 68, wmma::mem_row_major);
    __syncthreads();

    int r = tid >> 1;
    int ch = (tid & 1) * 32;
    int row = by * 64 + r;
    float kinv = rsqrtf(1.0f + 1e-5f);
    float s = 0.f;
    #pragma unroll
    for (int c = 0; c < 32; c++) {
        float t = (Cs[r * 68 + ch + c] + __ldg(gb1 + ch + c)) * kinv * __ldg(gamma + ch + c)
                  + __ldg(beta + ch + c);
        t = fmaxf(t, 0.f);
        s += t * __ldg(gw2 + ch + c);
    }
    s += __shfl_xor_sync(0xFFFFFFFFu, s, 1);
    if ((tid & 1) == 0 && row < N) gout[row] = s + gb2[0];
}

// ---------------- pooling + final ----------------
__global__ void __launch_bounds__(256) pool_kernel(const float* __restrict__ out2,
                                                   const float* __restrict__ lw,
                                                   const float* __restrict__ lb,
                                                   float* __restrict__ result, int N) {
    int b = blockIdx.x;
    __shared__ int sbound[2];
    __shared__ float smax[256];
    __shared__ float sacc[256];
    __shared__ float sden[4];
    int tid = threadIdx.x;
    if (tid < 2) {
        int val = b + tid;
        int lo = 0, hi = N;
        while (lo < hi) {
            int mid = (lo + hi) >> 1;
            if (g_batch[mid] < val) lo = mid + 1; else hi = mid;
        }
        sbound[tid] = lo;
    }
    __syncthreads();
    int start = sbound[0], end = sbound[1];

    float m = -1e30f;
    for (int v = start + tid; v < end; v += 256) m = fmaxf(m, g_gate[v]);
    smax[tid] = m;
    __syncthreads();
    for (int s = 128; s; s >>= 1) {
        if (tid < s) smax[tid] = fmaxf(smax[tid], smax[tid + s]);
        __syncthreads();
    }
    float mx = smax[0];
    __syncthreads();
    int c = tid & 63;
    int sub = tid >> 6;
    float acc = 0.f, dacc = 0.f;
    for (int v = start + sub; v < end; v += 4) {
        float w = expf(g_gate[v] - mx);
        acc += w * out2[(size_t)v * 64 + c];
        if (c == 0) dacc += w;
    }
    sacc[tid] = acc;
    if (c == 0) sden[sub] = dacc;
    __syncthreads();
    if (sub == 0) {
        float p = sacc[c] + sacc[64 + c] + sacc[128 + c] + sacc[192 + c];
        sacc[c] = p * __ldg(lw + c);
    }
    __syncthreads();
    if (tid < 32) {
        float t = sacc[tid] + sacc[tid + 32];
        #pragma unroll
        for (int o = 16; o; o >>= 1) t += __shfl_xor_sync(0xFFFFFFFFu, t, o);
        if (tid == 0) {
            float dt = sden[0] + sden[1] + sden[2] + sden[3];
            float s = t / (dt + 1e-16f) + lb[0];
            result[b] = 1.f / (1.f + expf(-s));
        }
    }
}

// ---------------- launch ----------------
extern "C" void kernel_launch(void* const* d_in, const int* in_sizes, int n_in,
                              void* d_out, int out_size) {
    const float* x  = (const float*)d_in[0];
    const void*  ei = d_in[1];
    const void*  bt = d_in[2];
    int o = (in_sizes[3] == 1) ? 1 : 0;
    const float* W1  = (const float*)d_in[3 + o];
    const float* as1 = (const float*)d_in[4 + o];
    const float* ad1 = (const float*)d_in[5 + o];
    const float* b1  = (const float*)d_in[6 + o];
    const float* W2  = (const float*)d_in[7 + o];
    const float* as2 = (const float*)d_in[8 + o];
    const float* ad2 = (const float*)d_in[9 + o];
    const float* b2  = (const float*)d_in[10 + o];
    const float* gw1 = (const float*)d_in[11 + o];
    const float* gb1 = (const float*)d_in[12 + o];
    const float* gam = (const float*)d_in[13 + o];
    const float* bet = (const float*)d_in[14 + o];
    const float* gw2 = (const float*)d_in[15 + o];
    const float* gb2 = (const float*)d_in[16 + o];
    const float* lw  = (const float*)d_in[17 + o];
    const float* lb  = (const float*)d_in[18 + o];

    int N = in_sizes[0] / 128;
    int E = in_sizes[1] / 2;

    __half *w1hb, *w2hb, *gw1hb, *o16b;
    uint4* hhbuf;
    float *asrcb, *adstb, *out1b, *out2b, *gateb;
    cudaGetSymbolAddress((void**)&w1hb,  g_w1h);
    cudaGetSymbolAddress((void**)&w2hb,  g_w2h);
    cudaGetSymbolAddress((void**)&gw1hb, g_gw1h);
    cudaGetSymbolAddress((void**)&o16b,  g_o16);
    cudaGetSymbolAddress((void**)&hhbuf, g_hh);
    cudaGetSymbolAddress((void**)&asrcb, g_asrc);
    cudaGetSymbolAddress((void**)&adstb, g_adst);
    cudaGetSymbolAddress((void**)&out1b, g_out1);
    cudaGetSymbolAddress((void**)&out2b, g_out2);
    cudaGetSymbolAddress((void**)&gateb, g_gate);

    int smem1 = 128 * 264 * 2 + 64 * 132 * 4;   // 101376 (K=128)
    int smem2 = 64 * 264 * 2 + 64 * 132 * 4;    //  67584 (K=64)
    static int attr_set = 0;
    if (!attr_set) {
        cudaFuncSetAttribute(gemm_attn_kernel,
                             cudaFuncAttributeMaxDynamicSharedMemorySize, smem1);
        attr_set = 1;
    }

    int prepT = (N > 128 * 256) ? N : 128 * 256;

    // 0: prep (deg zero, tile counters, dtype, fp16 weights only — x stays fp32)
    prep_kernel<<<(prepT + 255) / 256, 256>>>((const long long*)ei, W1, W2, gw1, N);
    // 1: layer-1 GEMM (A from fp32 x, converted in staging) + embedded CSR build
    gemm_attn_kernel<<<GEMMG, 512, smem1>>>(x, w1hb, hhbuf, as1, ad1, asrcb, adstb,
                                            128, 1, 1, 0, ei, bt, N, E);
    // 2: layer-1 aggregate
    int wblocks = (N + 7) / 8;
    aggregate_kernel<<<wblocks, 256>>>(hhbuf, asrcb, adstb, b1, out1b, (uint4*)o16b, N);
    // 3-4: layer 2 (A = fp16 o16)
    gemm_attn_kernel<<<GEMMG, 512, smem2>>>(o16b, w2hb, hhbuf, as2, ad2, asrcb, adstb,
                                            64, 0, 0, 1, ei, bt, N, E);
    aggregate_kernel<<<wblocks, 256>>>(hhbuf, asrcb, adstb, b2, out2b, (uint4*)o16b, N);
    // 5-6: gate, pool+final
    gate_wmma_kernel<<<NPAD / 64, 128>>>(o16b, gw1hb, gb1, gam, bet, gw2, gb2, gateb, N);
    pool_kernel<<<GNUM, 256>>>(out2b, lw, lb, (float*)d_out, N);
}